// round 6
// baseline (speedup 1.0000x reference)
#include <cuda_runtime.h>
#include <cuda_bf16.h>
#include <math.h>

#define MD 4096
#define DD 64
#define NJB 32
#define FFC 0.999f
#define REGC 0.01f
#define JIT 1e-10f
#define INV2LS2 (1.0f/128.0f)

#define OFF_MU   ((size_t)0)
#define OFF_SIG  ((size_t)16384)
#define OFF_Q    (OFF_SIG + (size_t)MD*MD)
#define OFF_DICT (OFF_Q   + (size_t)MD*MD)
#define OFF_TI   (OFF_DICT + (size_t)MD*DD)
#define OFF_NN   (OFF_TI + MD)
#define OFF_ND   (OFF_NN + 4)

// -------- scratch (device globals; allocations forbidden) --------
static __device__ float g_kdx[MD], g_alloc[MD], g_norm[MD];
static __device__ float g_q[MD], g_h[MD], g_hsig[MD], g_Qmu[4*MD];
static __device__ float g_hpart[NJB*MD];
static __device__ float g_colp[MD];
static __device__ __nv_bfloat16 g_kddbf[(size_t)MD*MD];   // 33.5 MB bf16 Kdd cache
static __device__ float g_pval[512];
static __device__ int   g_pidx[512];
static __device__ float gs_pu, gs_pm[4], gs_qh, gs_npv, gs_pv, gs_c[4];
static __device__ float gs_critM, gs_denom, gs_qp, gs_tval;
static __device__ int   gs_prune;

__device__ __forceinline__ unsigned pk_bf2(float a, float b) {
    __nv_bfloat162 h = __floats2bfloat162_rn(a, b);
    return *reinterpret_cast<unsigned*>(&h);
}

__device__ __forceinline__ void mma16816(float* c, unsigned a0, unsigned a1,
                                         unsigned a2, unsigned a3,
                                         unsigned b0, unsigned b1) {
    asm volatile(
        "mma.sync.aligned.m16n8k16.row.col.f32.bf16.bf16.f32 "
        "{%0,%1,%2,%3},{%4,%5,%6,%7},{%8,%9},{%0,%1,%2,%3};\n"
        : "+f"(c[0]), "+f"(c[1]), "+f"(c[2]), "+f"(c[3])
        : "r"(a0), "r"(a1), "r"(a2), "r"(a3), "r"(b0), "r"(b1));
}

// -------- K_dx, alloc, row norms --------
__global__ void k_kdx(const float* __restrict__ dict, const float* __restrict__ x,
                      const float* __restrict__ ti) {
    __shared__ float xs[DD];
    int tid = threadIdx.x;
    if (tid < DD) xs[tid] = x[tid];
    __syncthreads();
    int i = blockIdx.x * 256 + tid;
    const float* dr = dict + (size_t)i * DD;
    float a2 = 0.f, ip = 0.f, x2 = 0.f;
#pragma unroll
    for (int k = 0; k < DD; k++) { float d = dr[k], xv = xs[k]; a2 += d*d; ip += d*xv; x2 += xv*xv; }
    float d2 = fmaxf(a2 + x2 - 2.0f*ip, 0.0f);
    float al = (ti[i] >= 0.0f) ? 1.0f : 0.0f;
    g_kdx[i] = __expf(-d2 * INV2LS2) * al;
    g_alloc[i] = al;
    g_norm[i] = a2;
}

// -------- q = Q@kdx, Qmu = sqrt(FF)*Q@mu (warp per row) --------
__global__ void k_matvec5(const float* __restrict__ Q, const float* __restrict__ mu) {
    int gw = (blockIdx.x * 256 + threadIdx.x) >> 5;
    int lane = threadIdx.x & 31;
    const float4* Qr = reinterpret_cast<const float4*>(Q) + (size_t)gw * (MD/4);
    const float4* K4 = reinterpret_cast<const float4*>(g_kdx);
    const float4* M4 = reinterpret_cast<const float4*>(mu);
    float s[5] = {0,0,0,0,0};
#pragma unroll 4
    for (int jb = lane; jb < MD/4; jb += 32) {
        float4 qv = Qr[jb], kv = K4[jb];
        s[0] += qv.x*kv.x + qv.y*kv.y + qv.z*kv.z + qv.w*kv.w;
#pragma unroll
        for (int yd = 0; yd < 4; yd++) {
            float4 mv = M4[yd*(MD/4) + jb];
            s[1+yd] += qv.x*mv.x + qv.y*mv.y + qv.z*mv.z + qv.w*mv.w;
        }
    }
#pragma unroll
    for (int o = 16; o > 0; o >>= 1)
#pragma unroll
        for (int r = 0; r < 5; r++) s[r] += __shfl_xor_sync(0xffffffffu, s[r], o);
    if (lane == 0) {
        g_q[gw] = s[0];
        float sf = sqrtf(FFC);
#pragma unroll
        for (int yd = 0; yd < 4; yd++) g_Qmu[yd*MD + gw] = sf * s[1+yd];
    }
}

// -------- scalars 1: pu, pred_mean --------
__global__ void k_scalars1(const float* __restrict__ mu) {
    __shared__ float red[5][8];
    int tid = threadIdx.x;
    float s[5] = {0,0,0,0,0};
    for (int i = tid; i < MD; i += 256) {
        float qi = g_q[i];
        s[0] += g_kdx[i] * qi;
#pragma unroll
        for (int yd = 0; yd < 4; yd++) s[1+yd] += qi * mu[yd*MD + i];
    }
#pragma unroll
    for (int o = 16; o > 0; o >>= 1)
#pragma unroll
        for (int r = 0; r < 5; r++) s[r] += __shfl_xor_sync(0xffffffffu, s[r], o);
    if ((tid & 31) == 0)
#pragma unroll
        for (int r = 0; r < 5; r++) red[r][tid >> 5] = s[r];
    __syncthreads();
    if (tid == 0) {
        float t[5];
#pragma unroll
        for (int r = 0; r < 5; r++) { t[r] = 0.f;
#pragma unroll
            for (int w = 0; w < 8; w++) t[r] += red[r][w]; }
        gs_pu = fmaxf((1.0f + JIT) - t[0], 0.0f);
        float sf = sqrtf(FFC);
#pragma unroll
        for (int yd = 0; yd < 4; yd++) gs_pm[yd] = sf * t[1+yd];
    }
}

// -------- hsig = sigma @ q (warp per row) --------
__global__ void k_sigq(const float* __restrict__ sigma) {
    int gw = (blockIdx.x * 256 + threadIdx.x) >> 5;
    int lane = threadIdx.x & 31;
    const float4* Sr = reinterpret_cast<const float4*>(sigma) + (size_t)gw * (MD/4);
    const float4* Q4 = reinterpret_cast<const float4*>(g_q);
    float s = 0.f;
#pragma unroll 8
    for (int jb = lane; jb < MD/4; jb += 32) {
        float4 sv = Sr[jb], qv = Q4[jb];
        s += sv.x*qv.x + sv.y*qv.y + sv.z*qv.z + sv.w*qv.w;
    }
#pragma unroll
    for (int o = 16; o > 0; o >>= 1) s += __shfl_xor_sync(0xffffffffu, s, o);
    if (lane == 0) g_hsig[gw] = s;
}

// =================== Tensor-core Kdd GEMM machinery ====================
#define LDB36 36    // u32 row stride (72 bf16) for A/B tiles
#define STGLD 132   // float row stride for the staging buffer

__device__ __forceinline__ void fill_tiles(unsigned* AsU, unsigned* BsU,
                                           const float* __restrict__ dict,
                                           int I0, int J0, int tid) {
    const float4* dI = reinterpret_cast<const float4*>(dict + (size_t)I0 * DD);
    const float4* dJ = reinterpret_cast<const float4*>(dict + (size_t)J0 * DD);
    for (int idx = tid; idx < 2048; idx += 256) {
        int r = idx >> 4, c4 = idx & 15;
        float4 v = dI[r*16 + c4];
        AsU[r*LDB36 + c4*2]     = pk_bf2(v.x, v.y);
        AsU[r*LDB36 + c4*2 + 1] = pk_bf2(v.z, v.w);
        float4 w = dJ[r*16 + c4];
        BsU[r*LDB36 + c4*2]     = pk_bf2(w.x, w.y);
        BsU[r*LDB36 + c4*2 + 1] = pk_bf2(w.z, w.w);
    }
}

__device__ __forceinline__ void gemm_tiles(const unsigned* AsU, const unsigned* BsU,
                                           float acc[4][4][4], int wm, int wn,
                                           int g, int t) {
#pragma unroll
    for (int ks = 0; ks < 4; ks++) {
        unsigned bf[4][2];
#pragma unroll
        for (int n = 0; n < 4; n++) {
            int rb = wn*32 + n*8 + g;
            bf[n][0] = BsU[rb*LDB36 + ks*8 + t];
            bf[n][1] = BsU[rb*LDB36 + ks*8 + t + 4];
        }
#pragma unroll
        for (int m = 0; m < 4; m++) {
            int ra = wm*64 + m*16 + g;
            unsigned a0 = AsU[ra*LDB36 + ks*8 + t];
            unsigned a1 = AsU[(ra+8)*LDB36 + ks*8 + t];
            unsigned a2 = AsU[ra*LDB36 + ks*8 + t + 4];
            unsigned a3 = AsU[(ra+8)*LDB36 + ks*8 + t + 4];
#pragma unroll
            for (int n = 0; n < 4; n++)
                mma16816(acc[m][n], a0, a1, a2, a3, bf[n][0], bf[n][1]);
        }
    }
}

// -------- pass 1: Kdd bf16 cache + (Kdd@q) row partials (no sigma) ----
__global__ void __launch_bounds__(256, 2) k_pass1(const float* __restrict__ dict) {
    __shared__ __align__(16) char raw[128*LDB36*4*2];   // A/B tiles, then stage
    __shared__ float qs[128], nIv[128], nJv[128], aIv[128], aJv[128];

    unsigned* AsU = reinterpret_cast<unsigned*>(raw);
    unsigned* BsU = AsU + 128*LDB36;
    float* stage  = reinterpret_cast<float*>(raw);      // 64*STGLD floats

    int tid = threadIdx.x;
    int lane = tid & 31, w = tid >> 5;
    int g = lane >> 2, t = lane & 3;
    int wm = w >> 2, wn = w & 3;
    int I0 = blockIdx.y * 128, J0 = blockIdx.x * 128;

    fill_tiles(AsU, BsU, dict, I0, J0, tid);
    if (tid < 128) {
        qs[tid]  = g_q[J0 + tid];
        nJv[tid] = g_norm[J0 + tid]; aJv[tid] = g_alloc[J0 + tid];
        nIv[tid] = g_norm[I0 + tid]; aIv[tid] = g_alloc[I0 + tid];
    }
    __syncthreads();

    float acc[4][4][4];
#pragma unroll
    for (int m = 0; m < 4; m++)
#pragma unroll
        for (int n = 0; n < 4; n++)
#pragma unroll
            for (int r = 0; r < 4; r++) acc[m][n][r] = 0.f;

    gemm_tiles(AsU, BsU, acc, wm, wn, g, t);

#pragma unroll
    for (int half = 0; half < 2; half++) {
        __syncthreads();
        if (wm == half) {
#pragma unroll
            for (int m = 0; m < 4; m++)
#pragma unroll
                for (int n = 0; n < 4; n++)
#pragma unroll
                    for (int hf = 0; hf < 2; hf++) {
                        int rl = m*16 + g + 8*hf;
                        int cl = wn*32 + n*8 + 2*t;
                        *reinterpret_cast<float2*>(&stage[rl*STGLD + cl]) =
                            make_float2(acc[m][n][2*hf], acc[m][n][2*hf+1]);
                    }
        }
        __syncthreads();
#pragma unroll
        for (int r8 = 0; r8 < 8; r8++) {
            int r  = r8*8 + w;
            int ig = I0 + half*64 + r;
            float ni = nIv[half*64 + r], ai = aIv[half*64 + r];
            float4 ac = *reinterpret_cast<const float4*>(&stage[r*STGLD + lane*4]);
            int c0 = lane*4;
            float kd[4];
            float av[4] = {ac.x, ac.y, ac.z, ac.w};
            float hsum = 0.f;
#pragma unroll
            for (int c = 0; c < 4; c++) {
                float d2 = fmaxf(ni + nJv[c0+c] - 2.0f*av[c], 0.0f);
                kd[c] = __expf(-d2 * INV2LS2) * ai * aJv[c0+c];
                hsum += kd[c] * qs[c0+c];
            }
            uint2 pk;
            pk.x = pk_bf2(kd[0], kd[1]);
            pk.y = pk_bf2(kd[2], kd[3]);
            __stcs(reinterpret_cast<uint2*>(g_kddbf + (size_t)ig*MD + J0 + c0), pk);
#pragma unroll
            for (int o = 16; o > 0; o >>= 1)
                hsum += __shfl_xor_sync(0xffffffffu, hsum, o);
            if (lane == 0) g_hpart[(size_t)blockIdx.x*MD + ig] = hsum;
        }
    }
}

// -------- h combine + scalars2 fused (one block) --------
__global__ void k_hscal(const float* __restrict__ y, const float* __restrict__ nn,
                        const float* __restrict__ nd, float* __restrict__ out) {
    __shared__ float red[8];
    int tid = threadIdx.x;
    float qh_p = 0.f;
    for (int i = tid; i < MD; i += 256) {
        float s = 0.f;
#pragma unroll
        for (int b = 0; b < NJB; b++) s += g_hpart[(size_t)b*MD + i];
        float h = FFC * g_hsig[i] + (1.0f - FFC) * s;
        g_h[i] = h;
        qh_p += g_q[i] * h;
    }
#pragma unroll
    for (int o = 16; o > 0; o >>= 1) qh_p += __shfl_xor_sync(0xffffffffu, qh_p, o);
    if ((tid & 31) == 0) red[tid >> 5] = qh_p;
    __syncthreads();
    if (tid == 0) {
        float qh = 0.f;
#pragma unroll
        for (int w2 = 0; w2 < 8; w2++) qh += red[w2];
        gs_qh = qh;
        float pu = gs_pu;
        float npv = fmaxf(pu + qh, 0.0f);
        float pv = REGC + npv;
        gs_npv = npv; gs_pv = pv;
        float cm = 0.f;
#pragma unroll
        for (int yd = 0; yd < 4; yd++) {
            float dy = y[yd] - gs_pm[yd];
            float c = dy / pv;
            gs_c[yd] = c;
            out[OFF_NN + yd] = nn[yd] + FFC * dy * dy / pv;
            cm += fabsf(c * (npv - qh));
        }
        out[OFF_ND] = nd[0] + FFC;
        gs_critM = cm;
    }
}

// -------- Qh = Q@h fused with criterion + per-block argmin --------
__global__ void k_qhcrit(const float* __restrict__ Q) {
    __shared__ float sv[8]; __shared__ int si[8];
    int tid = threadIdx.x;
    int gw = (blockIdx.x * 256 + tid) >> 5;
    int lane = tid & 31;
    const float4* Qr = reinterpret_cast<const float4*>(Q) + (size_t)gw * (MD/4);
    const float4* H4 = reinterpret_cast<const float4*>(g_h);
    float s = 0.f;
#pragma unroll 4
    for (int jb = lane; jb < MD/4; jb += 32) {
        float4 qv = Qr[jb], hv = H4[jb];
        s += qv.x*hv.x + qv.y*hv.y + qv.z*hv.z + qv.w*hv.w;
    }
#pragma unroll
    for (int o = 16; o > 0; o >>= 1) s += __shfl_xor_sync(0xffffffffu, s, o);
    if (lane == 0) {
        float pu = gs_pu;
        float cv;
        if (pu < JIT) {
            cv = 0.f;
        } else {
            float qi = g_q[gw];
            float dq = (g_alloc[gw] != 0.f) ? (Q[(size_t)gw*MD + gw] + qi*qi/pu)
                                            : __int_as_float(0x7f800000);
            float r = qi / pu;
            float qhm = gs_qh - gs_npv;
            float acc2 = 0.f;
#pragma unroll
            for (int yd = 0; yd < 4; yd++) {
                float num = g_Qmu[yd*MD + gw] + gs_c[yd]*s + r*gs_c[yd]*qhm;
                acc2 += fabsf(num / dq);
            }
            cv = acc2;
        }
        sv[tid >> 5] = cv; si[tid >> 5] = gw;
    }
    __syncthreads();
    if (tid == 0) {
        float bv = sv[0]; int bi = si[0];
#pragma unroll
        for (int w2 = 1; w2 < 8; w2++) {
            if (sv[w2] < bv || (sv[w2] == bv && si[w2] < bi)) { bv = sv[w2]; bi = si[w2]; }
        }
        g_pval[blockIdx.x] = bv; g_pidx[blockIdx.x] = bi;
    }
}

// -------- argmin finalize + prune scalars --------
__global__ void k_finalize(const float* __restrict__ Q, const int* __restrict__ tptr) {
    if (threadIdx.x != 0) return;
    float pu = gs_pu;
    int bi;
    if (pu < JIT) {
        bi = MD;
    } else {
        float bv = g_pval[0]; bi = g_pidx[0];
        for (int b = 1; b < 512; b++) {
            float v = g_pval[b]; int ix = g_pidx[b];
            if (v < bv || (v == bv && ix < bi)) { bv = v; bi = ix; }
        }
        if (gs_critM < bv) bi = MD;
    }
    gs_prune = bi;
    float qp = (bi < MD) ? g_q[bi] : 0.0f;
    gs_qp = qp;
    bool xal = (bi == MD) ? true : (g_alloc[bi] != 0.f);
    float qaa = (bi == MD) ? (1.0f/pu) : (Q[(size_t)bi*MD + bi] + qp*qp/pu);
    gs_denom = xal ? qaa : __int_as_float(0x7f800000);
    int bits = tptr[0];
    gs_tval = (bits >= 0 && bits < (1 << 26)) ? (float)bits : __int_as_float(bits);
}

__global__ void k_colp(const float* __restrict__ Q) {
    int i = blockIdx.x * 256 + threadIdx.x;
    int p = gs_prune;
    g_colp[i] = (p < MD) ? Q[(size_t)i*MD + p] : 0.0f;
}

// -------- fused Q_n + sig_n writer (row per block, 2x MLP) --------
__device__ __forceinline__ float qn_elem(int p, bool rowp, int j, float Qij,
                                         float qi, float qj, float colj,
                                         float qp, float ipu, float Bi, float dinv) {
    float m, Bj;
    if (p < MD) {
        if (rowp) m = (j == p) ? ipu : (-qj * ipu);
        else      m = (j == p) ? (-qi * ipu) : (Qij + qi*qj*ipu);
        Bj = (j == p) ? (-qp * ipu) : (colj + qj*qp*ipu);
    } else {
        m  = Qij + qi*qj*ipu;
        Bj = -qj * ipu;
    }
    return m - Bi * Bj * dinv;
}

__global__ void k_post(const float* __restrict__ Q, const float* __restrict__ sigma,
                       const float* __restrict__ TI, float* __restrict__ out) {
    int i = blockIdx.x;
    int tid = threadIdx.x;
    int p = gs_prune;
    float pu = gs_pu, qp = gs_qp, qi = g_q[i];
    float ipu = 1.0f / pu;
    float dinv = 1.0f / gs_denom;
    float npv = gs_npv, ivp = 1.0f / gs_pv, tval = gs_tval;
    bool rowp = (p < MD) && (i == p);
    float Bi = (p < MD) ? (rowp ? (-qp*ipu) : (g_colp[i] + qi*qp*ipu)) : (-qi*ipu);
    float hi = g_h[i];
    float tni = rowp ? tval : TI[i];
    float mi = (tni >= 0.f) ? 1.f : 0.f;
    float ppi = rowp ? npv : hi;

    const float4* Qr = reinterpret_cast<const float4*>(Q + (size_t)i*MD);
    const float4* Sr = reinterpret_cast<const float4*>(sigma + (size_t)i*MD);
    const uint2*  Kr = reinterpret_cast<const uint2*>(g_kddbf + (size_t)i*MD);
    float4* oq = reinterpret_cast<float4*>(out + OFF_Q + (size_t)i*MD);
    float4* os = reinterpret_cast<float4*>(out + OFF_SIG + (size_t)i*MD);
    const float4* q4 = reinterpret_cast<const float4*>(g_q);
    const float4* c4 = reinterpret_cast<const float4*>(g_colp);
    const float4* h4 = reinterpret_cast<const float4*>(g_h);
    const float4* t4 = reinterpret_cast<const float4*>(TI);

#pragma unroll
    for (int base = 0; base < MD/4; base += 512) {
        int ja = base + tid;
        int jb2 = ja + 256;
        // batch independent loads (6 global streams x 2)
        float4 Qa = Qr[ja];        float4 Qb = Qr[jb2];
        float4 sa = __ldcs(&Sr[ja]); float4 sb = __ldcs(&Sr[jb2]);
        uint2  ka = __ldcs(&Kr[ja]); uint2  kb = __ldcs(&Kr[jb2]);
        float4 qa = q4[ja];        float4 qb = q4[jb2];
        float4 ca = c4[ja];        float4 cb = c4[jb2];
        float4 ha = h4[ja];        float4 hb = h4[jb2];
        float4 ta = t4[ja];        float4 tb = t4[jb2];

#pragma unroll
        for (int seg = 0; seg < 2; seg++) {
            int jb = seg ? jb2 : ja;
            float4 Qv = seg ? Qb : Qa;
            float4 sg = seg ? sb : sa;
            uint2  kp = seg ? kb : ka;
            float4 qq = seg ? qb : qa;
            float4 cc = seg ? cb : ca;
            float4 hh = seg ? hb : ha;
            float4 tt = seg ? tb : ta;
            int j0 = jb * 4;

            float4 oqv;
            oqv.x = qn_elem(p, rowp, j0+0, Qv.x, qi, qq.x, cc.x, qp, ipu, Bi, dinv);
            oqv.y = qn_elem(p, rowp, j0+1, Qv.y, qi, qq.y, cc.y, qp, ipu, Bi, dinv);
            oqv.z = qn_elem(p, rowp, j0+2, Qv.z, qi, qq.z, cc.z, qp, ipu, Bi, dinv);
            oqv.w = qn_elem(p, rowp, j0+3, Qv.w, qi, qq.w, cc.w, qp, ipu, Bi, dinv);
            __stcs(&oq[jb], oqv);

            float2 k01 = __bfloat1622float2(*reinterpret_cast<const __nv_bfloat162*>(&kp.x));
            float2 k23 = __bfloat1622float2(*reinterpret_cast<const __nv_bfloat162*>(&kp.y));
            float kdf[4] = {k01.x, k01.y, k23.x, k23.y};
            float svv[4] = {sg.x, sg.y, sg.z, sg.w};
            float hvv[4] = {hh.x, hh.y, hh.z, hh.w};
            float tvv[4] = {tt.x, tt.y, tt.z, tt.w};
            float ov[4];
#pragma unroll
            for (int c = 0; c < 4; c++) {
                int j = j0 + c;
                float spre = FFC*svv[c] + (1.0f-FFC)*kdf[c];
                bool colp = (p < MD) && (j == p);
                float tj = colp ? tval : tvv[c];
                float mj = (tj >= 0.f) ? 1.f : 0.f;
                float ms  = rowp ? (colp ? npv : hvv[c]) : (colp ? hi : spre);
                float ppj = colp ? npv : hvv[c];
                ov[c] = mi * mj * (ms - ppi * ppj * ivp);
            }
            float4 osv; osv.x=ov[0]; osv.y=ov[1]; osv.z=ov[2]; osv.w=ov[3];
            __stcs(&os[jb], osv);
        }
    }
}

// -------- tail: mu_n, dict_n, ti_n --------
__global__ void k_tail(const float* __restrict__ mu, const float* __restrict__ dict,
                       const float* __restrict__ x, const float* __restrict__ TI,
                       float* __restrict__ out) {
    int idx = blockIdx.x * 256 + threadIdx.x;   // 65536 threads
    int p = gs_prune;
    float tval = gs_tval;
    {
        int row = idx >> 4, c4i = idx & 15;
        float4 v;
        if (p < MD && row == p) v = *reinterpret_cast<const float4*>(x + c4i*4);
        else v = *reinterpret_cast<const float4*>(dict + (size_t)row*DD + c4i*4);
        *reinterpret_cast<float4*>(out + OFF_DICT + (size_t)row*DD + c4i*4) = v;
    }
    if (idx < MD) {
        bool rowp = (p < MD) && (idx == p);
        float tn = rowp ? tval : TI[idx];
        out[OFF_TI + idx] = tn;
        float sf = sqrtf(FFC);
        float hi = g_h[idx];
#pragma unroll
        for (int yd = 0; yd < 4; yd++) {
            float val;
            if (tn < 0.f) val = 0.f;
            else if (rowp) val = gs_pm[yd] + gs_c[yd] * gs_npv;
            else val = sf * mu[yd*MD + idx] + gs_c[yd] * hi;
            out[OFF_MU + yd*MD + idx] = val;
        }
    }
}

extern "C" void kernel_launch(void* const* d_in, const int* in_sizes, int n_in,
                              void* d_out, int out_size) {
    const float* dict = (const float*)d_in[0];
    const float* mu   = (const float*)d_in[1];
    const float* sigma= (const float*)d_in[2];
    const float* Q    = (const float*)d_in[3];
    const float* x    = (const float*)d_in[4];
    const float* y    = (const float*)d_in[5];
    const float* nn   = (const float*)d_in[6];
    const float* nd   = (const float*)d_in[7];
    const float* ti   = (const float*)d_in[8];
    const int*   tptr = (const int*)d_in[9];
    float* out = (float*)d_out;

    k_kdx<<<16, 256>>>(dict, x, ti);
    k_matvec5<<<512, 256>>>(Q, mu);
    k_scalars1<<<1, 256>>>(mu);
    k_pass1<<<dim3(32,32), 256>>>(dict);
    k_sigq<<<512, 256>>>(sigma);
    k_hscal<<<1, 256>>>(y, nn, nd, out);
    k_qhcrit<<<512, 256>>>(Q);
    k_finalize<<<1, 32>>>(Q, tptr);
    k_colp<<<16, 256>>>(Q);
    k_post<<<4096, 256>>>(Q, sigma, ti, out);
    k_tail<<<256, 256>>>(mu, dict, x, ti, out);
}

// round 7
// speedup vs baseline: 1.0686x; 1.0686x over previous
#include <cuda_runtime.h>
#include <cuda_bf16.h>
#include <math.h>

#define MD 4096
#define DD 64
#define NJB 32
#define FFC 0.999f
#define REGC 0.01f
#define JIT 1e-10f
#define INV2LS2 (1.0f/128.0f)

#define OFF_MU   ((size_t)0)
#define OFF_SIG  ((size_t)16384)
#define OFF_Q    (OFF_SIG + (size_t)MD*MD)
#define OFF_DICT (OFF_Q   + (size_t)MD*MD)
#define OFF_TI   (OFF_DICT + (size_t)MD*DD)
#define OFF_NN   (OFF_TI + MD)
#define OFF_ND   (OFF_NN + 4)

// -------- scratch (device globals; allocations forbidden) --------
static __device__ float g_kdx[MD], g_alloc[MD], g_norm[MD];
static __device__ float g_q[MD], g_h[MD], g_hsig[MD], g_Qmu[4*MD];
static __device__ float g_hpart[NJB*MD];
static __device__ float g_colp[MD];
static __device__ __nv_bfloat16 g_kddbf[(size_t)MD*MD];   // 33.5 MB bf16 Kdd cache
static __device__ float g_pval[512];
static __device__ int   g_pidx[512];
static __device__ float gs_pu, gs_pm[4], gs_qh, gs_npv, gs_pv, gs_c[4];
static __device__ float gs_critM, gs_denom, gs_qp, gs_tval;
static __device__ int   gs_prune;

__device__ __forceinline__ unsigned pk_bf2(float a, float b) {
    __nv_bfloat162 h = __floats2bfloat162_rn(a, b);
    return *reinterpret_cast<unsigned*>(&h);
}

__device__ __forceinline__ void mma16816(float* c, unsigned a0, unsigned a1,
                                         unsigned a2, unsigned a3,
                                         unsigned b0, unsigned b1) {
    asm volatile(
        "mma.sync.aligned.m16n8k16.row.col.f32.bf16.bf16.f32 "
        "{%0,%1,%2,%3},{%4,%5,%6,%7},{%8,%9},{%0,%1,%2,%3};\n"
        : "+f"(c[0]), "+f"(c[1]), "+f"(c[2]), "+f"(c[3])
        : "r"(a0), "r"(a1), "r"(a2), "r"(a3), "r"(b0), "r"(b1));
}

// -------- K_dx, alloc, row norms --------
__global__ void k_kdx(const float* __restrict__ dict, const float* __restrict__ x,
                      const float* __restrict__ ti) {
    __shared__ float xs[DD];
    int tid = threadIdx.x;
    if (tid < DD) xs[tid] = x[tid];
    __syncthreads();
    int i = blockIdx.x * 256 + tid;
    const float* dr = dict + (size_t)i * DD;
    float a2 = 0.f, ip = 0.f, x2 = 0.f;
#pragma unroll
    for (int k = 0; k < DD; k++) { float d = dr[k], xv = xs[k]; a2 += d*d; ip += d*xv; x2 += xv*xv; }
    float d2 = fmaxf(a2 + x2 - 2.0f*ip, 0.0f);
    float al = (ti[i] >= 0.0f) ? 1.0f : 0.0f;
    g_kdx[i] = __expf(-d2 * INV2LS2) * al;
    g_alloc[i] = al;
    g_norm[i] = a2;
}

// -------- q = Q@kdx, Qmu = sqrt(FF)*Q@mu (warp per row) --------
__global__ void k_matvec5(const float* __restrict__ Q, const float* __restrict__ mu) {
    int gw = (blockIdx.x * 256 + threadIdx.x) >> 5;
    int lane = threadIdx.x & 31;
    const float4* Qr = reinterpret_cast<const float4*>(Q) + (size_t)gw * (MD/4);
    const float4* K4 = reinterpret_cast<const float4*>(g_kdx);
    const float4* M4 = reinterpret_cast<const float4*>(mu);
    float s[5] = {0,0,0,0,0};
#pragma unroll 4
    for (int jb = lane; jb < MD/4; jb += 32) {
        float4 qv = Qr[jb], kv = K4[jb];
        s[0] += qv.x*kv.x + qv.y*kv.y + qv.z*kv.z + qv.w*kv.w;
#pragma unroll
        for (int yd = 0; yd < 4; yd++) {
            float4 mv = M4[yd*(MD/4) + jb];
            s[1+yd] += qv.x*mv.x + qv.y*mv.y + qv.z*mv.z + qv.w*mv.w;
        }
    }
#pragma unroll
    for (int o = 16; o > 0; o >>= 1)
#pragma unroll
        for (int r = 0; r < 5; r++) s[r] += __shfl_xor_sync(0xffffffffu, s[r], o);
    if (lane == 0) {
        g_q[gw] = s[0];
        float sf = sqrtf(FFC);
#pragma unroll
        for (int yd = 0; yd < 4; yd++) g_Qmu[yd*MD + gw] = sf * s[1+yd];
    }
}

// -------- scalars 1: pu, pred_mean --------
__global__ void k_scalars1(const float* __restrict__ mu) {
    __shared__ float red[5][8];
    int tid = threadIdx.x;
    float s[5] = {0,0,0,0,0};
    for (int i = tid; i < MD; i += 256) {
        float qi = g_q[i];
        s[0] += g_kdx[i] * qi;
#pragma unroll
        for (int yd = 0; yd < 4; yd++) s[1+yd] += qi * mu[yd*MD + i];
    }
#pragma unroll
    for (int o = 16; o > 0; o >>= 1)
#pragma unroll
        for (int r = 0; r < 5; r++) s[r] += __shfl_xor_sync(0xffffffffu, s[r], o);
    if ((tid & 31) == 0)
#pragma unroll
        for (int r = 0; r < 5; r++) red[r][tid >> 5] = s[r];
    __syncthreads();
    if (tid == 0) {
        float t[5];
#pragma unroll
        for (int r = 0; r < 5; r++) { t[r] = 0.f;
#pragma unroll
            for (int w = 0; w < 8; w++) t[r] += red[r][w]; }
        gs_pu = fmaxf((1.0f + JIT) - t[0], 0.0f);
        float sf = sqrtf(FFC);
#pragma unroll
        for (int yd = 0; yd < 4; yd++) gs_pm[yd] = sf * t[1+yd];
    }
}

// -------- hsig = sigma @ q (warp per row) --------
__global__ void k_sigq(const float* __restrict__ sigma) {
    int gw = (blockIdx.x * 256 + threadIdx.x) >> 5;
    int lane = threadIdx.x & 31;
    const float4* Sr = reinterpret_cast<const float4*>(sigma) + (size_t)gw * (MD/4);
    const float4* Q4 = reinterpret_cast<const float4*>(g_q);
    float s = 0.f;
#pragma unroll 8
    for (int jb = lane; jb < MD/4; jb += 32) {
        float4 sv = Sr[jb], qv = Q4[jb];
        s += sv.x*qv.x + sv.y*qv.y + sv.z*qv.z + sv.w*qv.w;
    }
#pragma unroll
    for (int o = 16; o > 0; o >>= 1) s += __shfl_xor_sync(0xffffffffu, s, o);
    if (lane == 0) g_hsig[gw] = s;
}

// =================== Tensor-core Kdd GEMM machinery ====================
#define LDB36 36    // u32 row stride (72 bf16) for A/B tiles
#define STGLD 132   // float row stride for the staging buffer

__device__ __forceinline__ void fill_tiles(unsigned* AsU, unsigned* BsU,
                                           const float* __restrict__ dict,
                                           int I0, int J0, int tid) {
    const float4* dI = reinterpret_cast<const float4*>(dict + (size_t)I0 * DD);
    const float4* dJ = reinterpret_cast<const float4*>(dict + (size_t)J0 * DD);
    for (int idx = tid; idx < 2048; idx += 256) {
        int r = idx >> 4, c4 = idx & 15;
        float4 v = dI[r*16 + c4];
        AsU[r*LDB36 + c4*2]     = pk_bf2(v.x, v.y);
        AsU[r*LDB36 + c4*2 + 1] = pk_bf2(v.z, v.w);
        float4 w = dJ[r*16 + c4];
        BsU[r*LDB36 + c4*2]     = pk_bf2(w.x, w.y);
        BsU[r*LDB36 + c4*2 + 1] = pk_bf2(w.z, w.w);
    }
}

__device__ __forceinline__ void gemm_tiles(const unsigned* AsU, const unsigned* BsU,
                                           float acc[4][4][4], int wm, int wn,
                                           int g, int t) {
#pragma unroll
    for (int ks = 0; ks < 4; ks++) {
        unsigned bf[4][2];
#pragma unroll
        for (int n = 0; n < 4; n++) {
            int rb = wn*32 + n*8 + g;
            bf[n][0] = BsU[rb*LDB36 + ks*8 + t];
            bf[n][1] = BsU[rb*LDB36 + ks*8 + t + 4];
        }
#pragma unroll
        for (int m = 0; m < 4; m++) {
            int ra = wm*64 + m*16 + g;
            unsigned a0 = AsU[ra*LDB36 + ks*8 + t];
            unsigned a1 = AsU[(ra+8)*LDB36 + ks*8 + t];
            unsigned a2 = AsU[ra*LDB36 + ks*8 + t + 4];
            unsigned a3 = AsU[(ra+8)*LDB36 + ks*8 + t + 4];
#pragma unroll
            for (int n = 0; n < 4; n++)
                mma16816(acc[m][n], a0, a1, a2, a3, bf[n][0], bf[n][1]);
        }
    }
}

// -------- pass 1: Kdd bf16 cache + (Kdd@q) row partials (no sigma) ----
__global__ void __launch_bounds__(256, 2) k_pass1(const float* __restrict__ dict) {
    __shared__ __align__(16) char raw[128*LDB36*4*2];   // A/B tiles, then stage
    __shared__ float qs[128], nIv[128], nJv[128], aIv[128], aJv[128];

    unsigned* AsU = reinterpret_cast<unsigned*>(raw);
    unsigned* BsU = AsU + 128*LDB36;
    float* stage  = reinterpret_cast<float*>(raw);      // 64*STGLD floats

    int tid = threadIdx.x;
    int lane = tid & 31, w = tid >> 5;
    int g = lane >> 2, t = lane & 3;
    int wm = w >> 2, wn = w & 3;
    int I0 = blockIdx.y * 128, J0 = blockIdx.x * 128;

    fill_tiles(AsU, BsU, dict, I0, J0, tid);
    if (tid < 128) {
        qs[tid]  = g_q[J0 + tid];
        nJv[tid] = g_norm[J0 + tid]; aJv[tid] = g_alloc[J0 + tid];
        nIv[tid] = g_norm[I0 + tid]; aIv[tid] = g_alloc[I0 + tid];
    }
    __syncthreads();

    float acc[4][4][4];
#pragma unroll
    for (int m = 0; m < 4; m++)
#pragma unroll
        for (int n = 0; n < 4; n++)
#pragma unroll
            for (int r = 0; r < 4; r++) acc[m][n][r] = 0.f;

    gemm_tiles(AsU, BsU, acc, wm, wn, g, t);

#pragma unroll
    for (int half = 0; half < 2; half++) {
        __syncthreads();
        if (wm == half) {
#pragma unroll
            for (int m = 0; m < 4; m++)
#pragma unroll
                for (int n = 0; n < 4; n++)
#pragma unroll
                    for (int hf = 0; hf < 2; hf++) {
                        int rl = m*16 + g + 8*hf;
                        int cl = wn*32 + n*8 + 2*t;
                        *reinterpret_cast<float2*>(&stage[rl*STGLD + cl]) =
                            make_float2(acc[m][n][2*hf], acc[m][n][2*hf+1]);
                    }
        }
        __syncthreads();
#pragma unroll
        for (int r8 = 0; r8 < 8; r8++) {
            int r  = r8*8 + w;
            int ig = I0 + half*64 + r;
            float ni = nIv[half*64 + r], ai = aIv[half*64 + r];
            float4 ac = *reinterpret_cast<const float4*>(&stage[r*STGLD + lane*4]);
            int c0 = lane*4;
            float kd[4];
            float av[4] = {ac.x, ac.y, ac.z, ac.w};
            float hsum = 0.f;
#pragma unroll
            for (int c = 0; c < 4; c++) {
                float d2 = fmaxf(ni + nJv[c0+c] - 2.0f*av[c], 0.0f);
                kd[c] = __expf(-d2 * INV2LS2) * ai * aJv[c0+c];
                hsum += kd[c] * qs[c0+c];
            }
            uint2 pk;
            pk.x = pk_bf2(kd[0], kd[1]);
            pk.y = pk_bf2(kd[2], kd[3]);
            __stcs(reinterpret_cast<uint2*>(g_kddbf + (size_t)ig*MD + J0 + c0), pk);
#pragma unroll
            for (int o = 16; o > 0; o >>= 1)
                hsum += __shfl_xor_sync(0xffffffffu, hsum, o);
            if (lane == 0) g_hpart[(size_t)blockIdx.x*MD + ig] = hsum;
        }
    }
}

// -------- h combine + scalars2 fused (one block) --------
__global__ void k_hscal(const float* __restrict__ y, const float* __restrict__ nn,
                        const float* __restrict__ nd, float* __restrict__ out) {
    __shared__ float red[8];
    int tid = threadIdx.x;
    float qh_p = 0.f;
    for (int i = tid; i < MD; i += 256) {
        float s = 0.f;
#pragma unroll
        for (int b = 0; b < NJB; b++) s += g_hpart[(size_t)b*MD + i];
        float h = FFC * g_hsig[i] + (1.0f - FFC) * s;
        g_h[i] = h;
        qh_p += g_q[i] * h;
    }
#pragma unroll
    for (int o = 16; o > 0; o >>= 1) qh_p += __shfl_xor_sync(0xffffffffu, qh_p, o);
    if ((tid & 31) == 0) red[tid >> 5] = qh_p;
    __syncthreads();
    if (tid == 0) {
        float qh = 0.f;
#pragma unroll
        for (int w2 = 0; w2 < 8; w2++) qh += red[w2];
        gs_qh = qh;
        float pu = gs_pu;
        float npv = fmaxf(pu + qh, 0.0f);
        float pv = REGC + npv;
        gs_npv = npv; gs_pv = pv;
        float cm = 0.f;
#pragma unroll
        for (int yd = 0; yd < 4; yd++) {
            float dy = y[yd] - gs_pm[yd];
            float c = dy / pv;
            gs_c[yd] = c;
            out[OFF_NN + yd] = nn[yd] + FFC * dy * dy / pv;
            cm += fabsf(c * (npv - qh));
        }
        out[OFF_ND] = nd[0] + FFC;
        gs_critM = cm;
    }
}

// -------- Qh = Q@h fused with criterion + per-block argmin --------
__global__ void k_qhcrit(const float* __restrict__ Q) {
    __shared__ float sv[8]; __shared__ int si[8];
    int tid = threadIdx.x;
    int gw = (blockIdx.x * 256 + tid) >> 5;
    int lane = tid & 31;
    const float4* Qr = reinterpret_cast<const float4*>(Q) + (size_t)gw * (MD/4);
    const float4* H4 = reinterpret_cast<const float4*>(g_h);
    float s = 0.f;
#pragma unroll 4
    for (int jb = lane; jb < MD/4; jb += 32) {
        float4 qv = Qr[jb], hv = H4[jb];
        s += qv.x*hv.x + qv.y*hv.y + qv.z*hv.z + qv.w*hv.w;
    }
#pragma unroll
    for (int o = 16; o > 0; o >>= 1) s += __shfl_xor_sync(0xffffffffu, s, o);
    if (lane == 0) {
        float pu = gs_pu;
        float cv;
        if (pu < JIT) {
            cv = 0.f;
        } else {
            float qi = g_q[gw];
            float dq = (g_alloc[gw] != 0.f) ? (Q[(size_t)gw*MD + gw] + qi*qi/pu)
                                            : __int_as_float(0x7f800000);
            float r = qi / pu;
            float qhm = gs_qh - gs_npv;
            float acc2 = 0.f;
#pragma unroll
            for (int yd = 0; yd < 4; yd++) {
                float num = g_Qmu[yd*MD + gw] + gs_c[yd]*s + r*gs_c[yd]*qhm;
                acc2 += fabsf(num / dq);
            }
            cv = acc2;
        }
        sv[tid >> 5] = cv; si[tid >> 5] = gw;
    }
    __syncthreads();
    if (tid == 0) {
        float bv = sv[0]; int bi = si[0];
#pragma unroll
        for (int w2 = 1; w2 < 8; w2++) {
            if (sv[w2] < bv || (sv[w2] == bv && si[w2] < bi)) { bv = sv[w2]; bi = si[w2]; }
        }
        g_pval[blockIdx.x] = bv; g_pidx[blockIdx.x] = bi;
    }
}

// -------- argmin finalize + prune scalars --------
__global__ void k_finalize(const float* __restrict__ Q, const int* __restrict__ tptr) {
    if (threadIdx.x != 0) return;
    float pu = gs_pu;
    int bi;
    if (pu < JIT) {
        bi = MD;
    } else {
        float bv = g_pval[0]; bi = g_pidx[0];
        for (int b = 1; b < 512; b++) {
            float v = g_pval[b]; int ix = g_pidx[b];
            if (v < bv || (v == bv && ix < bi)) { bv = v; bi = ix; }
        }
        if (gs_critM < bv) bi = MD;
    }
    gs_prune = bi;
    float qp = (bi < MD) ? g_q[bi] : 0.0f;
    gs_qp = qp;
    bool xal = (bi == MD) ? true : (g_alloc[bi] != 0.f);
    float qaa = (bi == MD) ? (1.0f/pu) : (Q[(size_t)bi*MD + bi] + qp*qp/pu);
    gs_denom = xal ? qaa : __int_as_float(0x7f800000);
    int bits = tptr[0];
    gs_tval = (bits >= 0 && bits < (1 << 26)) ? (float)bits : __int_as_float(bits);
}

__global__ void k_colp(const float* __restrict__ Q) {
    int i = blockIdx.x * 256 + threadIdx.x;
    int p = gs_prune;
    g_colp[i] = (p < MD) ? Q[(size_t)i*MD + p] : 0.0f;
}

// -------- fused Q_n + sig_n writer (row per block) --------
__device__ __forceinline__ float qn_elem(int p, bool rowp, int j, float Qij,
                                         float qi, float qj, float colj,
                                         float qp, float ipu, float Bi, float dinv) {
    float m, Bj;
    if (p < MD) {
        if (rowp) m = (j == p) ? ipu : (-qj * ipu);
        else      m = (j == p) ? (-qi * ipu) : (Qij + qi*qj*ipu);
        Bj = (j == p) ? (-qp * ipu) : (colj + qj*qp*ipu);
    } else {
        m  = Qij + qi*qj*ipu;
        Bj = -qj * ipu;
    }
    return m - Bi * Bj * dinv;
}

__global__ void k_post(const float* __restrict__ Q, const float* __restrict__ sigma,
                       const float* __restrict__ TI, float* __restrict__ out) {
    int i = blockIdx.x;
    int tid = threadIdx.x;
    int p = gs_prune;
    float pu = gs_pu, qp = gs_qp, qi = g_q[i];
    float ipu = 1.0f / pu;
    float dinv = 1.0f / gs_denom;
    float npv = gs_npv, ivp = 1.0f / gs_pv, tval = gs_tval;
    bool rowp = (p < MD) && (i == p);
    float Bi = (p < MD) ? (rowp ? (-qp*ipu) : (g_colp[i] + qi*qp*ipu)) : (-qi*ipu);
    float hi = g_h[i];
    float tni = rowp ? tval : TI[i];
    float mi = (tni >= 0.f) ? 1.f : 0.f;
    float ppi = rowp ? npv : hi;

    const float4* Qr = reinterpret_cast<const float4*>(Q + (size_t)i*MD);
    const float4* Sr = reinterpret_cast<const float4*>(sigma + (size_t)i*MD);
    const uint2*  Kr = reinterpret_cast<const uint2*>(g_kddbf + (size_t)i*MD);
    float4* oq = reinterpret_cast<float4*>(out + OFF_Q + (size_t)i*MD);
    float4* os = reinterpret_cast<float4*>(out + OFF_SIG + (size_t)i*MD);
    const float4* q4 = reinterpret_cast<const float4*>(g_q);
    const float4* c4 = reinterpret_cast<const float4*>(g_colp);
    const float4* h4 = reinterpret_cast<const float4*>(g_h);
    const float4* t4 = reinterpret_cast<const float4*>(TI);

    for (int jb = tid; jb < MD/4; jb += 256) {
        float4 Qv = Qr[jb];
        float4 sg = __ldcs(&Sr[jb]);
        uint2  kp = __ldcs(&Kr[jb]);
        float4 qq = q4[jb]; float4 cc = c4[jb];
        float4 hh = h4[jb]; float4 tt = t4[jb];
        int j0 = jb * 4;

        float4 oqv;
        oqv.x = qn_elem(p, rowp, j0+0, Qv.x, qi, qq.x, cc.x, qp, ipu, Bi, dinv);
        oqv.y = qn_elem(p, rowp, j0+1, Qv.y, qi, qq.y, cc.y, qp, ipu, Bi, dinv);
        oqv.z = qn_elem(p, rowp, j0+2, Qv.z, qi, qq.z, cc.z, qp, ipu, Bi, dinv);
        oqv.w = qn_elem(p, rowp, j0+3, Qv.w, qi, qq.w, cc.w, qp, ipu, Bi, dinv);
        __stcs(&oq[jb], oqv);

        float2 k01 = __bfloat1622float2(*reinterpret_cast<const __nv_bfloat162*>(&kp.x));
        float2 k23 = __bfloat1622float2(*reinterpret_cast<const __nv_bfloat162*>(&kp.y));
        float kdf[4] = {k01.x, k01.y, k23.x, k23.y};
        float svv[4] = {sg.x, sg.y, sg.z, sg.w};
        float hvv[4] = {hh.x, hh.y, hh.z, hh.w};
        float tvv[4] = {tt.x, tt.y, tt.z, tt.w};
        float ov[4];
#pragma unroll
        for (int c = 0; c < 4; c++) {
            int j = j0 + c;
            float spre = FFC*svv[c] + (1.0f-FFC)*kdf[c];
            bool colp = (p < MD) && (j == p);
            float tj = colp ? tval : tvv[c];
            float mj = (tj >= 0.f) ? 1.f : 0.f;
            float ms  = rowp ? (colp ? npv : hvv[c]) : (colp ? hi : spre);
            float ppj = colp ? npv : hvv[c];
            ov[c] = mi * mj * (ms - ppi * ppj * ivp);
        }
        float4 osv; osv.x=ov[0]; osv.y=ov[1]; osv.z=ov[2]; osv.w=ov[3];
        __stcs(&os[jb], osv);
    }
}

// -------- tail: mu_n, dict_n, ti_n --------
__global__ void k_tail(const float* __restrict__ mu, const float* __restrict__ dict,
                       const float* __restrict__ x, const float* __restrict__ TI,
                       float* __restrict__ out) {
    int idx = blockIdx.x * 256 + threadIdx.x;   // 65536 threads
    int p = gs_prune;
    float tval = gs_tval;
    {
        int row = idx >> 4, c4i = idx & 15;
        float4 v;
        if (p < MD && row == p) v = *reinterpret_cast<const float4*>(x + c4i*4);
        else v = *reinterpret_cast<const float4*>(dict + (size_t)row*DD + c4i*4);
        *reinterpret_cast<float4*>(out + OFF_DICT + (size_t)row*DD + c4i*4) = v;
    }
    if (idx < MD) {
        bool rowp = (p < MD) && (idx == p);
        float tn = rowp ? tval : TI[idx];
        out[OFF_TI + idx] = tn;
        float sf = sqrtf(FFC);
        float hi = g_h[idx];
#pragma unroll
        for (int yd = 0; yd < 4; yd++) {
            float val;
            if (tn < 0.f) val = 0.f;
            else if (rowp) val = gs_pm[yd] + gs_c[yd] * gs_npv;
            else val = sf * mu[yd*MD + idx] + gs_c[yd] * hi;
            out[OFF_MU + yd*MD + idx] = val;
        }
    }
}

extern "C" void kernel_launch(void* const* d_in, const int* in_sizes, int n_in,
                              void* d_out, int out_size) {
    const float* dict = (const float*)d_in[0];
    const float* mu   = (const float*)d_in[1];
    const float* sigma= (const float*)d_in[2];
    const float* Q    = (const float*)d_in[3];
    const float* x    = (const float*)d_in[4];
    const float* y    = (const float*)d_in[5];
    const float* nn   = (const float*)d_in[6];
    const float* nd   = (const float*)d_in[7];
    const float* ti   = (const float*)d_in[8];
    const int*   tptr = (const int*)d_in[9];
    float* out = (float*)d_out;

    static cudaStream_t s_aux = nullptr;
    static cudaEvent_t ev_fork1, ev_join1, ev_fork2, ev_join2;
    if (!s_aux) {
        cudaStreamCreateWithFlags(&s_aux, cudaStreamNonBlocking);
        cudaEventCreateWithFlags(&ev_fork1, cudaEventDisableTiming);
        cudaEventCreateWithFlags(&ev_join1, cudaEventDisableTiming);
        cudaEventCreateWithFlags(&ev_fork2, cudaEventDisableTiming);
        cudaEventCreateWithFlags(&ev_join2, cudaEventDisableTiming);
    }

    k_kdx<<<16, 256>>>(dict, x, ti);
    k_matvec5<<<512, 256>>>(Q, mu);
    k_scalars1<<<1, 256>>>(mu);

    // fork: sigma@q on aux stream, overlapped with the compute-bound GEMM pass
    cudaEventRecord(ev_fork1, 0);
    cudaStreamWaitEvent(s_aux, ev_fork1, 0);
    k_sigq<<<512, 256, 0, s_aux>>>(sigma);
    k_pass1<<<dim3(32,32), 256>>>(dict);
    cudaEventRecord(ev_join1, s_aux);
    cudaStreamWaitEvent(0, ev_join1, 0);

    k_hscal<<<1, 256>>>(y, nn, nd, out);
    k_qhcrit<<<512, 256>>>(Q);
    k_finalize<<<1, 32>>>(Q, tptr);
    k_colp<<<16, 256>>>(Q);

    // fork: tiny tail overlapped with the big post pass
    cudaEventRecord(ev_fork2, 0);
    cudaStreamWaitEvent(s_aux, ev_fork2, 0);
    k_tail<<<256, 256, 0, s_aux>>>(mu, dict, x, ti, out);
    k_post<<<4096, 256>>>(Q, sigma, ti, out);
    cudaEventRecord(ev_join2, s_aux);
    cudaStreamWaitEvent(0, ev_join2, 0);
}

// round 8
// speedup vs baseline: 1.1074x; 1.0364x over previous
#include <cuda_runtime.h>
#include <cuda_bf16.h>
#include <math.h>

#define MD 4096
#define DD 64
#define NJB 32
#define FFC 0.999f
#define REGC 0.01f
#define JIT 1e-10f
#define INV2LS2 (1.0f/128.0f)

#define OFF_MU   ((size_t)0)
#define OFF_SIG  ((size_t)16384)
#define OFF_Q    (OFF_SIG + (size_t)MD*MD)
#define OFF_DICT (OFF_Q   + (size_t)MD*MD)
#define OFF_TI   (OFF_DICT + (size_t)MD*DD)
#define OFF_NN   (OFF_TI + MD)
#define OFF_ND   (OFF_NN + 4)

// -------- scratch (device globals; allocations forbidden) --------
static __device__ float g_kdx[MD], g_alloc[MD], g_norm[MD];
static __device__ float g_q[MD], g_h[MD], g_hsig[MD], g_Qmu[4*MD];
static __device__ float g_hpart[NJB*MD];
static __device__ float g_colp[MD];
static __device__ __nv_bfloat16 g_kddbf[(size_t)MD*MD];   // 33.5 MB bf16 Kdd cache
static __device__ float g_pval[512];
static __device__ int   g_pidx[512];
static __device__ float gs_pu, gs_pm[4], gs_qh, gs_npv, gs_pv, gs_c[4];
static __device__ float gs_critM, gs_denom, gs_qp, gs_tval;
static __device__ int   gs_prune;

__device__ __forceinline__ unsigned pk_bf2(float a, float b) {
    __nv_bfloat162 h = __floats2bfloat162_rn(a, b);
    return *reinterpret_cast<unsigned*>(&h);
}

__device__ __forceinline__ void mma16816(float* c, unsigned a0, unsigned a1,
                                         unsigned a2, unsigned a3,
                                         unsigned b0, unsigned b1) {
    asm volatile(
        "mma.sync.aligned.m16n8k16.row.col.f32.bf16.bf16.f32 "
        "{%0,%1,%2,%3},{%4,%5,%6,%7},{%8,%9},{%0,%1,%2,%3};\n"
        : "+f"(c[0]), "+f"(c[1]), "+f"(c[2]), "+f"(c[3])
        : "r"(a0), "r"(a1), "r"(a2), "r"(a3), "r"(b0), "r"(b1));
}

// -------- K_dx, alloc, row norms --------
__global__ void k_kdx(const float* __restrict__ dict, const float* __restrict__ x,
                      const float* __restrict__ ti) {
    __shared__ float xs[DD];
    int tid = threadIdx.x;
    if (tid < DD) xs[tid] = x[tid];
    __syncthreads();
    int i = blockIdx.x * 256 + tid;
    const float* dr = dict + (size_t)i * DD;
    float a2 = 0.f, ip = 0.f, x2 = 0.f;
#pragma unroll
    for (int k = 0; k < DD; k++) { float d = dr[k], xv = xs[k]; a2 += d*d; ip += d*xv; x2 += xv*xv; }
    float d2 = fmaxf(a2 + x2 - 2.0f*ip, 0.0f);
    float al = (ti[i] >= 0.0f) ? 1.0f : 0.0f;
    g_kdx[i] = __expf(-d2 * INV2LS2) * al;
    g_alloc[i] = al;
    g_norm[i] = a2;
}

// -------- q = Q@kdx, Qmu = sqrt(FF)*Q@mu (warp per row) --------
__global__ void k_matvec5(const float* __restrict__ Q, const float* __restrict__ mu) {
    int gw = (blockIdx.x * 256 + threadIdx.x) >> 5;
    int lane = threadIdx.x & 31;
    const float4* Qr = reinterpret_cast<const float4*>(Q) + (size_t)gw * (MD/4);
    const float4* K4 = reinterpret_cast<const float4*>(g_kdx);
    const float4* M4 = reinterpret_cast<const float4*>(mu);
    float s[5] = {0,0,0,0,0};
#pragma unroll 4
    for (int jb = lane; jb < MD/4; jb += 32) {
        float4 qv = Qr[jb], kv = K4[jb];
        s[0] += qv.x*kv.x + qv.y*kv.y + qv.z*kv.z + qv.w*kv.w;
#pragma unroll
        for (int yd = 0; yd < 4; yd++) {
            float4 mv = M4[yd*(MD/4) + jb];
            s[1+yd] += qv.x*mv.x + qv.y*mv.y + qv.z*mv.z + qv.w*mv.w;
        }
    }
#pragma unroll
    for (int o = 16; o > 0; o >>= 1)
#pragma unroll
        for (int r = 0; r < 5; r++) s[r] += __shfl_xor_sync(0xffffffffu, s[r], o);
    if (lane == 0) {
        g_q[gw] = s[0];
        float sf = sqrtf(FFC);
#pragma unroll
        for (int yd = 0; yd < 4; yd++) g_Qmu[yd*MD + gw] = sf * s[1+yd];
    }
}

// -------- scalars 1: pu, pred_mean --------
__global__ void k_scalars1(const float* __restrict__ mu) {
    __shared__ float red[5][8];
    int tid = threadIdx.x;
    float s[5] = {0,0,0,0,0};
    for (int i = tid; i < MD; i += 256) {
        float qi = g_q[i];
        s[0] += g_kdx[i] * qi;
#pragma unroll
        for (int yd = 0; yd < 4; yd++) s[1+yd] += qi * mu[yd*MD + i];
    }
#pragma unroll
    for (int o = 16; o > 0; o >>= 1)
#pragma unroll
        for (int r = 0; r < 5; r++) s[r] += __shfl_xor_sync(0xffffffffu, s[r], o);
    if ((tid & 31) == 0)
#pragma unroll
        for (int r = 0; r < 5; r++) red[r][tid >> 5] = s[r];
    __syncthreads();
    if (tid == 0) {
        float t[5];
#pragma unroll
        for (int r = 0; r < 5; r++) { t[r] = 0.f;
#pragma unroll
            for (int w = 0; w < 8; w++) t[r] += red[r][w]; }
        gs_pu = fmaxf((1.0f + JIT) - t[0], 0.0f);
        float sf = sqrtf(FFC);
#pragma unroll
        for (int yd = 0; yd < 4; yd++) gs_pm[yd] = sf * t[1+yd];
    }
}

// -------- hsig = sigma @ q (warp per row) --------
__global__ void k_sigq(const float* __restrict__ sigma) {
    int gw = (blockIdx.x * 256 + threadIdx.x) >> 5;
    int lane = threadIdx.x & 31;
    const float4* Sr = reinterpret_cast<const float4*>(sigma) + (size_t)gw * (MD/4);
    const float4* Q4 = reinterpret_cast<const float4*>(g_q);
    float s = 0.f;
#pragma unroll 8
    for (int jb = lane; jb < MD/4; jb += 32) {
        float4 sv = Sr[jb], qv = Q4[jb];
        s += sv.x*qv.x + sv.y*qv.y + sv.z*qv.z + sv.w*qv.w;
    }
#pragma unroll
    for (int o = 16; o > 0; o >>= 1) s += __shfl_xor_sync(0xffffffffu, s, o);
    if (lane == 0) g_hsig[gw] = s;
}

// =================== Tensor-core Kdd GEMM machinery ====================
#define LDB36 36      // u32 row stride (72 bf16) for A/B tiles
#define KDLD 132      // bf16 row stride of the kd staging tile (64 x 128 used)

__device__ __forceinline__ void fill_tiles(unsigned* AsU, unsigned* BsU,
                                           const float* __restrict__ dict,
                                           int I0, int J0, int tid) {
    const float4* dI = reinterpret_cast<const float4*>(dict + (size_t)I0 * DD);
    const float4* dJ = reinterpret_cast<const float4*>(dict + (size_t)J0 * DD);
    for (int idx = tid; idx < 2048; idx += 256) {
        int r = idx >> 4, c4 = idx & 15;
        float4 v = dI[r*16 + c4];
        AsU[r*LDB36 + c4*2]     = pk_bf2(v.x, v.y);
        AsU[r*LDB36 + c4*2 + 1] = pk_bf2(v.z, v.w);
        float4 w = dJ[r*16 + c4];
        BsU[r*LDB36 + c4*2]     = pk_bf2(w.x, w.y);
        BsU[r*LDB36 + c4*2 + 1] = pk_bf2(w.z, w.w);
    }
}

__device__ __forceinline__ void gemm_tiles(const unsigned* AsU, const unsigned* BsU,
                                           float acc[4][4][4], int wm, int wn,
                                           int g, int t) {
#pragma unroll
    for (int ks = 0; ks < 4; ks++) {
        unsigned bf[4][2];
#pragma unroll
        for (int n = 0; n < 4; n++) {
            int rb = wn*32 + n*8 + g;
            bf[n][0] = BsU[rb*LDB36 + ks*8 + t];
            bf[n][1] = BsU[rb*LDB36 + ks*8 + t + 4];
        }
#pragma unroll
        for (int m = 0; m < 4; m++) {
            int ra = wm*64 + m*16 + g;
            unsigned a0 = AsU[ra*LDB36 + ks*8 + t];
            unsigned a1 = AsU[(ra+8)*LDB36 + ks*8 + t];
            unsigned a2 = AsU[ra*LDB36 + ks*8 + t + 4];
            unsigned a3 = AsU[(ra+8)*LDB36 + ks*8 + t + 4];
#pragma unroll
            for (int n = 0; n < 4; n++)
                mma16816(acc[m][n], a0, a1, a2, a3, bf[n][0], bf[n][1]);
        }
    }
}

// ---- pass 1 (triangular): kd tiles (a,b)+(b,a) in bf16, deterministic h partials
__global__ void __launch_bounds__(256, 2) k_pass1(const float* __restrict__ dict) {
    __shared__ __align__(16) char raw[128*LDB36*4*2];   // A/B tiles; then kd stage
    __shared__ float qs[128], qI[128], nIv[128], nJv[128], aIv[128], aJv[128];

    unsigned* AsU = reinterpret_cast<unsigned*>(raw);
    unsigned* BsU = AsU + 128*LDB36;
    __nv_bfloat16* kdS = reinterpret_cast<__nv_bfloat16*>(raw);  // 64 x KDLD bf16

    int tid = threadIdx.x;
    int lane = tid & 31, w = tid >> 5;
    int g = lane >> 2, t = lane & 3;
    int wm = w >> 2, wn = w & 3;

    // triangular decode: block -> (a, b), a <= b
    int a = 0, rem = blockIdx.x;
    while (rem >= 32 - a) { rem -= 32 - a; a++; }
    int b = a + rem;
    int I0 = a * 128, J0 = b * 128;
    bool offdiag = (a != b);

    fill_tiles(AsU, BsU, dict, I0, J0, tid);
    if (tid < 128) {
        qs[tid]  = g_q[J0 + tid];
        qI[tid]  = g_q[I0 + tid];
        nJv[tid] = g_norm[J0 + tid]; aJv[tid] = g_alloc[J0 + tid];
        nIv[tid] = g_norm[I0 + tid]; aIv[tid] = g_alloc[I0 + tid];
    }
    __syncthreads();

    float acc[4][4][4];
#pragma unroll
    for (int m = 0; m < 4; m++)
#pragma unroll
        for (int n = 0; n < 4; n++)
#pragma unroll
            for (int r = 0; r < 4; r++) acc[m][n][r] = 0.f;

    gemm_tiles(AsU, BsU, acc, wm, wn, g, t);

    float colsum = 0.f;    // transposed (column) partial, accumulated across halves

#pragma unroll
    for (int half = 0; half < 2; half++) {
        __syncthreads();   // protect kdS overwrite (A/B dead after gemm)
        if (wm == half) {
#pragma unroll
            for (int m = 0; m < 4; m++)
#pragma unroll
                for (int n = 0; n < 4; n++)
#pragma unroll
                    for (int hf = 0; hf < 2; hf++) {
                        int rl = m*16 + g + 8*hf;
                        int cl = wn*32 + n*8 + 2*t;
                        float ni = nIv[half*64 + rl], ai = aIv[half*64 + rl];
                        float c0v = acc[m][n][2*hf], c1v = acc[m][n][2*hf+1];
                        float d0 = fmaxf(ni + nJv[cl]   - 2.0f*c0v, 0.0f);
                        float d1 = fmaxf(ni + nJv[cl+1] - 2.0f*c1v, 0.0f);
                        float k0 = __expf(-d0*INV2LS2) * ai * aJv[cl];
                        float k1 = __expf(-d1*INV2LS2) * ai * aJv[cl+1];
                        *reinterpret_cast<unsigned*>(&kdS[rl*KDLD + cl]) = pk_bf2(k0, k1);
                    }
        }
        __syncthreads();

        // normal orientation: rows of I (this half) -> tile (a,b); row partials
#pragma unroll
        for (int r8 = 0; r8 < 8; r8++) {
            int r  = r8*8 + w;
            int ig = I0 + half*64 + r;
            uint2 kp = *reinterpret_cast<const uint2*>(&kdS[r*KDLD + lane*4]);
            float2 k01 = __bfloat1622float2(*reinterpret_cast<const __nv_bfloat162*>(&kp.x));
            float2 k23 = __bfloat1622float2(*reinterpret_cast<const __nv_bfloat162*>(&kp.y));
            int c0 = lane*4;
            float hsum = k01.x*qs[c0] + k01.y*qs[c0+1] + k23.x*qs[c0+2] + k23.y*qs[c0+3];
            __stcs(reinterpret_cast<uint2*>(g_kddbf + (size_t)ig*MD + J0 + c0), kp);
#pragma unroll
            for (int o = 16; o > 0; o >>= 1)
                hsum += __shfl_xor_sync(0xffffffffu, hsum, o);
            if (lane == 0) g_hpart[(size_t)b*MD + ig] = hsum;
        }

        // transposed orientation: rows of J -> tile (b,a); column partials
        if (offdiag) {
            int jr = tid >> 1, chunk = tid & 1;
            unsigned pk[16];
#pragma unroll
            for (int ii = 0; ii < 16; ii++) {
                int i0 = chunk*32 + 2*ii;
                __nv_bfloat16 v0 = kdS[i0*KDLD + jr];
                __nv_bfloat16 v1 = kdS[(i0+1)*KDLD + jr];
                unsigned s0 = *reinterpret_cast<unsigned short*>(&v0);
                unsigned s1 = *reinterpret_cast<unsigned short*>(&v1);
                pk[ii] = s0 | (s1 << 16);
                colsum += __bfloat162float(v0) * qI[half*64 + i0]
                        + __bfloat162float(v1) * qI[half*64 + i0 + 1];
            }
            __nv_bfloat16* dst = g_kddbf + (size_t)(J0+jr)*MD + I0 + half*64 + chunk*32;
            uint4* d4 = reinterpret_cast<uint4*>(dst);
            __stcs(&d4[0], make_uint4(pk[0], pk[1], pk[2], pk[3]));
            __stcs(&d4[1], make_uint4(pk[4], pk[5], pk[6], pk[7]));
            __stcs(&d4[2], make_uint4(pk[8], pk[9], pk[10], pk[11]));
            __stcs(&d4[3], make_uint4(pk[12], pk[13], pk[14], pk[15]));
        }
    }

    if (offdiag) {
        // combine the two chunks of each jr and write the deterministic col partial
        float other = __shfl_xor_sync(0xffffffffu, colsum, 1);
        if ((tid & 1) == 0) {
            int jr = tid >> 1;
            g_hpart[(size_t)a*MD + J0 + jr] = colsum + other;
        }
    }
}

// -------- h combine + scalars2 fused (one block) --------
__global__ void k_hscal(const float* __restrict__ y, const float* __restrict__ nn,
                        const float* __restrict__ nd, float* __restrict__ out) {
    __shared__ float red[8];
    int tid = threadIdx.x;
    float qh_p = 0.f;
    for (int i = tid; i < MD; i += 256) {
        float s = 0.f;
#pragma unroll
        for (int b = 0; b < NJB; b++) s += g_hpart[(size_t)b*MD + i];
        float h = FFC * g_hsig[i] + (1.0f - FFC) * s;
        g_h[i] = h;
        qh_p += g_q[i] * h;
    }
#pragma unroll
    for (int o = 16; o > 0; o >>= 1) qh_p += __shfl_xor_sync(0xffffffffu, qh_p, o);
    if ((tid & 31) == 0) red[tid >> 5] = qh_p;
    __syncthreads();
    if (tid == 0) {
        float qh = 0.f;
#pragma unroll
        for (int w2 = 0; w2 < 8; w2++) qh += red[w2];
        gs_qh = qh;
        float pu = gs_pu;
        float npv = fmaxf(pu + qh, 0.0f);
        float pv = REGC + npv;
        gs_npv = npv; gs_pv = pv;
        float cm = 0.f;
#pragma unroll
        for (int yd = 0; yd < 4; yd++) {
            float dy = y[yd] - gs_pm[yd];
            float c = dy / pv;
            gs_c[yd] = c;
            out[OFF_NN + yd] = nn[yd] + FFC * dy * dy / pv;
            cm += fabsf(c * (npv - qh));
        }
        out[OFF_ND] = nd[0] + FFC;
        gs_critM = cm;
    }
}

// -------- Qh = Q@h fused with criterion + per-block argmin --------
__global__ void k_qhcrit(const float* __restrict__ Q) {
    __shared__ float sv[8]; __shared__ int si[8];
    int tid = threadIdx.x;
    int gw = (blockIdx.x * 256 + tid) >> 5;
    int lane = tid & 31;
    const float4* Qr = reinterpret_cast<const float4*>(Q) + (size_t)gw * (MD/4);
    const float4* H4 = reinterpret_cast<const float4*>(g_h);
    float s = 0.f;
#pragma unroll 4
    for (int jb = lane; jb < MD/4; jb += 32) {
        float4 qv = Qr[jb], hv = H4[jb];
        s += qv.x*hv.x + qv.y*hv.y + qv.z*hv.z + qv.w*hv.w;
    }
#pragma unroll
    for (int o = 16; o > 0; o >>= 1) s += __shfl_xor_sync(0xffffffffu, s, o);
    if (lane == 0) {
        float pu = gs_pu;
        float cv;
        if (pu < JIT) {
            cv = 0.f;
        } else {
            float qi = g_q[gw];
            float dq = (g_alloc[gw] != 0.f) ? (Q[(size_t)gw*MD + gw] + qi*qi/pu)
                                            : __int_as_float(0x7f800000);
            float r = qi / pu;
            float qhm = gs_qh - gs_npv;
            float acc2 = 0.f;
#pragma unroll
            for (int yd = 0; yd < 4; yd++) {
                float num = g_Qmu[yd*MD + gw] + gs_c[yd]*s + r*gs_c[yd]*qhm;
                acc2 += fabsf(num / dq);
            }
            cv = acc2;
        }
        sv[tid >> 5] = cv; si[tid >> 5] = gw;
    }
    __syncthreads();
    if (tid == 0) {
        float bv = sv[0]; int bi = si[0];
#pragma unroll
        for (int w2 = 1; w2 < 8; w2++) {
            if (sv[w2] < bv || (sv[w2] == bv && si[w2] < bi)) { bv = sv[w2]; bi = si[w2]; }
        }
        g_pval[blockIdx.x] = bv; g_pidx[blockIdx.x] = bi;
    }
}

// -------- argmin finalize + prune scalars --------
__global__ void k_finalize(const float* __restrict__ Q, const int* __restrict__ tptr) {
    if (threadIdx.x != 0) return;
    float pu = gs_pu;
    int bi;
    if (pu < JIT) {
        bi = MD;
    } else {
        float bv = g_pval[0]; bi = g_pidx[0];
        for (int b = 1; b < 512; b++) {
            float v = g_pval[b]; int ix = g_pidx[b];
            if (v < bv || (v == bv && ix < bi)) { bv = v; bi = ix; }
        }
        if (gs_critM < bv) bi = MD;
    }
    gs_prune = bi;
    float qp = (bi < MD) ? g_q[bi] : 0.0f;
    gs_qp = qp;
    bool xal = (bi == MD) ? true : (g_alloc[bi] != 0.f);
    float qaa = (bi == MD) ? (1.0f/pu) : (Q[(size_t)bi*MD + bi] + qp*qp/pu);
    gs_denom = xal ? qaa : __int_as_float(0x7f800000);
    int bits = tptr[0];
    gs_tval = (bits >= 0 && bits < (1 << 26)) ? (float)bits : __int_as_float(bits);
}

__global__ void k_colp(const float* __restrict__ Q) {
    int i = blockIdx.x * 256 + threadIdx.x;
    int p = gs_prune;
    g_colp[i] = (p < MD) ? Q[(size_t)i*MD + p] : 0.0f;
}

// -------- fused Q_n + sig_n writer (row per block) --------
__device__ __forceinline__ float qn_elem(int p, bool rowp, int j, float Qij,
                                         float qi, float qj, float colj,
                                         float qp, float ipu, float Bi, float dinv) {
    float m, Bj;
    if (p < MD) {
        if (rowp) m = (j == p) ? ipu : (-qj * ipu);
        else      m = (j == p) ? (-qi * ipu) : (Qij + qi*qj*ipu);
        Bj = (j == p) ? (-qp * ipu) : (colj + qj*qp*ipu);
    } else {
        m  = Qij + qi*qj*ipu;
        Bj = -qj * ipu;
    }
    return m - Bi * Bj * dinv;
}

__global__ void k_post(const float* __restrict__ Q, const float* __restrict__ sigma,
                       const float* __restrict__ TI, float* __restrict__ out) {
    int i = blockIdx.x;
    int tid = threadIdx.x;
    int p = gs_prune;
    float pu = gs_pu, qp = gs_qp, qi = g_q[i];
    float ipu = 1.0f / pu;
    float dinv = 1.0f / gs_denom;
    float npv = gs_npv, ivp = 1.0f / gs_pv, tval = gs_tval;
    bool rowp = (p < MD) && (i == p);
    float Bi = (p < MD) ? (rowp ? (-qp*ipu) : (g_colp[i] + qi*qp*ipu)) : (-qi*ipu);
    float hi = g_h[i];
    float tni = rowp ? tval : TI[i];
    float mi = (tni >= 0.f) ? 1.f : 0.f;
    float ppi = rowp ? npv : hi;

    const float4* Qr = reinterpret_cast<const float4*>(Q + (size_t)i*MD);
    const float4* Sr = reinterpret_cast<const float4*>(sigma + (size_t)i*MD);
    const uint2*  Kr = reinterpret_cast<const uint2*>(g_kddbf + (size_t)i*MD);
    float4* oq = reinterpret_cast<float4*>(out + OFF_Q + (size_t)i*MD);
    float4* os = reinterpret_cast<float4*>(out + OFF_SIG + (size_t)i*MD);
    const float4* q4 = reinterpret_cast<const float4*>(g_q);
    const float4* c4 = reinterpret_cast<const float4*>(g_colp);
    const float4* h4 = reinterpret_cast<const float4*>(g_h);
    const float4* t4 = reinterpret_cast<const float4*>(TI);

    for (int jb = tid; jb < MD/4; jb += 256) {
        float4 Qv = Qr[jb];
        float4 sg = __ldcs(&Sr[jb]);
        uint2  kp = __ldcs(&Kr[jb]);
        float4 qq = q4[jb]; float4 cc = c4[jb];
        float4 hh = h4[jb]; float4 tt = t4[jb];
        int j0 = jb * 4;

        float4 oqv;
        oqv.x = qn_elem(p, rowp, j0+0, Qv.x, qi, qq.x, cc.x, qp, ipu, Bi, dinv);
        oqv.y = qn_elem(p, rowp, j0+1, Qv.y, qi, qq.y, cc.y, qp, ipu, Bi, dinv);
        oqv.z = qn_elem(p, rowp, j0+2, Qv.z, qi, qq.z, cc.z, qp, ipu, Bi, dinv);
        oqv.w = qn_elem(p, rowp, j0+3, Qv.w, qi, qq.w, cc.w, qp, ipu, Bi, dinv);
        __stcs(&oq[jb], oqv);

        float2 k01 = __bfloat1622float2(*reinterpret_cast<const __nv_bfloat162*>(&kp.x));
        float2 k23 = __bfloat1622float2(*reinterpret_cast<const __nv_bfloat162*>(&kp.y));
        float kdf[4] = {k01.x, k01.y, k23.x, k23.y};
        float svv[4] = {sg.x, sg.y, sg.z, sg.w};
        float hvv[4] = {hh.x, hh.y, hh.z, hh.w};
        float tvv[4] = {tt.x, tt.y, tt.z, tt.w};
        float ov[4];
#pragma unroll
        for (int c = 0; c < 4; c++) {
            int j = j0 + c;
            float spre = FFC*svv[c] + (1.0f-FFC)*kdf[c];
            bool colp = (p < MD) && (j == p);
            float tj = colp ? tval : tvv[c];
            float mj = (tj >= 0.f) ? 1.f : 0.f;
            float ms  = rowp ? (colp ? npv : hvv[c]) : (colp ? hi : spre);
            float ppj = colp ? npv : hvv[c];
            ov[c] = mi * mj * (ms - ppi * ppj * ivp);
        }
        float4 osv; osv.x=ov[0]; osv.y=ov[1]; osv.z=ov[2]; osv.w=ov[3];
        __stcs(&os[jb], osv);
    }
}

// -------- tail: mu_n, dict_n, ti_n --------
__global__ void k_tail(const float* __restrict__ mu, const float* __restrict__ dict,
                       const float* __restrict__ x, const float* __restrict__ TI,
                       float* __restrict__ out) {
    int idx = blockIdx.x * 256 + threadIdx.x;   // 65536 threads
    int p = gs_prune;
    float tval = gs_tval;
    {
        int row = idx >> 4, c4i = idx & 15;
        float4 v;
        if (p < MD && row == p) v = *reinterpret_cast<const float4*>(x + c4i*4);
        else v = *reinterpret_cast<const float4*>(dict + (size_t)row*DD + c4i*4);
        *reinterpret_cast<float4*>(out + OFF_DICT + (size_t)row*DD + c4i*4) = v;
    }
    if (idx < MD) {
        bool rowp = (p < MD) && (idx == p);
        float tn = rowp ? tval : TI[idx];
        out[OFF_TI + idx] = tn;
        float sf = sqrtf(FFC);
        float hi = g_h[idx];
#pragma unroll
        for (int yd = 0; yd < 4; yd++) {
            float val;
            if (tn < 0.f) val = 0.f;
            else if (rowp) val = gs_pm[yd] + gs_c[yd] * gs_npv;
            else val = sf * mu[yd*MD + idx] + gs_c[yd] * hi;
            out[OFF_MU + yd*MD + idx] = val;
        }
    }
}

extern "C" void kernel_launch(void* const* d_in, const int* in_sizes, int n_in,
                              void* d_out, int out_size) {
    const float* dict = (const float*)d_in[0];
    const float* mu   = (const float*)d_in[1];
    const float* sigma= (const float*)d_in[2];
    const float* Q    = (const float*)d_in[3];
    const float* x    = (const float*)d_in[4];
    const float* y    = (const float*)d_in[5];
    const float* nn   = (const float*)d_in[6];
    const float* nd   = (const float*)d_in[7];
    const float* ti   = (const float*)d_in[8];
    const int*   tptr = (const int*)d_in[9];
    float* out = (float*)d_out;

    static cudaStream_t s_aux = nullptr;
    static cudaEvent_t ev_fork1, ev_join1, ev_fork2, ev_join2;
    if (!s_aux) {
        cudaStreamCreateWithFlags(&s_aux, cudaStreamNonBlocking);
        cudaEventCreateWithFlags(&ev_fork1, cudaEventDisableTiming);
        cudaEventCreateWithFlags(&ev_join1, cudaEventDisableTiming);
        cudaEventCreateWithFlags(&ev_fork2, cudaEventDisableTiming);
        cudaEventCreateWithFlags(&ev_join2, cudaEventDisableTiming);
    }

    k_kdx<<<16, 256>>>(dict, x, ti);
    k_matvec5<<<512, 256>>>(Q, mu);
    k_scalars1<<<1, 256>>>(mu);

    // fork: sigma@q on aux stream, overlapped with the compute-bound GEMM pass
    cudaEventRecord(ev_fork1, 0);
    cudaStreamWaitEvent(s_aux, ev_fork1, 0);
    k_sigq<<<512, 256, 0, s_aux>>>(sigma);
    k_pass1<<<528, 256>>>(dict);
    cudaEventRecord(ev_join1, s_aux);
    cudaStreamWaitEvent(0, ev_join1, 0);

    k_hscal<<<1, 256>>>(y, nn, nd, out);
    k_qhcrit<<<512, 256>>>(Q);
    k_finalize<<<1, 32>>>(Q, tptr);
    k_colp<<<16, 256>>>(Q);

    // fork: tiny tail overlapped with the big post pass
    cudaEventRecord(ev_fork2, 0);
    cudaStreamWaitEvent(s_aux, ev_fork2, 0);
    k_tail<<<256, 256, 0, s_aux>>>(mu, dict, x, ti, out);
    k_post<<<4096, 256>>>(Q, sigma, ti, out);
    cudaEventRecord(ev_join2, s_aux);
    cudaStreamWaitEvent(0, ev_join2, 0);
}

// round 10
// speedup vs baseline: 1.1971x; 1.0810x over previous
#include <cuda_runtime.h>
#include <cuda_bf16.h>
#include <cuda_fp16.h>
#include <math.h>

#define MD 4096
#define DD 64
#define NJB 32
#define FFC 0.999f
#define REGC 0.01f
#define JIT 1e-10f
#define INV2LS2 (1.0f/128.0f)

#define OFF_MU   ((size_t)0)
#define OFF_SIG  ((size_t)16384)
#define OFF_Q    (OFF_SIG + (size_t)MD*MD)
#define OFF_DICT (OFF_Q   + (size_t)MD*MD)
#define OFF_TI   (OFF_DICT + (size_t)MD*DD)
#define OFF_NN   (OFF_TI + MD)
#define OFF_ND   (OFF_NN + 4)

// -------- scratch (device globals; allocations forbidden) --------
static __device__ float g_kdx[MD], g_alloc[MD], g_norm[MD];
static __device__ float g_q[MD], g_h[MD], g_hsig[MD], g_Qmu[4*MD];
static __device__ float g_hpart[NJB*MD];
static __device__ float g_colp[MD];
static __device__ unsigned char g_kdd8[(size_t)MD*MD];   // 16.7 MB fp8(e4m3) Kdd cache
static __device__ float g_pval[512];
static __device__ int   g_pidx[512];
static __device__ float gs_pu, gs_pm[4], gs_qh, gs_npv, gs_pv, gs_c[4];
static __device__ float gs_critM, gs_denom, gs_qp, gs_tval;
static __device__ int   gs_prune;

__device__ __forceinline__ unsigned pk_bf2(float a, float b) {
    __nv_bfloat162 h = __floats2bfloat162_rn(a, b);
    return *reinterpret_cast<unsigned*>(&h);
}

// pack two floats to e4m3x2: low byte = lo, high byte = hi
__device__ __forceinline__ unsigned short pk_fp8(float lo, float hi) {
    unsigned short r;
    asm("cvt.rn.satfinite.e4m3x2.f32 %0, %1, %2;" : "=h"(r) : "f"(hi), "f"(lo));
    return r;
}

// decode 4 packed e4m3 bytes -> 4 floats
__device__ __forceinline__ float4 fp8x4_to_f4(unsigned v) {
    unsigned short lo = (unsigned short)(v & 0xFFFFu);
    unsigned short hi = (unsigned short)(v >> 16);
    unsigned r0, r1;
    asm("cvt.rn.f16x2.e4m3x2 %0, %1;" : "=r"(r0) : "h"(lo));
    asm("cvt.rn.f16x2.e4m3x2 %0, %1;" : "=r"(r1) : "h"(hi));
    __half2 h0 = *reinterpret_cast<__half2*>(&r0);
    __half2 h1 = *reinterpret_cast<__half2*>(&r1);
    float2 f0 = __half22float2(h0);
    float2 f1 = __half22float2(h1);
    return make_float4(f0.x, f0.y, f1.x, f1.y);
}

__device__ __forceinline__ void mma16816(float* c, unsigned a0, unsigned a1,
                                         unsigned a2, unsigned a3,
                                         unsigned b0, unsigned b1) {
    asm volatile(
        "mma.sync.aligned.m16n8k16.row.col.f32.bf16.bf16.f32 "
        "{%0,%1,%2,%3},{%4,%5,%6,%7},{%8,%9},{%0,%1,%2,%3};\n"
        : "+f"(c[0]), "+f"(c[1]), "+f"(c[2]), "+f"(c[3])
        : "r"(a0), "r"(a1), "r"(a2), "r"(a3), "r"(b0), "r"(b1));
}

// -------- K_dx, alloc, row norms --------
__global__ void k_kdx(const float* __restrict__ dict, const float* __restrict__ x,
                      const float* __restrict__ ti) {
    __shared__ float xs[DD];
    int tid = threadIdx.x;
    if (tid < DD) xs[tid] = x[tid];
    __syncthreads();
    int i = blockIdx.x * 256 + tid;
    const float* dr = dict + (size_t)i * DD;
    float a2 = 0.f, ip = 0.f, x2 = 0.f;
#pragma unroll
    for (int k = 0; k < DD; k++) { float d = dr[k], xv = xs[k]; a2 += d*d; ip += d*xv; x2 += xv*xv; }
    float d2 = fmaxf(a2 + x2 - 2.0f*ip, 0.0f);
    float al = (ti[i] >= 0.0f) ? 1.0f : 0.0f;
    g_kdx[i] = __expf(-d2 * INV2LS2) * al;
    g_alloc[i] = al;
    g_norm[i] = a2;
}

// -------- q = Q@kdx, Qmu = sqrt(FF)*Q@mu (warp per row; Q stays L2-resident) --------
__global__ void k_matvec5(const float* __restrict__ Q, const float* __restrict__ mu) {
    int gw = (blockIdx.x * 256 + threadIdx.x) >> 5;
    int lane = threadIdx.x & 31;
    const float4* Qr = reinterpret_cast<const float4*>(Q) + (size_t)gw * (MD/4);
    const float4* K4 = reinterpret_cast<const float4*>(g_kdx);
    const float4* M4 = reinterpret_cast<const float4*>(mu);
    float s[5] = {0,0,0,0,0};
#pragma unroll 4
    for (int jb = lane; jb < MD/4; jb += 32) {
        float4 qv = Qr[jb], kv = K4[jb];
        s[0] += qv.x*kv.x + qv.y*kv.y + qv.z*kv.z + qv.w*kv.w;
#pragma unroll
        for (int yd = 0; yd < 4; yd++) {
            float4 mv = M4[yd*(MD/4) + jb];
            s[1+yd] += qv.x*mv.x + qv.y*mv.y + qv.z*mv.z + qv.w*mv.w;
        }
    }
#pragma unroll
    for (int o = 16; o > 0; o >>= 1)
#pragma unroll
        for (int r = 0; r < 5; r++) s[r] += __shfl_xor_sync(0xffffffffu, s[r], o);
    if (lane == 0) {
        g_q[gw] = s[0];
        float sf = sqrtf(FFC);
#pragma unroll
        for (int yd = 0; yd < 4; yd++) g_Qmu[yd*MD + gw] = sf * s[1+yd];
    }
}

// -------- scalars 1: pu, pred_mean --------
__global__ void k_scalars1(const float* __restrict__ mu) {
    __shared__ float red[5][8];
    int tid = threadIdx.x;
    float s[5] = {0,0,0,0,0};
    for (int i = tid; i < MD; i += 256) {
        float qi = g_q[i];
        s[0] += g_kdx[i] * qi;
#pragma unroll
        for (int yd = 0; yd < 4; yd++) s[1+yd] += qi * mu[yd*MD + i];
    }
#pragma unroll
    for (int o = 16; o > 0; o >>= 1)
#pragma unroll
        for (int r = 0; r < 5; r++) s[r] += __shfl_xor_sync(0xffffffffu, s[r], o);
    if ((tid & 31) == 0)
#pragma unroll
        for (int r = 0; r < 5; r++) red[r][tid >> 5] = s[r];
    __syncthreads();
    if (tid == 0) {
        float t[5];
#pragma unroll
        for (int r = 0; r < 5; r++) { t[r] = 0.f;
#pragma unroll
            for (int w = 0; w < 8; w++) t[r] += red[r][w]; }
        gs_pu = fmaxf((1.0f + JIT) - t[0], 0.0f);
        float sf = sqrtf(FFC);
#pragma unroll
        for (int yd = 0; yd < 4; yd++) gs_pm[yd] = sf * t[1+yd];
    }
}

// -------- hsig = sigma @ q (warp per row, streaming loads: keep Q in L2) --------
__global__ void k_sigq(const float* __restrict__ sigma) {
    int gw = (blockIdx.x * 256 + threadIdx.x) >> 5;
    int lane = threadIdx.x & 31;
    const float4* Sr = reinterpret_cast<const float4*>(sigma) + (size_t)gw * (MD/4);
    const float4* Q4 = reinterpret_cast<const float4*>(g_q);
    float s = 0.f;
#pragma unroll 8
    for (int jb = lane; jb < MD/4; jb += 32) {
        float4 sv = __ldcs(&Sr[jb]);
        float4 qv = Q4[jb];
        s += sv.x*qv.x + sv.y*qv.y + sv.z*qv.z + sv.w*qv.w;
    }
#pragma unroll
    for (int o = 16; o > 0; o >>= 1) s += __shfl_xor_sync(0xffffffffu, s, o);
    if (lane == 0) g_hsig[gw] = s;
}

// =================== Tensor-core Kdd GEMM machinery ====================
#define LDB36 36      // u32 row stride (72 bf16) for A/B tiles
#define KDLD 132      // bf16 row stride of the kd staging tile (64 x 128 used)

__device__ __forceinline__ void fill_tiles(unsigned* AsU, unsigned* BsU,
                                           const float* __restrict__ dict,
                                           int I0, int J0, int tid) {
    const float4* dI = reinterpret_cast<const float4*>(dict + (size_t)I0 * DD);
    const float4* dJ = reinterpret_cast<const float4*>(dict + (size_t)J0 * DD);
    for (int idx = tid; idx < 2048; idx += 256) {
        int r = idx >> 4, c4 = idx & 15;
        float4 v = dI[r*16 + c4];
        AsU[r*LDB36 + c4*2]     = pk_bf2(v.x, v.y);
        AsU[r*LDB36 + c4*2 + 1] = pk_bf2(v.z, v.w);
        float4 w = dJ[r*16 + c4];
        BsU[r*LDB36 + c4*2]     = pk_bf2(w.x, w.y);
        BsU[r*LDB36 + c4*2 + 1] = pk_bf2(w.z, w.w);
    }
}

__device__ __forceinline__ void gemm_tiles(const unsigned* AsU, const unsigned* BsU,
                                           float acc[4][4][4], int wm, int wn,
                                           int g, int t) {
#pragma unroll
    for (int ks = 0; ks < 4; ks++) {
        unsigned bf[4][2];
#pragma unroll
        for (int n = 0; n < 4; n++) {
            int rb = wn*32 + n*8 + g;
            bf[n][0] = BsU[rb*LDB36 + ks*8 + t];
            bf[n][1] = BsU[rb*LDB36 + ks*8 + t + 4];
        }
#pragma unroll
        for (int m = 0; m < 4; m++) {
            int ra = wm*64 + m*16 + g;
            unsigned a0 = AsU[ra*LDB36 + ks*8 + t];
            unsigned a1 = AsU[(ra+8)*LDB36 + ks*8 + t];
            unsigned a2 = AsU[ra*LDB36 + ks*8 + t + 4];
            unsigned a3 = AsU[(ra+8)*LDB36 + ks*8 + t + 4];
#pragma unroll
            for (int n = 0; n < 4; n++)
                mma16816(acc[m][n], a0, a1, a2, a3, bf[n][0], bf[n][1]);
        }
    }
}

// ---- pass 1 (triangular): kd tiles (a,b)+(b,a) in fp8, deterministic h partials
__global__ void __launch_bounds__(256, 2) k_pass1(const float* __restrict__ dict) {
    __shared__ __align__(16) char raw[128*LDB36*4*2];   // A/B tiles; then kd stage
    __shared__ float qs[128], qI[128], nIv[128], nJv[128], aIv[128], aJv[128];

    unsigned* AsU = reinterpret_cast<unsigned*>(raw);
    unsigned* BsU = AsU + 128*LDB36;
    __nv_bfloat16* kdS = reinterpret_cast<__nv_bfloat16*>(raw);  // 64 x KDLD bf16

    int tid = threadIdx.x;
    int lane = tid & 31, w = tid >> 5;
    int g = lane >> 2, t = lane & 3;
    int wm = w >> 2, wn = w & 3;

    // triangular decode: block -> (a, b), a <= b
    int a = 0, rem = blockIdx.x;
    while (rem >= 32 - a) { rem -= 32 - a; a++; }
    int b = a + rem;
    int I0 = a * 128, J0 = b * 128;
    bool offdiag = (a != b);

    fill_tiles(AsU, BsU, dict, I0, J0, tid);
    if (tid < 128) {
        qs[tid]  = g_q[J0 + tid];
        qI[tid]  = g_q[I0 + tid];
        nJv[tid] = g_norm[J0 + tid]; aJv[tid] = g_alloc[J0 + tid];
        nIv[tid] = g_norm[I0 + tid]; aIv[tid] = g_alloc[I0 + tid];
    }
    __syncthreads();

    float acc[4][4][4];
#pragma unroll
    for (int m = 0; m < 4; m++)
#pragma unroll
        for (int n = 0; n < 4; n++)
#pragma unroll
            for (int r = 0; r < 4; r++) acc[m][n][r] = 0.f;

    gemm_tiles(AsU, BsU, acc, wm, wn, g, t);

    float colsum = 0.f;    // transposed (column) partial, accumulated across halves

#pragma unroll
    for (int half = 0; half < 2; half++) {
        __syncthreads();   // protect kdS overwrite (A/B dead after gemm)
        if (wm == half) {
#pragma unroll
            for (int m = 0; m < 4; m++)
#pragma unroll
                for (int n = 0; n < 4; n++)
#pragma unroll
                    for (int hf = 0; hf < 2; hf++) {
                        int rl = m*16 + g + 8*hf;
                        int cl = wn*32 + n*8 + 2*t;
                        float ni = nIv[half*64 + rl], ai = aIv[half*64 + rl];
                        float c0v = acc[m][n][2*hf], c1v = acc[m][n][2*hf+1];
                        float d0 = fmaxf(ni + nJv[cl]   - 2.0f*c0v, 0.0f);
                        float d1 = fmaxf(ni + nJv[cl+1] - 2.0f*c1v, 0.0f);
                        float k0 = __expf(-d0*INV2LS2) * ai * aJv[cl];
                        float k1 = __expf(-d1*INV2LS2) * ai * aJv[cl+1];
                        *reinterpret_cast<unsigned*>(&kdS[rl*KDLD + cl]) = pk_bf2(k0, k1);
                    }
        }
        __syncthreads();

        // normal orientation: rows of I (this half) -> tile (a,b); row partials
#pragma unroll
        for (int r8 = 0; r8 < 8; r8++) {
            int r  = r8*8 + w;
            int ig = I0 + half*64 + r;
            uint2 kp = *reinterpret_cast<const uint2*>(&kdS[r*KDLD + lane*4]);
            float2 k01 = __bfloat1622float2(*reinterpret_cast<const __nv_bfloat162*>(&kp.x));
            float2 k23 = __bfloat1622float2(*reinterpret_cast<const __nv_bfloat162*>(&kp.y));
            int c0 = lane*4;
            float hsum = k01.x*qs[c0] + k01.y*qs[c0+1] + k23.x*qs[c0+2] + k23.y*qs[c0+3];
            unsigned short s0 = pk_fp8(k01.x, k01.y);
            unsigned short s1 = pk_fp8(k23.x, k23.y);
            unsigned word = (unsigned)s0 | ((unsigned)s1 << 16);
            __stcs(reinterpret_cast<unsigned*>(g_kdd8 + (size_t)ig*MD + J0 + c0), word);
#pragma unroll
            for (int o = 16; o > 0; o >>= 1)
                hsum += __shfl_xor_sync(0xffffffffu, hsum, o);
            if (lane == 0) g_hpart[(size_t)b*MD + ig] = hsum;
        }

        // transposed orientation: rows of J -> tile (b,a); column partials
        if (offdiag) {
            int jr = tid >> 1, chunk = tid & 1;
            unsigned short sh[16];
#pragma unroll
            for (int ii = 0; ii < 16; ii++) {
                int i0 = chunk*32 + 2*ii;
                __nv_bfloat16 v0 = kdS[i0*KDLD + jr];
                __nv_bfloat16 v1 = kdS[(i0+1)*KDLD + jr];
                float f0 = __bfloat162float(v0), f1 = __bfloat162float(v1);
                sh[ii] = pk_fp8(f0, f1);
                colsum += f0 * qI[half*64 + i0] + f1 * qI[half*64 + i0 + 1];
            }
            unsigned wrd[8];
#pragma unroll
            for (int k2 = 0; k2 < 8; k2++)
                wrd[k2] = (unsigned)sh[2*k2] | ((unsigned)sh[2*k2+1] << 16);
            unsigned char* dst = g_kdd8 + (size_t)(J0+jr)*MD + I0 + half*64 + chunk*32;
            uint4* d4 = reinterpret_cast<uint4*>(dst);
            __stcs(&d4[0], make_uint4(wrd[0], wrd[1], wrd[2], wrd[3]));
            __stcs(&d4[1], make_uint4(wrd[4], wrd[5], wrd[6], wrd[7]));
        }
    }

    if (offdiag) {
        float other = __shfl_xor_sync(0xffffffffu, colsum, 1);
        if ((tid & 1) == 0) {
            int jr = tid >> 1;
            g_hpart[(size_t)a*MD + J0 + jr] = colsum + other;
        }
    }
}

// -------- h combine + scalars2 fused (one block) --------
__global__ void k_hscal(const float* __restrict__ y, const float* __restrict__ nn,
                        const float* __restrict__ nd, float* __restrict__ out) {
    __shared__ float red[8];
    int tid = threadIdx.x;
    float qh_p = 0.f;
    for (int i = tid; i < MD; i += 256) {
        float s = 0.f;
#pragma unroll
        for (int b = 0; b < NJB; b++) s += g_hpart[(size_t)b*MD + i];
        float h = FFC * g_hsig[i] + (1.0f - FFC) * s;
        g_h[i] = h;
        qh_p += g_q[i] * h;
    }
#pragma unroll
    for (int o = 16; o > 0; o >>= 1) qh_p += __shfl_xor_sync(0xffffffffu, qh_p, o);
    if ((tid & 31) == 0) red[tid >> 5] = qh_p;
    __syncthreads();
    if (tid == 0) {
        float qh = 0.f;
#pragma unroll
        for (int w2 = 0; w2 < 8; w2++) qh += red[w2];
        gs_qh = qh;
        float pu = gs_pu;
        float npv = fmaxf(pu + qh, 0.0f);
        float pv = REGC + npv;
        gs_npv = npv; gs_pv = pv;
        float cm = 0.f;
#pragma unroll
        for (int yd = 0; yd < 4; yd++) {
            float dy = y[yd] - gs_pm[yd];
            float c = dy / pv;
            gs_c[yd] = c;
            out[OFF_NN + yd] = nn[yd] + FFC * dy * dy / pv;
            cm += fabsf(c * (npv - qh));
        }
        out[OFF_ND] = nd[0] + FFC;
        gs_critM = cm;
    }
}

// -------- Qh = Q@h fused with criterion + per-block argmin --------
__global__ void k_qhcrit(const float* __restrict__ Q) {
    __shared__ float sv[8]; __shared__ int si[8];
    int tid = threadIdx.x;
    int gw = (blockIdx.x * 256 + tid) >> 5;
    int lane = tid & 31;
    const float4* Qr = reinterpret_cast<const float4*>(Q) + (size_t)gw * (MD/4);
    const float4* H4 = reinterpret_cast<const float4*>(g_h);
    float s = 0.f;
#pragma unroll 4
    for (int jb = lane; jb < MD/4; jb += 32) {
        float4 qv = Qr[jb], hv = H4[jb];
        s += qv.x*hv.x + qv.y*hv.y + qv.z*hv.z + qv.w*hv.w;
    }
#pragma unroll
    for (int o = 16; o > 0; o >>= 1) s += __shfl_xor_sync(0xffffffffu, s, o);
    if (lane == 0) {
        float pu = gs_pu;
        float cv;
        if (pu < JIT) {
            cv = 0.f;
        } else {
            float qi = g_q[gw];
            float dq = (g_alloc[gw] != 0.f) ? (Q[(size_t)gw*MD + gw] + qi*qi/pu)
                                            : __int_as_float(0x7f800000);
            float r = qi / pu;
            float qhm = gs_qh - gs_npv;
            float acc2 = 0.f;
#pragma unroll
            for (int yd = 0; yd < 4; yd++) {
                float num = g_Qmu[yd*MD + gw] + gs_c[yd]*s + r*gs_c[yd]*qhm;
                acc2 += fabsf(num / dq);
            }
            cv = acc2;
        }
        sv[tid >> 5] = cv; si[tid >> 5] = gw;
    }
    __syncthreads();
    if (tid == 0) {
        float bv = sv[0]; int bi = si[0];
#pragma unroll
        for (int w2 = 1; w2 < 8; w2++) {
            if (sv[w2] < bv || (sv[w2] == bv && si[w2] < bi)) { bv = sv[w2]; bi = si[w2]; }
        }
        g_pval[blockIdx.x] = bv; g_pidx[blockIdx.x] = bi;
    }
}

// -------- argmin finalize + prune scalars --------
__global__ void k_finalize(const float* __restrict__ Q, const int* __restrict__ tptr) {
    if (threadIdx.x != 0) return;
    float pu = gs_pu;
    int bi;
    if (pu < JIT) {
        bi = MD;
    } else {
        float bv = g_pval[0]; bi = g_pidx[0];
        for (int b = 1; b < 512; b++) {
            float v = g_pval[b]; int ix = g_pidx[b];
            if (v < bv || (v == bv && ix < bi)) { bv = v; bi = ix; }
        }
        if (gs_critM < bv) bi = MD;
    }
    gs_prune = bi;
    float qp = (bi < MD) ? g_q[bi] : 0.0f;
    gs_qp = qp;
    bool xal = (bi == MD) ? true : (g_alloc[bi] != 0.f);
    float qaa = (bi == MD) ? (1.0f/pu) : (Q[(size_t)bi*MD + bi] + qp*qp/pu);
    gs_denom = xal ? qaa : __int_as_float(0x7f800000);
    int bits = tptr[0];
    gs_tval = (bits >= 0 && bits < (1 << 26)) ? (float)bits : __int_as_float(bits);
}

__global__ void k_colp(const float* __restrict__ Q) {
    int i = blockIdx.x * 256 + threadIdx.x;
    int p = gs_prune;
    g_colp[i] = (p < MD) ? Q[(size_t)i*MD + p] : 0.0f;
}

// -------- fused Q_n + sig_n writer (row per block) --------
__device__ __forceinline__ float qn_elem(int p, bool rowp, int j, float Qij,
                                         float qi, float qj, float colj,
                                         float qp, float ipu, float Bi, float dinv) {
    float m, Bj;
    if (p < MD) {
        if (rowp) m = (j == p) ? ipu : (-qj * ipu);
        else      m = (j == p) ? (-qi * ipu) : (Qij + qi*qj*ipu);
        Bj = (j == p) ? (-qp * ipu) : (colj + qj*qp*ipu);
    } else {
        m  = Qij + qi*qj*ipu;
        Bj = -qj * ipu;
    }
    return m - Bi * Bj * dinv;
}

__global__ void k_post(const float* __restrict__ Q, const float* __restrict__ sigma,
                       const float* __restrict__ TI, float* __restrict__ out) {
    int i = blockIdx.x;
    int tid = threadIdx.x;
    int p = gs_prune;
    float pu = gs_pu, qp = gs_qp, qi = g_q[i];
    float ipu = 1.0f / pu;
    float dinv = 1.0f / gs_denom;
    float npv = gs_npv, ivp = 1.0f / gs_pv, tval = gs_tval;
    bool rowp = (p < MD) && (i == p);
    float Bi = (p < MD) ? (rowp ? (-qp*ipu) : (g_colp[i] + qi*qp*ipu)) : (-qi*ipu);
    float hi = g_h[i];
    float tni = rowp ? tval : TI[i];
    float mi = (tni >= 0.f) ? 1.f : 0.f;
    float ppi = rowp ? npv : hi;

    const float4* Qr = reinterpret_cast<const float4*>(Q + (size_t)i*MD);
    const float4* Sr = reinterpret_cast<const float4*>(sigma + (size_t)i*MD);
    const unsigned* Kr = reinterpret_cast<const unsigned*>(g_kdd8 + (size_t)i*MD);
    float4* oq = reinterpret_cast<float4*>(out + OFF_Q + (size_t)i*MD);
    float4* os = reinterpret_cast<float4*>(out + OFF_SIG + (size_t)i*MD);
    const float4* q4 = reinterpret_cast<const float4*>(g_q);
    const float4* c4 = reinterpret_cast<const float4*>(g_colp);
    const float4* h4 = reinterpret_cast<const float4*>(g_h);
    const float4* t4 = reinterpret_cast<const float4*>(TI);

    for (int jb = tid; jb < MD/4; jb += 256) {
        float4 Qv = Qr[jb];
        float4 sg = __ldcs(&Sr[jb]);
        unsigned kp = __ldcs(&Kr[jb]);
        float4 qq = q4[jb]; float4 cc = c4[jb];
        float4 hh = h4[jb]; float4 tt = t4[jb];
        int j0 = jb * 4;

        float4 oqv;
        oqv.x = qn_elem(p, rowp, j0+0, Qv.x, qi, qq.x, cc.x, qp, ipu, Bi, dinv);
        oqv.y = qn_elem(p, rowp, j0+1, Qv.y, qi, qq.y, cc.y, qp, ipu, Bi, dinv);
        oqv.z = qn_elem(p, rowp, j0+2, Qv.z, qi, qq.z, cc.z, qp, ipu, Bi, dinv);
        oqv.w = qn_elem(p, rowp, j0+3, Qv.w, qi, qq.w, cc.w, qp, ipu, Bi, dinv);
        __stcs(&oq[jb], oqv);

        float4 kf = fp8x4_to_f4(kp);
        float kdf[4] = {kf.x, kf.y, kf.z, kf.w};
        float svv[4] = {sg.x, sg.y, sg.z, sg.w};
        float hvv[4] = {hh.x, hh.y, hh.z, hh.w};
        float tvv[4] = {tt.x, tt.y, tt.z, tt.w};
        float ov[4];
#pragma unroll
        for (int c = 0; c < 4; c++) {
            int j = j0 + c;
            float spre = FFC*svv[c] + (1.0f-FFC)*kdf[c];
            bool colp = (p < MD) && (j == p);
            float tj = colp ? tval : tvv[c];
            float mj = (tj >= 0.f) ? 1.f : 0.f;
            float ms  = rowp ? (colp ? npv : hvv[c]) : (colp ? hi : spre);
            float ppj = colp ? npv : hvv[c];
            ov[c] = mi * mj * (ms - ppi * ppj * ivp);
        }
        float4 osv; osv.x=ov[0]; osv.y=ov[1]; osv.z=ov[2]; osv.w=ov[3];
        __stcs(&os[jb], osv);
    }
}

// -------- tail: mu_n, dict_n, ti_n --------
__global__ void k_tail(const float* __restrict__ mu, const float* __restrict__ dict,
                       const float* __restrict__ x, const float* __restrict__ TI,
                       float* __restrict__ out) {
    int idx = blockIdx.x * 256 + threadIdx.x;   // 65536 threads
    int p = gs_prune;
    float tval = gs_tval;
    {
        int row = idx >> 4, c4i = idx & 15;
        float4 v;
        if (p < MD && row == p) v = *reinterpret_cast<const float4*>(x + c4i*4);
        else v = *reinterpret_cast<const float4*>(dict + (size_t)row*DD + c4i*4);
        *reinterpret_cast<float4*>(out + OFF_DICT + (size_t)row*DD + c4i*4) = v;
    }
    if (idx < MD) {
        bool rowp = (p < MD) && (idx == p);
        float tn = rowp ? tval : TI[idx];
        out[OFF_TI + idx] = tn;
        float sf = sqrtf(FFC);
        float hi = g_h[idx];
#pragma unroll
        for (int yd = 0; yd < 4; yd++) {
            float val;
            if (tn < 0.f) val = 0.f;
            else if (rowp) val = gs_pm[yd] + gs_c[yd] * gs_npv;
            else val = sf * mu[yd*MD + idx] + gs_c[yd] * hi;
            out[OFF_MU + yd*MD + idx] = val;
        }
    }
}

extern "C" void kernel_launch(void* const* d_in, const int* in_sizes, int n_in,
                              void* d_out, int out_size) {
    const float* dict = (const float*)d_in[0];
    const float* mu   = (const float*)d_in[1];
    const float* sigma= (const float*)d_in[2];
    const float* Q    = (const float*)d_in[3];
    const float* x    = (const float*)d_in[4];
    const float* y    = (const float*)d_in[5];
    const float* nn   = (const float*)d_in[6];
    const float* nd   = (const float*)d_in[7];
    const float* ti   = (const float*)d_in[8];
    const int*   tptr = (const int*)d_in[9];
    float* out = (float*)d_out;

    static cudaStream_t s_aux = nullptr;
    static cudaEvent_t ev_fork1, ev_join1, ev_fork2, ev_join2;
    if (!s_aux) {
        cudaStreamCreateWithFlags(&s_aux, cudaStreamNonBlocking);
        cudaEventCreateWithFlags(&ev_fork1, cudaEventDisableTiming);
        cudaEventCreateWithFlags(&ev_join1, cudaEventDisableTiming);
        cudaEventCreateWithFlags(&ev_fork2, cudaEventDisableTiming);
        cudaEventCreateWithFlags(&ev_join2, cudaEventDisableTiming);
    }

    k_kdx<<<16, 256>>>(dict, x, ti);
    k_matvec5<<<512, 256>>>(Q, mu);
    k_scalars1<<<1, 256>>>(mu);

    // fork: sigma@q on aux stream, overlapped with the compute-bound GEMM pass
    cudaEventRecord(ev_fork1, 0);
    cudaStreamWaitEvent(s_aux, ev_fork1, 0);
    k_sigq<<<512, 256, 0, s_aux>>>(sigma);
    k_pass1<<<528, 256>>>(dict);
    cudaEventRecord(ev_join1, s_aux);
    cudaStreamWaitEvent(0, ev_join1, 0);

    k_hscal<<<1, 256>>>(y, nn, nd, out);
    k_qhcrit<<<512, 256>>>(Q);
    k_finalize<<<1, 32>>>(Q, tptr);
    k_colp<<<16, 256>>>(Q);

    // fork: tiny tail overlapped with the big post pass
    cudaEventRecord(ev_fork2, 0);
    cudaStreamWaitEvent(s_aux, ev_fork2, 0);
    k_tail<<<256, 256, 0, s_aux>>>(mu, dict, x, ti, out);
    k_post<<<4096, 256>>>(Q, sigma, ti, out);
    cudaEventRecord(ev_join2, s_aux);
    cudaStreamWaitEvent(0, ev_join2, 0);
}

// round 11
// speedup vs baseline: 1.3132x; 1.0970x over previous
#include <cuda_runtime.h>
#include <cuda_bf16.h>
#include <cuda_fp16.h>
#include <math.h>

#define MD 4096
#define DD 64
#define NJB 32
#define FFC 0.999f
#define REGC 0.01f
#define JIT 1e-10f
#define INV2LS2 (1.0f/128.0f)

#define OFF_MU   ((size_t)0)
#define OFF_SIG  ((size_t)16384)
#define OFF_Q    (OFF_SIG + (size_t)MD*MD)
#define OFF_DICT (OFF_Q   + (size_t)MD*MD)
#define OFF_TI   (OFF_DICT + (size_t)MD*DD)
#define OFF_NN   (OFF_TI + MD)
#define OFF_ND   (OFF_NN + 4)

// -------- scratch (device globals; allocations forbidden) --------
static __device__ float g_kdx[MD], g_alloc[MD], g_norm[MD];
static __device__ float g_q[MD], g_h[MD], g_hsig[MD], g_Qmu[4*MD];
static __device__ float g_hpart[NJB*MD];
static __device__ float g_colp[MD];
static __device__ unsigned char g_kdd8[(size_t)MD*MD];   // 16.7 MB fp8(e4m3) Kdd cache
static __device__ float g_pval[512];
static __device__ int   g_pidx[512];
static __device__ float gs_pu, gs_pm[4], gs_qh, gs_npv, gs_pv, gs_c[4];
static __device__ float gs_critM, gs_denom, gs_qp, gs_tval;
static __device__ int   gs_prune;

__device__ __forceinline__ unsigned pk_bf2(float a, float b) {
    __nv_bfloat162 h = __floats2bfloat162_rn(a, b);
    return *reinterpret_cast<unsigned*>(&h);
}

// pack two floats to e4m3x2: low byte = lo, high byte = hi
__device__ __forceinline__ unsigned short pk_fp8(float lo, float hi) {
    unsigned short r;
    asm("cvt.rn.satfinite.e4m3x2.f32 %0, %1, %2;" : "=h"(r) : "f"(hi), "f"(lo));
    return r;
}

// decode 4 packed e4m3 bytes -> 4 floats
__device__ __forceinline__ float4 fp8x4_to_f4(unsigned v) {
    unsigned short lo = (unsigned short)(v & 0xFFFFu);
    unsigned short hi = (unsigned short)(v >> 16);
    unsigned r0, r1;
    asm("cvt.rn.f16x2.e4m3x2 %0, %1;" : "=r"(r0) : "h"(lo));
    asm("cvt.rn.f16x2.e4m3x2 %0, %1;" : "=r"(r1) : "h"(hi));
    __half2 h0 = *reinterpret_cast<__half2*>(&r0);
    __half2 h1 = *reinterpret_cast<__half2*>(&r1);
    float2 f0 = __half22float2(h0);
    float2 f1 = __half22float2(h1);
    return make_float4(f0.x, f0.y, f1.x, f1.y);
}

__device__ __forceinline__ void mma16816(float* c, unsigned a0, unsigned a1,
                                         unsigned a2, unsigned a3,
                                         unsigned b0, unsigned b1) {
    asm volatile(
        "mma.sync.aligned.m16n8k16.row.col.f32.bf16.bf16.f32 "
        "{%0,%1,%2,%3},{%4,%5,%6,%7},{%8,%9},{%0,%1,%2,%3};\n"
        : "+f"(c[0]), "+f"(c[1]), "+f"(c[2]), "+f"(c[3])
        : "r"(a0), "r"(a1), "r"(a2), "r"(a3), "r"(b0), "r"(b1));
}

// -------- K_dx, alloc, row norms --------
__global__ void k_kdx(const float* __restrict__ dict, const float* __restrict__ x,
                      const float* __restrict__ ti) {
    __shared__ float xs[DD];
    int tid = threadIdx.x;
    if (tid < DD) xs[tid] = x[tid];
    __syncthreads();
    int i = blockIdx.x * 256 + tid;
    const float* dr = dict + (size_t)i * DD;
    float a2 = 0.f, ip = 0.f, x2 = 0.f;
#pragma unroll
    for (int k = 0; k < DD; k++) { float d = dr[k], xv = xs[k]; a2 += d*d; ip += d*xv; x2 += xv*xv; }
    float d2 = fmaxf(a2 + x2 - 2.0f*ip, 0.0f);
    float al = (ti[i] >= 0.0f) ? 1.0f : 0.0f;
    g_kdx[i] = __expf(-d2 * INV2LS2) * al;
    g_alloc[i] = al;
    g_norm[i] = a2;
}

// -------- q = Q@kdx, Qmu = sqrt(FF)*Q@mu (warp per row) --------
__global__ void k_matvec5(const float* __restrict__ Q, const float* __restrict__ mu) {
    int gw = (blockIdx.x * 256 + threadIdx.x) >> 5;
    int lane = threadIdx.x & 31;
    const float4* Qr = reinterpret_cast<const float4*>(Q) + (size_t)gw * (MD/4);
    const float4* K4 = reinterpret_cast<const float4*>(g_kdx);
    const float4* M4 = reinterpret_cast<const float4*>(mu);
    float s[5] = {0,0,0,0,0};
#pragma unroll 4
    for (int jb = lane; jb < MD/4; jb += 32) {
        float4 qv = Qr[jb], kv = K4[jb];
        s[0] += qv.x*kv.x + qv.y*kv.y + qv.z*kv.z + qv.w*kv.w;
#pragma unroll
        for (int yd = 0; yd < 4; yd++) {
            float4 mv = M4[yd*(MD/4) + jb];
            s[1+yd] += qv.x*mv.x + qv.y*mv.y + qv.z*mv.z + qv.w*mv.w;
        }
    }
#pragma unroll
    for (int o = 16; o > 0; o >>= 1)
#pragma unroll
        for (int r = 0; r < 5; r++) s[r] += __shfl_xor_sync(0xffffffffu, s[r], o);
    if (lane == 0) {
        g_q[gw] = s[0];
        float sf = sqrtf(FFC);
#pragma unroll
        for (int yd = 0; yd < 4; yd++) g_Qmu[yd*MD + gw] = sf * s[1+yd];
    }
}

// -------- scalars 1: pu, pred_mean --------
__global__ void k_scalars1(const float* __restrict__ mu) {
    __shared__ float red[5][8];
    int tid = threadIdx.x;
    float s[5] = {0,0,0,0,0};
    for (int i = tid; i < MD; i += 256) {
        float qi = g_q[i];
        s[0] += g_kdx[i] * qi;
#pragma unroll
        for (int yd = 0; yd < 4; yd++) s[1+yd] += qi * mu[yd*MD + i];
    }
#pragma unroll
    for (int o = 16; o > 0; o >>= 1)
#pragma unroll
        for (int r = 0; r < 5; r++) s[r] += __shfl_xor_sync(0xffffffffu, s[r], o);
    if ((tid & 31) == 0)
#pragma unroll
        for (int r = 0; r < 5; r++) red[r][tid >> 5] = s[r];
    __syncthreads();
    if (tid == 0) {
        float t[5];
#pragma unroll
        for (int r = 0; r < 5; r++) { t[r] = 0.f;
#pragma unroll
            for (int w = 0; w < 8; w++) t[r] += red[r][w]; }
        gs_pu = fmaxf((1.0f + JIT) - t[0], 0.0f);
        float sf = sqrtf(FFC);
#pragma unroll
        for (int yd = 0; yd < 4; yd++) gs_pm[yd] = sf * t[1+yd];
    }
}

// -------- hsig = sigma @ q (warp per row, streaming loads: keep Q in L2) --------
__global__ void k_sigq(const float* __restrict__ sigma) {
    int gw = (blockIdx.x * 256 + threadIdx.x) >> 5;
    int lane = threadIdx.x & 31;
    const float4* Sr = reinterpret_cast<const float4*>(sigma) + (size_t)gw * (MD/4);
    const float4* Q4 = reinterpret_cast<const float4*>(g_q);
    float s = 0.f;
#pragma unroll 8
    for (int jb = lane; jb < MD/4; jb += 32) {
        float4 sv = __ldcs(&Sr[jb]);
        float4 qv = Q4[jb];
        s += sv.x*qv.x + sv.y*qv.y + sv.z*qv.z + sv.w*qv.w;
    }
#pragma unroll
    for (int o = 16; o > 0; o >>= 1) s += __shfl_xor_sync(0xffffffffu, s, o);
    if (lane == 0) g_hsig[gw] = s;
}

// =================== Tensor-core Kdd GEMM machinery ====================
#define LDB36 36      // u32 row stride (72 bf16) for A/B tiles
#define KDLD 132      // bf16 row stride of the kd staging tile (64 x 128 used)

__device__ __forceinline__ void fill_tiles(unsigned* AsU, unsigned* BsU,
                                           const float* __restrict__ dict,
                                           int I0, int J0, int tid) {
    const float4* dI = reinterpret_cast<const float4*>(dict + (size_t)I0 * DD);
    const float4* dJ = reinterpret_cast<const float4*>(dict + (size_t)J0 * DD);
    for (int idx = tid; idx < 2048; idx += 256) {
        int r = idx >> 4, c4 = idx & 15;
        float4 v = dI[r*16 + c4];
        AsU[r*LDB36 + c4*2]     = pk_bf2(v.x, v.y);
        AsU[r*LDB36 + c4*2 + 1] = pk_bf2(v.z, v.w);
        float4 w = dJ[r*16 + c4];
        BsU[r*LDB36 + c4*2]     = pk_bf2(w.x, w.y);
        BsU[r*LDB36 + c4*2 + 1] = pk_bf2(w.z, w.w);
    }
}

__device__ __forceinline__ void gemm_tiles(const unsigned* AsU, const unsigned* BsU,
                                           float acc[4][4][4], int wm, int wn,
                                           int g, int t) {
#pragma unroll
    for (int ks = 0; ks < 4; ks++) {
        unsigned bf[4][2];
#pragma unroll
        for (int n = 0; n < 4; n++) {
            int rb = wn*32 + n*8 + g;
            bf[n][0] = BsU[rb*LDB36 + ks*8 + t];
            bf[n][1] = BsU[rb*LDB36 + ks*8 + t + 4];
        }
#pragma unroll
        for (int m = 0; m < 4; m++) {
            int ra = wm*64 + m*16 + g;
            unsigned a0 = AsU[ra*LDB36 + ks*8 + t];
            unsigned a1 = AsU[(ra+8)*LDB36 + ks*8 + t];
            unsigned a2 = AsU[ra*LDB36 + ks*8 + t + 4];
            unsigned a3 = AsU[(ra+8)*LDB36 + ks*8 + t + 4];
#pragma unroll
            for (int n = 0; n < 4; n++)
                mma16816(acc[m][n], a0, a1, a2, a3, bf[n][0], bf[n][1]);
        }
    }
}

// ---- pass 1 (triangular): kd tiles (a,b)+(b,a) in fp8, deterministic h partials
__global__ void __launch_bounds__(256, 2) k_pass1(const float* __restrict__ dict) {
    __shared__ __align__(16) char raw[128*LDB36*4*2];   // A/B tiles; then kd stage
    __shared__ float qs[128], qI[128], nIv[128], nJv[128], aIv[128], aJv[128];

    unsigned* AsU = reinterpret_cast<unsigned*>(raw);
    unsigned* BsU = AsU + 128*LDB36;
    __nv_bfloat16* kdS = reinterpret_cast<__nv_bfloat16*>(raw);  // 64 x KDLD bf16

    int tid = threadIdx.x;
    int lane = tid & 31, w = tid >> 5;
    int g = lane >> 2, t = lane & 3;
    int wm = w >> 2, wn = w & 3;

    // triangular decode: block -> (a, b), a <= b
    int a = 0, rem = blockIdx.x;
    while (rem >= 32 - a) { rem -= 32 - a; a++; }
    int b = a + rem;
    int I0 = a * 128, J0 = b * 128;
    bool offdiag = (a != b);

    fill_tiles(AsU, BsU, dict, I0, J0, tid);
    if (tid < 128) {
        qs[tid]  = g_q[J0 + tid];
        qI[tid]  = g_q[I0 + tid];
        nJv[tid] = g_norm[J0 + tid]; aJv[tid] = g_alloc[J0 + tid];
        nIv[tid] = g_norm[I0 + tid]; aIv[tid] = g_alloc[I0 + tid];
    }
    __syncthreads();

    float acc[4][4][4];
#pragma unroll
    for (int m = 0; m < 4; m++)
#pragma unroll
        for (int n = 0; n < 4; n++)
#pragma unroll
            for (int r = 0; r < 4; r++) acc[m][n][r] = 0.f;

    gemm_tiles(AsU, BsU, acc, wm, wn, g, t);

    float colsum = 0.f;    // transposed (column) partial, accumulated across halves

#pragma unroll
    for (int half = 0; half < 2; half++) {
        __syncthreads();   // protect kdS overwrite (A/B dead after gemm)
        if (wm == half) {
#pragma unroll
            for (int m = 0; m < 4; m++)
#pragma unroll
                for (int n = 0; n < 4; n++)
#pragma unroll
                    for (int hf = 0; hf < 2; hf++) {
                        int rl = m*16 + g + 8*hf;
                        int cl = wn*32 + n*8 + 2*t;
                        float ni = nIv[half*64 + rl], ai = aIv[half*64 + rl];
                        float c0v = acc[m][n][2*hf], c1v = acc[m][n][2*hf+1];
                        float d0 = fmaxf(ni + nJv[cl]   - 2.0f*c0v, 0.0f);
                        float d1 = fmaxf(ni + nJv[cl+1] - 2.0f*c1v, 0.0f);
                        float k0 = __expf(-d0*INV2LS2) * ai * aJv[cl];
                        float k1 = __expf(-d1*INV2LS2) * ai * aJv[cl+1];
                        *reinterpret_cast<unsigned*>(&kdS[rl*KDLD + cl]) = pk_bf2(k0, k1);
                    }
        }
        __syncthreads();

        // normal orientation: rows of I (this half) -> tile (a,b); row partials
#pragma unroll
        for (int r8 = 0; r8 < 8; r8++) {
            int r  = r8*8 + w;
            int ig = I0 + half*64 + r;
            uint2 kp = *reinterpret_cast<const uint2*>(&kdS[r*KDLD + lane*4]);
            float2 k01 = __bfloat1622float2(*reinterpret_cast<const __nv_bfloat162*>(&kp.x));
            float2 k23 = __bfloat1622float2(*reinterpret_cast<const __nv_bfloat162*>(&kp.y));
            int c0 = lane*4;
            float hsum = k01.x*qs[c0] + k01.y*qs[c0+1] + k23.x*qs[c0+2] + k23.y*qs[c0+3];
            unsigned short s0 = pk_fp8(k01.x, k01.y);
            unsigned short s1 = pk_fp8(k23.x, k23.y);
            unsigned word = (unsigned)s0 | ((unsigned)s1 << 16);
            __stcs(reinterpret_cast<unsigned*>(g_kdd8 + (size_t)ig*MD + J0 + c0), word);
#pragma unroll
            for (int o = 16; o > 0; o >>= 1)
                hsum += __shfl_xor_sync(0xffffffffu, hsum, o);
            if (lane == 0) g_hpart[(size_t)b*MD + ig] = hsum;
        }

        // transposed orientation: rows of J -> tile (b,a); column partials
        if (offdiag) {
            int jr = tid >> 1, chunk = tid & 1;
            unsigned short sh[16];
#pragma unroll
            for (int ii = 0; ii < 16; ii++) {
                int i0 = chunk*32 + 2*ii;
                __nv_bfloat16 v0 = kdS[i0*KDLD + jr];
                __nv_bfloat16 v1 = kdS[(i0+1)*KDLD + jr];
                float f0 = __bfloat162float(v0), f1 = __bfloat162float(v1);
                sh[ii] = pk_fp8(f0, f1);
                colsum += f0 * qI[half*64 + i0] + f1 * qI[half*64 + i0 + 1];
            }
            unsigned wrd[8];
#pragma unroll
            for (int k2 = 0; k2 < 8; k2++)
                wrd[k2] = (unsigned)sh[2*k2] | ((unsigned)sh[2*k2+1] << 16);
            unsigned char* dst = g_kdd8 + (size_t)(J0+jr)*MD + I0 + half*64 + chunk*32;
            uint4* d4 = reinterpret_cast<uint4*>(dst);
            __stcs(&d4[0], make_uint4(wrd[0], wrd[1], wrd[2], wrd[3]));
            __stcs(&d4[1], make_uint4(wrd[4], wrd[5], wrd[6], wrd[7]));
        }
    }

    if (offdiag) {
        float other = __shfl_xor_sync(0xffffffffu, colsum, 1);
        if ((tid & 1) == 0) {
            int jr = tid >> 1;
            g_hpart[(size_t)a*MD + J0 + jr] = colsum + other;
        }
    }
}

// -------- h combine + scalars2 fused (one block) --------
__global__ void k_hscal(const float* __restrict__ y, const float* __restrict__ nn,
                        const float* __restrict__ nd, float* __restrict__ out) {
    __shared__ float red[8];
    int tid = threadIdx.x;
    float qh_p = 0.f;
    for (int i = tid; i < MD; i += 256) {
        float s = 0.f;
#pragma unroll
        for (int b = 0; b < NJB; b++) s += g_hpart[(size_t)b*MD + i];
        float h = FFC * g_hsig[i] + (1.0f - FFC) * s;
        g_h[i] = h;
        qh_p += g_q[i] * h;
    }
#pragma unroll
    for (int o = 16; o > 0; o >>= 1) qh_p += __shfl_xor_sync(0xffffffffu, qh_p, o);
    if ((tid & 31) == 0) red[tid >> 5] = qh_p;
    __syncthreads();
    if (tid == 0) {
        float qh = 0.f;
#pragma unroll
        for (int w2 = 0; w2 < 8; w2++) qh += red[w2];
        gs_qh = qh;
        float pu = gs_pu;
        float npv = fmaxf(pu + qh, 0.0f);
        float pv = REGC + npv;
        gs_npv = npv; gs_pv = pv;
        float cm = 0.f;
#pragma unroll
        for (int yd = 0; yd < 4; yd++) {
            float dy = y[yd] - gs_pm[yd];
            float c = dy / pv;
            gs_c[yd] = c;
            out[OFF_NN + yd] = nn[yd] + FFC * dy * dy / pv;
            cm += fabsf(c * (npv - qh));
        }
        out[OFF_ND] = nd[0] + FFC;
        gs_critM = cm;
    }
}

// -------- Qh = Q@h fused with criterion + per-block argmin --------
__global__ void k_qhcrit(const float* __restrict__ Q) {
    __shared__ float sv[8]; __shared__ int si[8];
    int tid = threadIdx.x;
    int gw = (blockIdx.x * 256 + tid) >> 5;
    int lane = tid & 31;
    const float4* Qr = reinterpret_cast<const float4*>(Q) + (size_t)gw * (MD/4);
    const float4* H4 = reinterpret_cast<const float4*>(g_h);
    float s = 0.f;
#pragma unroll 8
    for (int jb = lane; jb < MD/4; jb += 32) {
        float4 qv = Qr[jb], hv = H4[jb];
        s += qv.x*hv.x + qv.y*hv.y + qv.z*hv.z + qv.w*hv.w;
    }
#pragma unroll
    for (int o = 16; o > 0; o >>= 1) s += __shfl_xor_sync(0xffffffffu, s, o);
    if (lane == 0) {
        float pu = gs_pu;
        float cv;
        if (pu < JIT) {
            cv = 0.f;
        } else {
            float qi = g_q[gw];
            float dq = (g_alloc[gw] != 0.f) ? (Q[(size_t)gw*MD + gw] + qi*qi/pu)
                                            : __int_as_float(0x7f800000);
            float r = qi / pu;
            float qhm = gs_qh - gs_npv;
            float acc2 = 0.f;
#pragma unroll
            for (int yd = 0; yd < 4; yd++) {
                float num = g_Qmu[yd*MD + gw] + gs_c[yd]*s + r*gs_c[yd]*qhm;
                acc2 += fabsf(num / dq);
            }
            cv = acc2;
        }
        sv[tid >> 5] = cv; si[tid >> 5] = gw;
    }
    __syncthreads();
    if (tid == 0) {
        float bv = sv[0]; int bi = si[0];
#pragma unroll
        for (int w2 = 1; w2 < 8; w2++) {
            if (sv[w2] < bv || (sv[w2] == bv && si[w2] < bi)) { bv = sv[w2]; bi = si[w2]; }
        }
        g_pval[blockIdx.x] = bv; g_pidx[blockIdx.x] = bi;
    }
}

// -------- merged argmin + prune scalars + column copy --------
__global__ void k_colpfin(const float* __restrict__ Q, const int* __restrict__ tptr) {
    __shared__ float sv[256]; __shared__ int si[256];
    int tid = threadIdx.x;
    // every block re-derives the argmin deterministically (256 threads x 2 entries)
    float v0 = g_pval[tid], v1 = g_pval[tid + 256];
    int   i0 = g_pidx[tid], i1 = g_pidx[tid + 256];
    float bv; int bi;
    if (v1 < v0 || (v1 == v0 && i1 < i0)) { bv = v1; bi = i1; } else { bv = v0; bi = i0; }
    sv[tid] = bv; si[tid] = bi;
    __syncthreads();
    for (int st = 128; st > 0; st >>= 1) {
        if (tid < st) {
            if (sv[tid+st] < sv[tid] || (sv[tid+st] == sv[tid] && si[tid+st] < si[tid])) {
                sv[tid] = sv[tid+st]; si[tid] = si[tid+st];
            }
        }
        __syncthreads();
    }
    float pu = gs_pu;
    int p;
    if (pu < JIT) p = MD;
    else { p = si[0]; if (gs_critM < sv[0]) p = MD; }

    int i = blockIdx.x * 256 + tid;
    g_colp[i] = (p < MD) ? Q[(size_t)i*MD + p] : 0.0f;

    if (blockIdx.x == 0 && tid == 0) {
        gs_prune = p;
        float qp = (p < MD) ? g_q[p] : 0.0f;
        gs_qp = qp;
        bool xal = (p == MD) ? true : (g_alloc[p] != 0.f);
        float qaa = (p == MD) ? (1.0f/pu) : (Q[(size_t)p*MD + p] + qp*qp/pu);
        gs_denom = xal ? qaa : __int_as_float(0x7f800000);
        int bits = tptr[0];
        gs_tval = (bits >= 0 && bits < (1 << 26)) ? (float)bits : __int_as_float(bits);
    }
}

// -------- Q_n writer (row per block) --------
__device__ __forceinline__ float qn_elem(int p, bool rowp, int j, float Qij,
                                         float qi, float qj, float colj,
                                         float qp, float ipu, float Bi, float dinv) {
    float m, Bj;
    if (p < MD) {
        if (rowp) m = (j == p) ? ipu : (-qj * ipu);
        else      m = (j == p) ? (-qi * ipu) : (Qij + qi*qj*ipu);
        Bj = (j == p) ? (-qp * ipu) : (colj + qj*qp*ipu);
    } else {
        m  = Qij + qi*qj*ipu;
        Bj = -qj * ipu;
    }
    return m - Bi * Bj * dinv;
}

__global__ void k_postQ(const float* __restrict__ Q, float* __restrict__ out) {
    int i = blockIdx.x;
    int tid = threadIdx.x;
    int p = gs_prune;
    float pu = gs_pu, qp = gs_qp, qi = g_q[i];
    float ipu = 1.0f / pu;
    float dinv = 1.0f / gs_denom;
    bool rowp = (p < MD) && (i == p);
    float Bi = (p < MD) ? (rowp ? (-qp*ipu) : (g_colp[i] + qi*qp*ipu)) : (-qi*ipu);

    const float4* Qr = reinterpret_cast<const float4*>(Q + (size_t)i*MD);
    float4* oq = reinterpret_cast<float4*>(out + OFF_Q + (size_t)i*MD);
    const float4* q4 = reinterpret_cast<const float4*>(g_q);
    const float4* c4 = reinterpret_cast<const float4*>(g_colp);

    for (int jb = tid; jb < MD/4; jb += 256) {
        float4 Qv = Qr[jb];
        float4 qq = q4[jb]; float4 cc = c4[jb];
        int j0 = jb * 4;
        float4 oqv;
        oqv.x = qn_elem(p, rowp, j0+0, Qv.x, qi, qq.x, cc.x, qp, ipu, Bi, dinv);
        oqv.y = qn_elem(p, rowp, j0+1, Qv.y, qi, qq.y, cc.y, qp, ipu, Bi, dinv);
        oqv.z = qn_elem(p, rowp, j0+2, Qv.z, qi, qq.z, cc.z, qp, ipu, Bi, dinv);
        oqv.w = qn_elem(p, rowp, j0+3, Qv.w, qi, qq.w, cc.w, qp, ipu, Bi, dinv);
        __stcs(&oq[jb], oqv);
    }
}

// -------- sig_n writer (row per block) --------
__global__ void k_postS(const float* __restrict__ sigma, const float* __restrict__ TI,
                        float* __restrict__ out) {
    int i = blockIdx.x;
    int tid = threadIdx.x;
    int p = gs_prune;
    float npv = gs_npv, ivp = 1.0f / gs_pv, tval = gs_tval;
    bool rowp = (p < MD) && (i == p);
    float hi = g_h[i];
    float tni = rowp ? tval : TI[i];
    float mi = (tni >= 0.f) ? 1.f : 0.f;
    float ppi = rowp ? npv : hi;

    const float4* Sr = reinterpret_cast<const float4*>(sigma + (size_t)i*MD);
    const unsigned* Kr = reinterpret_cast<const unsigned*>(g_kdd8 + (size_t)i*MD);
    float4* os = reinterpret_cast<float4*>(out + OFF_SIG + (size_t)i*MD);
    const float4* h4 = reinterpret_cast<const float4*>(g_h);
    const float4* t4 = reinterpret_cast<const float4*>(TI);

    for (int jb = tid; jb < MD/4; jb += 256) {
        float4 sg = __ldcs(&Sr[jb]);
        unsigned kp = __ldcs(&Kr[jb]);
        float4 hh = h4[jb]; float4 tt = t4[jb];
        int j0 = jb * 4;

        float4 kf = fp8x4_to_f4(kp);
        float kdf[4] = {kf.x, kf.y, kf.z, kf.w};
        float svv[4] = {sg.x, sg.y, sg.z, sg.w};
        float hvv[4] = {hh.x, hh.y, hh.z, hh.w};
        float tvv[4] = {tt.x, tt.y, tt.z, tt.w};
        float ov[4];
#pragma unroll
        for (int c = 0; c < 4; c++) {
            int j = j0 + c;
            float spre = FFC*svv[c] + (1.0f-FFC)*kdf[c];
            bool colp = (p < MD) && (j == p);
            float tj = colp ? tval : tvv[c];
            float mj = (tj >= 0.f) ? 1.f : 0.f;
            float ms  = rowp ? (colp ? npv : hvv[c]) : (colp ? hi : spre);
            float ppj = colp ? npv : hvv[c];
            ov[c] = mi * mj * (ms - ppi * ppj * ivp);
        }
        float4 osv; osv.x=ov[0]; osv.y=ov[1]; osv.z=ov[2]; osv.w=ov[3];
        __stcs(&os[jb], osv);
    }
}

// -------- tail: mu_n, dict_n, ti_n --------
__global__ void k_tail(const float* __restrict__ mu, const float* __restrict__ dict,
                       const float* __restrict__ x, const float* __restrict__ TI,
                       float* __restrict__ out) {
    int idx = blockIdx.x * 256 + threadIdx.x;   // 65536 threads
    int p = gs_prune;
    float tval = gs_tval;
    {
        int row = idx >> 4, c4i = idx & 15;
        float4 v;
        if (p < MD && row == p) v = *reinterpret_cast<const float4*>(x + c4i*4);
        else v = *reinterpret_cast<const float4*>(dict + (size_t)row*DD + c4i*4);
        *reinterpret_cast<float4*>(out + OFF_DICT + (size_t)row*DD + c4i*4) = v;
    }
    if (idx < MD) {
        bool rowp = (p < MD) && (idx == p);
        float tn = rowp ? tval : TI[idx];
        out[OFF_TI + idx] = tn;
        float sf = sqrtf(FFC);
        float hi = g_h[idx];
#pragma unroll
        for (int yd = 0; yd < 4; yd++) {
            float val;
            if (tn < 0.f) val = 0.f;
            else if (rowp) val = gs_pm[yd] + gs_c[yd] * gs_npv;
            else val = sf * mu[yd*MD + idx] + gs_c[yd] * hi;
            out[OFF_MU + yd*MD + idx] = val;
        }
    }
}

extern "C" void kernel_launch(void* const* d_in, const int* in_sizes, int n_in,
                              void* d_out, int out_size) {
    const float* dict = (const float*)d_in[0];
    const float* mu   = (const float*)d_in[1];
    const float* sigma= (const float*)d_in[2];
    const float* Q    = (const float*)d_in[3];
    const float* x    = (const float*)d_in[4];
    const float* y    = (const float*)d_in[5];
    const float* nn   = (const float*)d_in[6];
    const float* nd   = (const float*)d_in[7];
    const float* ti   = (const float*)d_in[8];
    const int*   tptr = (const int*)d_in[9];
    float* out = (float*)d_out;

    static cudaStream_t s_aux = nullptr;
    static cudaEvent_t ev_fork1, ev_join1, ev_fork2, ev_join2;
    if (!s_aux) {
        cudaStreamCreateWithFlags(&s_aux, cudaStreamNonBlocking);
        cudaEventCreateWithFlags(&ev_fork1, cudaEventDisableTiming);
        cudaEventCreateWithFlags(&ev_join1, cudaEventDisableTiming);
        cudaEventCreateWithFlags(&ev_fork2, cudaEventDisableTiming);
        cudaEventCreateWithFlags(&ev_join2, cudaEventDisableTiming);
    }

    k_kdx<<<16, 256>>>(dict, x, ti);
    k_matvec5<<<512, 256>>>(Q, mu);
    k_scalars1<<<1, 256>>>(mu);

    // fork: sigma@q on aux stream, overlapped with the compute-bound GEMM pass
    cudaEventRecord(ev_fork1, 0);
    cudaStreamWaitEvent(s_aux, ev_fork1, 0);
    k_sigq<<<512, 256, 0, s_aux>>>(sigma);
    k_pass1<<<528, 256>>>(dict);
    cudaEventRecord(ev_join1, s_aux);
    cudaStreamWaitEvent(0, ev_join1, 0);

    k_hscal<<<1, 256>>>(y, nn, nd, out);
    k_qhcrit<<<512, 256>>>(Q);
    k_colpfin<<<16, 256>>>(Q, tptr);

    // fork: tail + Q_n on aux, sig_n on main — disjoint inputs/outputs
    cudaEventRecord(ev_fork2, 0);
    cudaStreamWaitEvent(s_aux, ev_fork2, 0);
    k_tail<<<256, 256, 0, s_aux>>>(mu, dict, x, ti, out);
    k_postQ<<<4096, 256, 0, s_aux>>>(Q, out);
    k_postS<<<4096, 256>>>(sigma, ti, out);
    cudaEventRecord(ev_join2, s_aux);
    cudaStreamWaitEvent(0, ev_join2, 0);
}

// round 12
// speedup vs baseline: 1.5973x; 1.2163x over previous
#include <cuda_runtime.h>
#include <cuda_bf16.h>
#include <cuda_fp16.h>
#include <math.h>

#define MD 4096
#define DD 64
#define NJB 32
#define FFC 0.999f
#define REGC 0.01f
#define JIT 1e-10f
#define INV2LS2 (1.0f/128.0f)

#define OFF_MU   ((size_t)0)
#define OFF_SIG  ((size_t)16384)
#define OFF_Q    (OFF_SIG + (size_t)MD*MD)
#define OFF_DICT (OFF_Q   + (size_t)MD*MD)
#define OFF_TI   (OFF_DICT + (size_t)MD*DD)
#define OFF_NN   (OFF_TI + MD)
#define OFF_ND   (OFF_NN + 4)

// -------- scratch (device globals; allocations forbidden) --------
static __device__ float g_kdx[MD], g_alloc[MD], g_norm[MD];
static __device__ float g_q[MD], g_h[MD], g_hsig[MD], g_Qmu[4*MD];
static __device__ float g_hpart[NJB*MD];
static __device__ float g_colp[MD];
static __device__ unsigned char g_kdd8[(size_t)MD*MD];   // 16.7 MB fp8(e4m3) Kdd cache
static __device__ float g_pval[512];
static __device__ int   g_pidx[512];
static __device__ float g_qhp[16];
static __device__ float gs_pu, gs_pm[4], gs_qh, gs_npv, gs_pv, gs_c[4];
static __device__ float gs_critM, gs_denom, gs_qp, gs_tval;
static __device__ int   gs_prune;

__device__ __forceinline__ unsigned pk_bf2(float a, float b) {
    __nv_bfloat162 h = __floats2bfloat162_rn(a, b);
    return *reinterpret_cast<unsigned*>(&h);
}

// pack two floats to e4m3x2: low byte = lo, high byte = hi
__device__ __forceinline__ unsigned short pk_fp8(float lo, float hi) {
    unsigned short r;
    asm("cvt.rn.satfinite.e4m3x2.f32 %0, %1, %2;" : "=h"(r) : "f"(hi), "f"(lo));
    return r;
}

// decode 4 packed e4m3 bytes -> 4 floats
__device__ __forceinline__ float4 fp8x4_to_f4(unsigned v) {
    unsigned short lo = (unsigned short)(v & 0xFFFFu);
    unsigned short hi = (unsigned short)(v >> 16);
    unsigned r0, r1;
    asm("cvt.rn.f16x2.e4m3x2 %0, %1;" : "=r"(r0) : "h"(lo));
    asm("cvt.rn.f16x2.e4m3x2 %0, %1;" : "=r"(r1) : "h"(hi));
    __half2 h0 = *reinterpret_cast<__half2*>(&r0);
    __half2 h1 = *reinterpret_cast<__half2*>(&r1);
    float2 f0 = __half22float2(h0);
    float2 f1 = __half22float2(h1);
    return make_float4(f0.x, f0.y, f1.x, f1.y);
}

__device__ __forceinline__ void mma16816(float* c, unsigned a0, unsigned a1,
                                         unsigned a2, unsigned a3,
                                         unsigned b0, unsigned b1) {
    asm volatile(
        "mma.sync.aligned.m16n8k16.row.col.f32.bf16.bf16.f32 "
        "{%0,%1,%2,%3},{%4,%5,%6,%7},{%8,%9},{%0,%1,%2,%3};\n"
        : "+f"(c[0]), "+f"(c[1]), "+f"(c[2]), "+f"(c[3])
        : "r"(a0), "r"(a1), "r"(a2), "r"(a3), "r"(b0), "r"(b1));
}

// -------- K_dx, alloc, row norms --------
__global__ void k_kdx(const float* __restrict__ dict, const float* __restrict__ x,
                      const float* __restrict__ ti) {
    __shared__ float xs[DD];
    int tid = threadIdx.x;
    if (tid < DD) xs[tid] = x[tid];
    __syncthreads();
    int i = blockIdx.x * 256 + tid;
    const float* dr = dict + (size_t)i * DD;
    float a2 = 0.f, ip = 0.f, x2 = 0.f;
#pragma unroll
    for (int k = 0; k < DD; k++) { float d = dr[k], xv = xs[k]; a2 += d*d; ip += d*xv; x2 += xv*xv; }
    float d2 = fmaxf(a2 + x2 - 2.0f*ip, 0.0f);
    float al = (ti[i] >= 0.0f) ? 1.0f : 0.0f;
    g_kdx[i] = __expf(-d2 * INV2LS2) * al;
    g_alloc[i] = al;
    g_norm[i] = a2;
}

// -------- q = Q@kdx, Qmu = sqrt(FF)*Q@mu (warp per row) --------
__global__ void k_matvec5(const float* __restrict__ Q, const float* __restrict__ mu) {
    int gw = (blockIdx.x * 256 + threadIdx.x) >> 5;
    int lane = threadIdx.x & 31;
    const float4* Qr = reinterpret_cast<const float4*>(Q) + (size_t)gw * (MD/4);
    const float4* K4 = reinterpret_cast<const float4*>(g_kdx);
    const float4* M4 = reinterpret_cast<const float4*>(mu);
    float s[5] = {0,0,0,0,0};
#pragma unroll 4
    for (int jb = lane; jb < MD/4; jb += 32) {
        float4 qv = Qr[jb], kv = K4[jb];
        s[0] += qv.x*kv.x + qv.y*kv.y + qv.z*kv.z + qv.w*kv.w;
#pragma unroll
        for (int yd = 0; yd < 4; yd++) {
            float4 mv = M4[yd*(MD/4) + jb];
            s[1+yd] += qv.x*mv.x + qv.y*mv.y + qv.z*mv.z + qv.w*mv.w;
        }
    }
#pragma unroll
    for (int o = 16; o > 0; o >>= 1)
#pragma unroll
        for (int r = 0; r < 5; r++) s[r] += __shfl_xor_sync(0xffffffffu, s[r], o);
    if (lane == 0) {
        g_q[gw] = s[0];
        float sf = sqrtf(FFC);
#pragma unroll
        for (int yd = 0; yd < 4; yd++) g_Qmu[yd*MD + gw] = sf * s[1+yd];
    }
}

// -------- scalars 1: pu, pred_mean --------
__global__ void k_scalars1(const float* __restrict__ mu) {
    __shared__ float red[5][8];
    int tid = threadIdx.x;
    float s[5] = {0,0,0,0,0};
    for (int i = tid; i < MD; i += 256) {
        float qi = g_q[i];
        s[0] += g_kdx[i] * qi;
#pragma unroll
        for (int yd = 0; yd < 4; yd++) s[1+yd] += qi * mu[yd*MD + i];
    }
#pragma unroll
    for (int o = 16; o > 0; o >>= 1)
#pragma unroll
        for (int r = 0; r < 5; r++) s[r] += __shfl_xor_sync(0xffffffffu, s[r], o);
    if ((tid & 31) == 0)
#pragma unroll
        for (int r = 0; r < 5; r++) red[r][tid >> 5] = s[r];
    __syncthreads();
    if (tid == 0) {
        float t[5];
#pragma unroll
        for (int r = 0; r < 5; r++) { t[r] = 0.f;
#pragma unroll
            for (int w = 0; w < 8; w++) t[r] += red[r][w]; }
        gs_pu = fmaxf((1.0f + JIT) - t[0], 0.0f);
        float sf = sqrtf(FFC);
#pragma unroll
        for (int yd = 0; yd < 4; yd++) gs_pm[yd] = sf * t[1+yd];
    }
}

// -------- hsig = sigma @ q (warp per row, streaming loads: keep Q in L2) --------
__global__ void k_sigq(const float* __restrict__ sigma) {
    int gw = (blockIdx.x * 256 + threadIdx.x) >> 5;
    int lane = threadIdx.x & 31;
    const float4* Sr = reinterpret_cast<const float4*>(sigma) + (size_t)gw * (MD/4);
    const float4* Q4 = reinterpret_cast<const float4*>(g_q);
    float s = 0.f;
#pragma unroll 8
    for (int jb = lane; jb < MD/4; jb += 32) {
        float4 sv = __ldcs(&Sr[jb]);
        float4 qv = Q4[jb];
        s += sv.x*qv.x + sv.y*qv.y + sv.z*qv.z + sv.w*qv.w;
    }
#pragma unroll
    for (int o = 16; o > 0; o >>= 1) s += __shfl_xor_sync(0xffffffffu, s, o);
    if (lane == 0) g_hsig[gw] = s;
}

// =================== Tensor-core Kdd GEMM machinery ====================
#define LDB36 36      // u32 row stride (72 bf16) for A/B tiles
#define KDLD 132      // bf16 row stride of the kd staging tile (64 x 128 used)

__device__ __forceinline__ void fill_tiles(unsigned* AsU, unsigned* BsU,
                                           const float* __restrict__ dict,
                                           int I0, int J0, int tid) {
    const float4* dI = reinterpret_cast<const float4*>(dict + (size_t)I0 * DD);
    const float4* dJ = reinterpret_cast<const float4*>(dict + (size_t)J0 * DD);
    for (int idx = tid; idx < 2048; idx += 256) {
        int r = idx >> 4, c4 = idx & 15;
        float4 v = dI[r*16 + c4];
        AsU[r*LDB36 + c4*2]     = pk_bf2(v.x, v.y);
        AsU[r*LDB36 + c4*2 + 1] = pk_bf2(v.z, v.w);
        float4 w = dJ[r*16 + c4];
        BsU[r*LDB36 + c4*2]     = pk_bf2(w.x, w.y);
        BsU[r*LDB36 + c4*2 + 1] = pk_bf2(w.z, w.w);
    }
}

__device__ __forceinline__ void gemm_tiles(const unsigned* AsU, const unsigned* BsU,
                                           float acc[4][4][4], int wm, int wn,
                                           int g, int t) {
#pragma unroll
    for (int ks = 0; ks < 4; ks++) {
        unsigned bf[4][2];
#pragma unroll
        for (int n = 0; n < 4; n++) {
            int rb = wn*32 + n*8 + g;
            bf[n][0] = BsU[rb*LDB36 + ks*8 + t];
            bf[n][1] = BsU[rb*LDB36 + ks*8 + t + 4];
        }
#pragma unroll
        for (int m = 0; m < 4; m++) {
            int ra = wm*64 + m*16 + g;
            unsigned a0 = AsU[ra*LDB36 + ks*8 + t];
            unsigned a1 = AsU[(ra+8)*LDB36 + ks*8 + t];
            unsigned a2 = AsU[ra*LDB36 + ks*8 + t + 4];
            unsigned a3 = AsU[(ra+8)*LDB36 + ks*8 + t + 4];
#pragma unroll
            for (int n = 0; n < 4; n++)
                mma16816(acc[m][n], a0, a1, a2, a3, bf[n][0], bf[n][1]);
        }
    }
}

// ---- pass 1 (triangular): kd tiles (a,b)+(b,a) in fp8, deterministic h partials
__global__ void __launch_bounds__(256, 2) k_pass1(const float* __restrict__ dict) {
    __shared__ __align__(16) char raw[128*LDB36*4*2];   // A/B tiles; then kd stage
    __shared__ float qs[128], qI[128], nIv[128], nJv[128], aIv[128], aJv[128];

    unsigned* AsU = reinterpret_cast<unsigned*>(raw);
    unsigned* BsU = AsU + 128*LDB36;
    __nv_bfloat16* kdS = reinterpret_cast<__nv_bfloat16*>(raw);  // 64 x KDLD bf16

    int tid = threadIdx.x;
    int lane = tid & 31, w = tid >> 5;
    int g = lane >> 2, t = lane & 3;
    int wm = w >> 2, wn = w & 3;

    // triangular decode: block -> (a, b), a <= b
    int a = 0, rem = blockIdx.x;
    while (rem >= 32 - a) { rem -= 32 - a; a++; }
    int b = a + rem;
    int I0 = a * 128, J0 = b * 128;
    bool offdiag = (a != b);

    fill_tiles(AsU, BsU, dict, I0, J0, tid);
    if (tid < 128) {
        qs[tid]  = g_q[J0 + tid];
        qI[tid]  = g_q[I0 + tid];
        nJv[tid] = g_norm[J0 + tid]; aJv[tid] = g_alloc[J0 + tid];
        nIv[tid] = g_norm[I0 + tid]; aIv[tid] = g_alloc[I0 + tid];
    }
    __syncthreads();

    float acc[4][4][4];
#pragma unroll
    for (int m = 0; m < 4; m++)
#pragma unroll
        for (int n = 0; n < 4; n++)
#pragma unroll
            for (int r = 0; r < 4; r++) acc[m][n][r] = 0.f;

    gemm_tiles(AsU, BsU, acc, wm, wn, g, t);

    float colsum = 0.f;    // transposed (column) partial, accumulated across halves

#pragma unroll
    for (int half = 0; half < 2; half++) {
        __syncthreads();   // protect kdS overwrite (A/B dead after gemm)
        if (wm == half) {
#pragma unroll
            for (int m = 0; m < 4; m++)
#pragma unroll
                for (int n = 0; n < 4; n++)
#pragma unroll
                    for (int hf = 0; hf < 2; hf++) {
                        int rl = m*16 + g + 8*hf;
                        int cl = wn*32 + n*8 + 2*t;
                        float ni = nIv[half*64 + rl], ai = aIv[half*64 + rl];
                        float c0v = acc[m][n][2*hf], c1v = acc[m][n][2*hf+1];
                        float d0 = fmaxf(ni + nJv[cl]   - 2.0f*c0v, 0.0f);
                        float d1 = fmaxf(ni + nJv[cl+1] - 2.0f*c1v, 0.0f);
                        float k0 = __expf(-d0*INV2LS2) * ai * aJv[cl];
                        float k1 = __expf(-d1*INV2LS2) * ai * aJv[cl+1];
                        *reinterpret_cast<unsigned*>(&kdS[rl*KDLD + cl]) = pk_bf2(k0, k1);
                    }
        }
        __syncthreads();

        // normal orientation: rows of I (this half) -> tile (a,b); row partials
#pragma unroll
        for (int r8 = 0; r8 < 8; r8++) {
            int r  = r8*8 + w;
            int ig = I0 + half*64 + r;
            uint2 kp = *reinterpret_cast<const uint2*>(&kdS[r*KDLD + lane*4]);
            float2 k01 = __bfloat1622float2(*reinterpret_cast<const __nv_bfloat162*>(&kp.x));
            float2 k23 = __bfloat1622float2(*reinterpret_cast<const __nv_bfloat162*>(&kp.y));
            int c0 = lane*4;
            float hsum = k01.x*qs[c0] + k01.y*qs[c0+1] + k23.x*qs[c0+2] + k23.y*qs[c0+3];
            unsigned short s0 = pk_fp8(k01.x, k01.y);
            unsigned short s1 = pk_fp8(k23.x, k23.y);
            unsigned word = (unsigned)s0 | ((unsigned)s1 << 16);
            __stcs(reinterpret_cast<unsigned*>(g_kdd8 + (size_t)ig*MD + J0 + c0), word);
#pragma unroll
            for (int o = 16; o > 0; o >>= 1)
                hsum += __shfl_xor_sync(0xffffffffu, hsum, o);
            if (lane == 0) g_hpart[(size_t)b*MD + ig] = hsum;
        }

        // transposed orientation: rows of J -> tile (b,a); column partials
        if (offdiag) {
            int jr = tid >> 1, chunk = tid & 1;
            unsigned short sh[16];
#pragma unroll
            for (int ii = 0; ii < 16; ii++) {
                int i0 = chunk*32 + 2*ii;
                __nv_bfloat16 v0 = kdS[i0*KDLD + jr];
                __nv_bfloat16 v1 = kdS[(i0+1)*KDLD + jr];
                float f0 = __bfloat162float(v0), f1 = __bfloat162float(v1);
                sh[ii] = pk_fp8(f0, f1);
                colsum += f0 * qI[half*64 + i0] + f1 * qI[half*64 + i0 + 1];
            }
            unsigned wrd[8];
#pragma unroll
            for (int k2 = 0; k2 < 8; k2++)
                wrd[k2] = (unsigned)sh[2*k2] | ((unsigned)sh[2*k2+1] << 16);
            unsigned char* dst = g_kdd8 + (size_t)(J0+jr)*MD + I0 + half*64 + chunk*32;
            uint4* d4 = reinterpret_cast<uint4*>(dst);
            __stcs(&d4[0], make_uint4(wrd[0], wrd[1], wrd[2], wrd[3]));
            __stcs(&d4[1], make_uint4(wrd[4], wrd[5], wrd[6], wrd[7]));
        }
    }

    if (offdiag) {
        float other = __shfl_xor_sync(0xffffffffu, colsum, 1);
        if ((tid & 1) == 0) {
            int jr = tid >> 1;
            g_hpart[(size_t)a*MD + J0 + jr] = colsum + other;
        }
    }
}

// -------- h reduce (parallel): h = FF*hsig + (1-FF)*sum(hpart), qh partials ----
__global__ void k_hred() {
    __shared__ float red[8];
    int tid = threadIdx.x;
    int i = blockIdx.x * 256 + tid;
    float s = 0.f;
#pragma unroll
    for (int b = 0; b < NJB; b++) s += g_hpart[(size_t)b*MD + i];
    float h = FFC * g_hsig[i] + (1.0f - FFC) * s;
    g_h[i] = h;
    float qh_p = g_q[i] * h;
#pragma unroll
    for (int o = 16; o > 0; o >>= 1) qh_p += __shfl_xor_sync(0xffffffffu, qh_p, o);
    if ((tid & 31) == 0) red[tid >> 5] = qh_p;
    __syncthreads();
    if (tid == 0) {
        float t = 0.f;
#pragma unroll
        for (int w2 = 0; w2 < 8; w2++) t += red[w2];
        g_qhp[blockIdx.x] = t;
    }
}

// -------- scalars 2 (one warp): qh, npv, pv, c; nnum/nden out --------
__global__ void k_hfin(const float* __restrict__ y, const float* __restrict__ nn,
                       const float* __restrict__ nd, float* __restrict__ out) {
    if (threadIdx.x != 0) return;
    float qh = 0.f;
#pragma unroll
    for (int b = 0; b < 16; b++) qh += g_qhp[b];
    gs_qh = qh;
    float pu = gs_pu;
    float npv = fmaxf(pu + qh, 0.0f);
    float pv = REGC + npv;
    gs_npv = npv; gs_pv = pv;
    float cm = 0.f;
#pragma unroll
    for (int yd = 0; yd < 4; yd++) {
        float dy = y[yd] - gs_pm[yd];
        float c = dy / pv;
        gs_c[yd] = c;
        out[OFF_NN + yd] = nn[yd] + FFC * dy * dy / pv;
        cm += fabsf(c * (npv - qh));
    }
    out[OFF_ND] = nd[0] + FFC;
    gs_critM = cm;
}

// -------- Qh = Q@h fused with criterion + per-block argmin --------
__global__ void k_qhcrit(const float* __restrict__ Q) {
    __shared__ float sv[8]; __shared__ int si[8];
    int tid = threadIdx.x;
    int gw = (blockIdx.x * 256 + tid) >> 5;
    int lane = tid & 31;
    const float4* Qr = reinterpret_cast<const float4*>(Q) + (size_t)gw * (MD/4);
    const float4* H4 = reinterpret_cast<const float4*>(g_h);
    float s = 0.f;
#pragma unroll 8
    for (int jb = lane; jb < MD/4; jb += 32) {
        float4 qv = Qr[jb], hv = H4[jb];
        s += qv.x*hv.x + qv.y*hv.y + qv.z*hv.z + qv.w*hv.w;
    }
#pragma unroll
    for (int o = 16; o > 0; o >>= 1) s += __shfl_xor_sync(0xffffffffu, s, o);
    if (lane == 0) {
        float pu = gs_pu;
        float cv;
        if (pu < JIT) {
            cv = 0.f;
        } else {
            float qi = g_q[gw];
            float dq = (g_alloc[gw] != 0.f) ? (Q[(size_t)gw*MD + gw] + qi*qi/pu)
                                            : __int_as_float(0x7f800000);
            float r = qi / pu;
            float qhm = gs_qh - gs_npv;
            float acc2 = 0.f;
#pragma unroll
            for (int yd = 0; yd < 4; yd++) {
                float num = g_Qmu[yd*MD + gw] + gs_c[yd]*s + r*gs_c[yd]*qhm;
                acc2 += fabsf(num / dq);
            }
            cv = acc2;
        }
        sv[tid >> 5] = cv; si[tid >> 5] = gw;
    }
    __syncthreads();
    if (tid == 0) {
        float bv = sv[0]; int bi = si[0];
#pragma unroll
        for (int w2 = 1; w2 < 8; w2++) {
            if (sv[w2] < bv || (sv[w2] == bv && si[w2] < bi)) { bv = sv[w2]; bi = si[w2]; }
        }
        g_pval[blockIdx.x] = bv; g_pidx[blockIdx.x] = bi;
    }
}

// -------- merged argmin + prune scalars + column copy --------
__global__ void k_colpfin(const float* __restrict__ Q, const int* __restrict__ tptr) {
    __shared__ float sv[256]; __shared__ int si[256];
    int tid = threadIdx.x;
    float v0 = g_pval[tid], v1 = g_pval[tid + 256];
    int   i0 = g_pidx[tid], i1 = g_pidx[tid + 256];
    float bv; int bi;
    if (v1 < v0 || (v1 == v0 && i1 < i0)) { bv = v1; bi = i1; } else { bv = v0; bi = i0; }
    sv[tid] = bv; si[tid] = bi;
    __syncthreads();
    for (int st = 128; st > 0; st >>= 1) {
        if (tid < st) {
            if (sv[tid+st] < sv[tid] || (sv[tid+st] == sv[tid] && si[tid+st] < si[tid])) {
                sv[tid] = sv[tid+st]; si[tid] = si[tid+st];
            }
        }
        __syncthreads();
    }
    float pu = gs_pu;
    int p;
    if (pu < JIT) p = MD;
    else { p = si[0]; if (gs_critM < sv[0]) p = MD; }

    int i = blockIdx.x * 256 + tid;
    g_colp[i] = (p < MD) ? Q[(size_t)i*MD + p] : 0.0f;

    if (blockIdx.x == 0 && tid == 0) {
        gs_prune = p;
        float qp = (p < MD) ? g_q[p] : 0.0f;
        gs_qp = qp;
        bool xal = (p == MD) ? true : (g_alloc[p] != 0.f);
        float qaa = (p == MD) ? (1.0f/pu) : (Q[(size_t)p*MD + p] + qp*qp/pu);
        gs_denom = xal ? qaa : __int_as_float(0x7f800000);
        int bits = tptr[0];
        gs_tval = (bits >= 0 && bits < (1 << 26)) ? (float)bits : __int_as_float(bits);
    }
}

// -------- Q_n writer (row per block) --------
__device__ __forceinline__ float qn_elem(int p, bool rowp, int j, float Qij,
                                         float qi, float qj, float colj,
                                         float qp, float ipu, float Bi, float dinv) {
    float m, Bj;
    if (p < MD) {
        if (rowp) m = (j == p) ? ipu : (-qj * ipu);
        else      m = (j == p) ? (-qi * ipu) : (Qij + qi*qj*ipu);
        Bj = (j == p) ? (-qp * ipu) : (colj + qj*qp*ipu);
    } else {
        m  = Qij + qi*qj*ipu;
        Bj = -qj * ipu;
    }
    return m - Bi * Bj * dinv;
}

__global__ void k_postQ(const float* __restrict__ Q, float* __restrict__ out) {
    int i = blockIdx.x;
    int tid = threadIdx.x;
    int p = gs_prune;
    float pu = gs_pu, qp = gs_qp, qi = g_q[i];
    float ipu = 1.0f / pu;
    float dinv = 1.0f / gs_denom;
    bool rowp = (p < MD) && (i == p);
    float Bi = (p < MD) ? (rowp ? (-qp*ipu) : (g_colp[i] + qi*qp*ipu)) : (-qi*ipu);

    const float4* Qr = reinterpret_cast<const float4*>(Q + (size_t)i*MD);
    float4* oq = reinterpret_cast<float4*>(out + OFF_Q + (size_t)i*MD);
    const float4* q4 = reinterpret_cast<const float4*>(g_q);
    const float4* c4 = reinterpret_cast<const float4*>(g_colp);

    for (int jb = tid; jb < MD/4; jb += 256) {
        float4 Qv = Qr[jb];
        float4 qq = q4[jb]; float4 cc = c4[jb];
        int j0 = jb * 4;
        float4 oqv;
        oqv.x = qn_elem(p, rowp, j0+0, Qv.x, qi, qq.x, cc.x, qp, ipu, Bi, dinv);
        oqv.y = qn_elem(p, rowp, j0+1, Qv.y, qi, qq.y, cc.y, qp, ipu, Bi, dinv);
        oqv.z = qn_elem(p, rowp, j0+2, Qv.z, qi, qq.z, cc.z, qp, ipu, Bi, dinv);
        oqv.w = qn_elem(p, rowp, j0+3, Qv.w, qi, qq.w, cc.w, qp, ipu, Bi, dinv);
        __stcs(&oq[jb], oqv);
    }
}

// -------- sig_n writer (row per block) --------
__global__ void k_postS(const float* __restrict__ sigma, const float* __restrict__ TI,
                        float* __restrict__ out) {
    int i = blockIdx.x;
    int tid = threadIdx.x;
    int p = gs_prune;
    float npv = gs_npv, ivp = 1.0f / gs_pv, tval = gs_tval;
    bool rowp = (p < MD) && (i == p);
    float hi = g_h[i];
    float tni = rowp ? tval : TI[i];
    float mi = (tni >= 0.f) ? 1.f : 0.f;
    float ppi = rowp ? npv : hi;

    const float4* Sr = reinterpret_cast<const float4*>(sigma + (size_t)i*MD);
    const unsigned* Kr = reinterpret_cast<const unsigned*>(g_kdd8 + (size_t)i*MD);
    float4* os = reinterpret_cast<float4*>(out + OFF_SIG + (size_t)i*MD);
    const float4* h4 = reinterpret_cast<const float4*>(g_h);
    const float4* t4 = reinterpret_cast<const float4*>(TI);

    for (int jb = tid; jb < MD/4; jb += 256) {
        float4 sg = __ldcs(&Sr[jb]);
        unsigned kp = __ldcs(&Kr[jb]);
        float4 hh = h4[jb]; float4 tt = t4[jb];
        int j0 = jb * 4;

        float4 kf = fp8x4_to_f4(kp);
        float kdf[4] = {kf.x, kf.y, kf.z, kf.w};
        float svv[4] = {sg.x, sg.y, sg.z, sg.w};
        float hvv[4] = {hh.x, hh.y, hh.z, hh.w};
        float tvv[4] = {tt.x, tt.y, tt.z, tt.w};
        float ov[4];
#pragma unroll
        for (int c = 0; c < 4; c++) {
            int j = j0 + c;
            float spre = FFC*svv[c] + (1.0f-FFC)*kdf[c];
            bool colp = (p < MD) && (j == p);
            float tj = colp ? tval : tvv[c];
            float mj = (tj >= 0.f) ? 1.f : 0.f;
            float ms  = rowp ? (colp ? npv : hvv[c]) : (colp ? hi : spre);
            float ppj = colp ? npv : hvv[c];
            ov[c] = mi * mj * (ms - ppi * ppj * ivp);
        }
        float4 osv; osv.x=ov[0]; osv.y=ov[1]; osv.z=ov[2]; osv.w=ov[3];
        __stcs(&os[jb], osv);
    }
}

// -------- tail: mu_n, dict_n, ti_n --------
__global__ void k_tail(const float* __restrict__ mu, const float* __restrict__ dict,
                       const float* __restrict__ x, const float* __restrict__ TI,
                       float* __restrict__ out) {
    int idx = blockIdx.x * 256 + threadIdx.x;   // 65536 threads
    int p = gs_prune;
    float tval = gs_tval;
    {
        int row = idx >> 4, c4i = idx & 15;
        float4 v;
        if (p < MD && row == p) v = *reinterpret_cast<const float4*>(x + c4i*4);
        else v = *reinterpret_cast<const float4*>(dict + (size_t)row*DD + c4i*4);
        *reinterpret_cast<float4*>(out + OFF_DICT + (size_t)row*DD + c4i*4) = v;
    }
    if (idx < MD) {
        bool rowp = (p < MD) && (idx == p);
        float tn = rowp ? tval : TI[idx];
        out[OFF_TI + idx] = tn;
        float sf = sqrtf(FFC);
        float hi = g_h[idx];
#pragma unroll
        for (int yd = 0; yd < 4; yd++) {
            float val;
            if (tn < 0.f) val = 0.f;
            else if (rowp) val = gs_pm[yd] + gs_c[yd] * gs_npv;
            else val = sf * mu[yd*MD + idx] + gs_c[yd] * hi;
            out[OFF_MU + yd*MD + idx] = val;
        }
    }
}

extern "C" void kernel_launch(void* const* d_in, const int* in_sizes, int n_in,
                              void* d_out, int out_size) {
    const float* dict = (const float*)d_in[0];
    const float* mu   = (const float*)d_in[1];
    const float* sigma= (const float*)d_in[2];
    const float* Q    = (const float*)d_in[3];
    const float* x    = (const float*)d_in[4];
    const float* y    = (const float*)d_in[5];
    const float* nn   = (const float*)d_in[6];
    const float* nd   = (const float*)d_in[7];
    const float* ti   = (const float*)d_in[8];
    const int*   tptr = (const int*)d_in[9];
    float* out = (float*)d_out;

    static cudaStream_t s_aux = nullptr;
    static cudaEvent_t ev_fork1, ev_join1, ev_fork2, ev_join2;
    if (!s_aux) {
        cudaStreamCreateWithFlags(&s_aux, cudaStreamNonBlocking);
        cudaEventCreateWithFlags(&ev_fork1, cudaEventDisableTiming);
        cudaEventCreateWithFlags(&ev_join1, cudaEventDisableTiming);
        cudaEventCreateWithFlags(&ev_fork2, cudaEventDisableTiming);
        cudaEventCreateWithFlags(&ev_join2, cudaEventDisableTiming);
    }

    k_kdx<<<16, 256>>>(dict, x, ti);
    k_matvec5<<<512, 256>>>(Q, mu);

    // fork: scalars1 + sigma@q on aux stream, overlapped with the GEMM pass
    cudaEventRecord(ev_fork1, 0);
    cudaStreamWaitEvent(s_aux, ev_fork1, 0);
    k_scalars1<<<1, 256, 0, s_aux>>>(mu);
    k_sigq<<<512, 256, 0, s_aux>>>(sigma);
    k_pass1<<<528, 256>>>(dict);
    cudaEventRecord(ev_join1, s_aux);
    cudaStreamWaitEvent(0, ev_join1, 0);

    k_hred<<<16, 256>>>();
    k_hfin<<<1, 32>>>(y, nn, nd, out);
    k_qhcrit<<<512, 256>>>(Q);
    k_colpfin<<<16, 256>>>(Q, tptr);

    // fork: tail + Q_n on aux, sig_n on main — disjoint inputs/outputs
    cudaEventRecord(ev_fork2, 0);
    cudaStreamWaitEvent(s_aux, ev_fork2, 0);
    k_tail<<<256, 256, 0, s_aux>>>(mu, dict, x, ti, out);
    k_postQ<<<4096, 256, 0, s_aux>>>(Q, out);
    k_postS<<<4096, 256>>>(sigma, ti, out);
    cudaEventRecord(ev_join2, s_aux);
    cudaStreamWaitEvent(0, ev_join2, 0);
}

// round 13
// speedup vs baseline: 1.6292x; 1.0200x over previous
#include <cuda_runtime.h>
#include <cuda_bf16.h>
#include <cuda_fp16.h>
#include <math.h>

#define MD 4096
#define DD 64
#define NJB 32
#define FFC 0.999f
#define REGC 0.01f
#define JIT 1e-10f
#define INV2LS2 (1.0f/128.0f)

#define OFF_MU   ((size_t)0)
#define OFF_SIG  ((size_t)16384)
#define OFF_Q    (OFF_SIG + (size_t)MD*MD)
#define OFF_DICT (OFF_Q   + (size_t)MD*MD)
#define OFF_TI   (OFF_DICT + (size_t)MD*DD)
#define OFF_NN   (OFF_TI + MD)
#define OFF_ND   (OFF_NN + 4)

// -------- scratch (device globals; allocations forbidden) --------
static __device__ float g_kdx[MD], g_alloc[MD], g_norm[MD];
static __device__ float g_q[MD], g_h[MD], g_hsig[MD], g_Qmu[4*MD];
static __device__ float g_hpart[NJB*MD];
static __device__ float g_colp[MD];
static __device__ unsigned char g_kdd8[(size_t)MD*MD];   // 16.7 MB fp8(e4m3) Kdd cache
static __device__ float g_pval[512];
static __device__ int   g_pidx[512];
static __device__ float g_qhp[16];
static __device__ float gs_pu, gs_pm[4], gs_qh, gs_npv, gs_pv, gs_c[4];
static __device__ float gs_critM, gs_denom, gs_qp, gs_tval;
static __device__ int   gs_prune;

__device__ __forceinline__ unsigned pk_bf2(float a, float b) {
    __nv_bfloat162 h = __floats2bfloat162_rn(a, b);
    return *reinterpret_cast<unsigned*>(&h);
}

// pack two floats to e4m3x2: low byte = lo, high byte = hi
__device__ __forceinline__ unsigned short pk_fp8(float lo, float hi) {
    unsigned short r;
    asm("cvt.rn.satfinite.e4m3x2.f32 %0, %1, %2;" : "=h"(r) : "f"(hi), "f"(lo));
    return r;
}

// decode 4 packed e4m3 bytes -> 4 floats
__device__ __forceinline__ float4 fp8x4_to_f4(unsigned v) {
    unsigned short lo = (unsigned short)(v & 0xFFFFu);
    unsigned short hi = (unsigned short)(v >> 16);
    unsigned r0, r1;
    asm("cvt.rn.f16x2.e4m3x2 %0, %1;" : "=r"(r0) : "h"(lo));
    asm("cvt.rn.f16x2.e4m3x2 %0, %1;" : "=r"(r1) : "h"(hi));
    __half2 h0 = *reinterpret_cast<__half2*>(&r0);
    __half2 h1 = *reinterpret_cast<__half2*>(&r1);
    float2 f0 = __half22float2(h0);
    float2 f1 = __half22float2(h1);
    return make_float4(f0.x, f0.y, f1.x, f1.y);
}

__device__ __forceinline__ void mma16816(float* c, unsigned a0, unsigned a1,
                                         unsigned a2, unsigned a3,
                                         unsigned b0, unsigned b1) {
    asm volatile(
        "mma.sync.aligned.m16n8k16.row.col.f32.bf16.bf16.f32 "
        "{%0,%1,%2,%3},{%4,%5,%6,%7},{%8,%9},{%0,%1,%2,%3};\n"
        : "+f"(c[0]), "+f"(c[1]), "+f"(c[2]), "+f"(c[3])
        : "r"(a0), "r"(a1), "r"(a2), "r"(a3), "r"(b0), "r"(b1));
}

// -------- K_dx, alloc, row norms --------
__global__ void k_kdx(const float* __restrict__ dict, const float* __restrict__ x,
                      const float* __restrict__ ti) {
    __shared__ float xs[DD];
    int tid = threadIdx.x;
    if (tid < DD) xs[tid] = x[tid];
    __syncthreads();
    int i = blockIdx.x * 256 + tid;
    const float* dr = dict + (size_t)i * DD;
    float a2 = 0.f, ip = 0.f, x2 = 0.f;
#pragma unroll
    for (int k = 0; k < DD; k++) { float d = dr[k], xv = xs[k]; a2 += d*d; ip += d*xv; x2 += xv*xv; }
    float d2 = fmaxf(a2 + x2 - 2.0f*ip, 0.0f);
    float al = (ti[i] >= 0.0f) ? 1.0f : 0.0f;
    g_kdx[i] = __expf(-d2 * INV2LS2) * al;
    g_alloc[i] = al;
    g_norm[i] = a2;
}

// -------- q = Q@kdx, Qmu = sqrt(FF)*Q@mu (warp per row) --------
__global__ void k_matvec5(const float* __restrict__ Q, const float* __restrict__ mu) {
    int gw = (blockIdx.x * 256 + threadIdx.x) >> 5;
    int lane = threadIdx.x & 31;
    const float4* Qr = reinterpret_cast<const float4*>(Q) + (size_t)gw * (MD/4);
    const float4* K4 = reinterpret_cast<const float4*>(g_kdx);
    const float4* M4 = reinterpret_cast<const float4*>(mu);
    float s[5] = {0,0,0,0,0};
#pragma unroll 8
    for (int jb = lane; jb < MD/4; jb += 32) {
        float4 qv = Qr[jb], kv = K4[jb];
        s[0] += qv.x*kv.x + qv.y*kv.y + qv.z*kv.z + qv.w*kv.w;
#pragma unroll
        for (int yd = 0; yd < 4; yd++) {
            float4 mv = M4[yd*(MD/4) + jb];
            s[1+yd] += qv.x*mv.x + qv.y*mv.y + qv.z*mv.z + qv.w*mv.w;
        }
    }
#pragma unroll
    for (int o = 16; o > 0; o >>= 1)
#pragma unroll
        for (int r = 0; r < 5; r++) s[r] += __shfl_xor_sync(0xffffffffu, s[r], o);
    if (lane == 0) {
        g_q[gw] = s[0];
        float sf = sqrtf(FFC);
#pragma unroll
        for (int yd = 0; yd < 4; yd++) g_Qmu[yd*MD + gw] = sf * s[1+yd];
    }
}

// -------- scalars 1: pu, pred_mean --------
__global__ void k_scalars1(const float* __restrict__ mu) {
    __shared__ float red[5][8];
    int tid = threadIdx.x;
    float s[5] = {0,0,0,0,0};
    for (int i = tid; i < MD; i += 256) {
        float qi = g_q[i];
        s[0] += g_kdx[i] * qi;
#pragma unroll
        for (int yd = 0; yd < 4; yd++) s[1+yd] += qi * mu[yd*MD + i];
    }
#pragma unroll
    for (int o = 16; o > 0; o >>= 1)
#pragma unroll
        for (int r = 0; r < 5; r++) s[r] += __shfl_xor_sync(0xffffffffu, s[r], o);
    if ((tid & 31) == 0)
#pragma unroll
        for (int r = 0; r < 5; r++) red[r][tid >> 5] = s[r];
    __syncthreads();
    if (tid == 0) {
        float t[5];
#pragma unroll
        for (int r = 0; r < 5; r++) { t[r] = 0.f;
#pragma unroll
            for (int w = 0; w < 8; w++) t[r] += red[r][w]; }
        gs_pu = fmaxf((1.0f + JIT) - t[0], 0.0f);
        float sf = sqrtf(FFC);
#pragma unroll
        for (int yd = 0; yd < 4; yd++) gs_pm[yd] = sf * t[1+yd];
    }
}

// -------- hsig = sigma @ q (warp per row, streaming loads: keep Q in L2) --------
__global__ void k_sigq(const float* __restrict__ sigma) {
    int gw = (blockIdx.x * 256 + threadIdx.x) >> 5;
    int lane = threadIdx.x & 31;
    const float4* Sr = reinterpret_cast<const float4*>(sigma) + (size_t)gw * (MD/4);
    const float4* Q4 = reinterpret_cast<const float4*>(g_q);
    float s = 0.f;
#pragma unroll 8
    for (int jb = lane; jb < MD/4; jb += 32) {
        float4 sv = __ldcs(&Sr[jb]);
        float4 qv = Q4[jb];
        s += sv.x*qv.x + sv.y*qv.y + sv.z*qv.z + sv.w*qv.w;
    }
#pragma unroll
    for (int o = 16; o > 0; o >>= 1) s += __shfl_xor_sync(0xffffffffu, s, o);
    if (lane == 0) g_hsig[gw] = s;
}

// =================== Tensor-core Kdd GEMM machinery ====================
#define LDB36 36      // u32 row stride (72 bf16) for A/B tiles
#define KDLD 132      // bf16 row stride of the kd staging tile (64 x 128 used)

__device__ __forceinline__ void fill_tiles(unsigned* AsU, unsigned* BsU,
                                           const float* __restrict__ dict,
                                           int I0, int J0, int tid) {
    const float4* dI = reinterpret_cast<const float4*>(dict + (size_t)I0 * DD);
    const float4* dJ = reinterpret_cast<const float4*>(dict + (size_t)J0 * DD);
    for (int idx = tid; idx < 2048; idx += 256) {
        int r = idx >> 4, c4 = idx & 15;
        float4 v = dI[r*16 + c4];
        AsU[r*LDB36 + c4*2]     = pk_bf2(v.x, v.y);
        AsU[r*LDB36 + c4*2 + 1] = pk_bf2(v.z, v.w);
        float4 w = dJ[r*16 + c4];
        BsU[r*LDB36 + c4*2]     = pk_bf2(w.x, w.y);
        BsU[r*LDB36 + c4*2 + 1] = pk_bf2(w.z, w.w);
    }
}

__device__ __forceinline__ void gemm_tiles(const unsigned* AsU, const unsigned* BsU,
                                           float acc[4][4][4], int wm, int wn,
                                           int g, int t) {
#pragma unroll
    for (int ks = 0; ks < 4; ks++) {
        unsigned bf[4][2];
#pragma unroll
        for (int n = 0; n < 4; n++) {
            int rb = wn*32 + n*8 + g;
            bf[n][0] = BsU[rb*LDB36 + ks*8 + t];
            bf[n][1] = BsU[rb*LDB36 + ks*8 + t + 4];
        }
#pragma unroll
        for (int m = 0; m < 4; m++) {
            int ra = wm*64 + m*16 + g;
            unsigned a0 = AsU[ra*LDB36 + ks*8 + t];
            unsigned a1 = AsU[(ra+8)*LDB36 + ks*8 + t];
            unsigned a2 = AsU[ra*LDB36 + ks*8 + t + 4];
            unsigned a3 = AsU[(ra+8)*LDB36 + ks*8 + t + 4];
#pragma unroll
            for (int n = 0; n < 4; n++)
                mma16816(acc[m][n], a0, a1, a2, a3, bf[n][0], bf[n][1]);
        }
    }
}

// ---- pass 1 (triangular): kd tiles (a,b)+(b,a) in fp8, deterministic h partials
__global__ void __launch_bounds__(256, 2) k_pass1(const float* __restrict__ dict) {
    __shared__ __align__(16) char raw[128*LDB36*4*2];   // A/B tiles; then kd stage
    __shared__ float qs[128], qI[128], nIv[128], nJv[128], aIv[128], aJv[128];

    unsigned* AsU = reinterpret_cast<unsigned*>(raw);
    unsigned* BsU = AsU + 128*LDB36;
    __nv_bfloat16* kdS = reinterpret_cast<__nv_bfloat16*>(raw);  // 64 x KDLD bf16

    int tid = threadIdx.x;
    int lane = tid & 31, w = tid >> 5;
    int g = lane >> 2, t = lane & 3;
    int wm = w >> 2, wn = w & 3;

    // triangular decode: block -> (a, b), a <= b
    int a = 0, rem = blockIdx.x;
    while (rem >= 32 - a) { rem -= 32 - a; a++; }
    int b = a + rem;
    int I0 = a * 128, J0 = b * 128;
    bool offdiag = (a != b);

    fill_tiles(AsU, BsU, dict, I0, J0, tid);
    if (tid < 128) {
        qs[tid]  = g_q[J0 + tid];
        qI[tid]  = g_q[I0 + tid];
        nJv[tid] = g_norm[J0 + tid]; aJv[tid] = g_alloc[J0 + tid];
        nIv[tid] = g_norm[I0 + tid]; aIv[tid] = g_alloc[I0 + tid];
    }
    __syncthreads();

    float acc[4][4][4];
#pragma unroll
    for (int m = 0; m < 4; m++)
#pragma unroll
        for (int n = 0; n < 4; n++)
#pragma unroll
            for (int r = 0; r < 4; r++) acc[m][n][r] = 0.f;

    gemm_tiles(AsU, BsU, acc, wm, wn, g, t);

    float colsum = 0.f;    // transposed (column) partial, accumulated across halves

#pragma unroll
    for (int half = 0; half < 2; half++) {
        __syncthreads();   // protect kdS overwrite (A/B dead after gemm)
        if (wm == half) {
#pragma unroll
            for (int m = 0; m < 4; m++)
#pragma unroll
                for (int n = 0; n < 4; n++)
#pragma unroll
                    for (int hf = 0; hf < 2; hf++) {
                        int rl = m*16 + g + 8*hf;
                        int cl = wn*32 + n*8 + 2*t;
                        float ni = nIv[half*64 + rl], ai = aIv[half*64 + rl];
                        float c0v = acc[m][n][2*hf], c1v = acc[m][n][2*hf+1];
                        float d0 = fmaxf(ni + nJv[cl]   - 2.0f*c0v, 0.0f);
                        float d1 = fmaxf(ni + nJv[cl+1] - 2.0f*c1v, 0.0f);
                        float k0 = __expf(-d0*INV2LS2) * ai * aJv[cl];
                        float k1 = __expf(-d1*INV2LS2) * ai * aJv[cl+1];
                        *reinterpret_cast<unsigned*>(&kdS[rl*KDLD + cl]) = pk_bf2(k0, k1);
                    }
        }
        __syncthreads();

        // normal orientation: rows of I (this half) -> tile (a,b); row partials
#pragma unroll
        for (int r8 = 0; r8 < 8; r8++) {
            int r  = r8*8 + w;
            int ig = I0 + half*64 + r;
            uint2 kp = *reinterpret_cast<const uint2*>(&kdS[r*KDLD + lane*4]);
            float2 k01 = __bfloat1622float2(*reinterpret_cast<const __nv_bfloat162*>(&kp.x));
            float2 k23 = __bfloat1622float2(*reinterpret_cast<const __nv_bfloat162*>(&kp.y));
            int c0 = lane*4;
            float hsum = k01.x*qs[c0] + k01.y*qs[c0+1] + k23.x*qs[c0+2] + k23.y*qs[c0+3];
            unsigned short s0 = pk_fp8(k01.x, k01.y);
            unsigned short s1 = pk_fp8(k23.x, k23.y);
            unsigned word = (unsigned)s0 | ((unsigned)s1 << 16);
            __stcs(reinterpret_cast<unsigned*>(g_kdd8 + (size_t)ig*MD + J0 + c0), word);
#pragma unroll
            for (int o = 16; o > 0; o >>= 1)
                hsum += __shfl_xor_sync(0xffffffffu, hsum, o);
            if (lane == 0) g_hpart[(size_t)b*MD + ig] = hsum;
        }

        // transposed orientation: rows of J -> tile (b,a); column partials
        if (offdiag) {
            int jr = tid >> 1, chunk = tid & 1;
            unsigned short sh[16];
#pragma unroll
            for (int ii = 0; ii < 16; ii++) {
                int i0 = chunk*32 + 2*ii;
                __nv_bfloat16 v0 = kdS[i0*KDLD + jr];
                __nv_bfloat16 v1 = kdS[(i0+1)*KDLD + jr];
                float f0 = __bfloat162float(v0), f1 = __bfloat162float(v1);
                sh[ii] = pk_fp8(f0, f1);
                colsum += f0 * qI[half*64 + i0] + f1 * qI[half*64 + i0 + 1];
            }
            unsigned wrd[8];
#pragma unroll
            for (int k2 = 0; k2 < 8; k2++)
                wrd[k2] = (unsigned)sh[2*k2] | ((unsigned)sh[2*k2+1] << 16);
            unsigned char* dst = g_kdd8 + (size_t)(J0+jr)*MD + I0 + half*64 + chunk*32;
            uint4* d4 = reinterpret_cast<uint4*>(dst);
            __stcs(&d4[0], make_uint4(wrd[0], wrd[1], wrd[2], wrd[3]));
            __stcs(&d4[1], make_uint4(wrd[4], wrd[5], wrd[6], wrd[7]));
        }
    }

    if (offdiag) {
        float other = __shfl_xor_sync(0xffffffffu, colsum, 1);
        if ((tid & 1) == 0) {
            int jr = tid >> 1;
            g_hpart[(size_t)a*MD + J0 + jr] = colsum + other;
        }
    }
}

// -------- h reduce (parallel): h = FF*hsig + (1-FF)*sum(hpart), qh partials ----
__global__ void k_hred() {
    __shared__ float red[8];
    int tid = threadIdx.x;
    int i = blockIdx.x * 256 + tid;
    float s = 0.f;
#pragma unroll
    for (int b = 0; b < NJB; b++) s += g_hpart[(size_t)b*MD + i];
    float h = FFC * g_hsig[i] + (1.0f - FFC) * s;
    g_h[i] = h;
    float qh_p = g_q[i] * h;
#pragma unroll
    for (int o = 16; o > 0; o >>= 1) qh_p += __shfl_xor_sync(0xffffffffu, qh_p, o);
    if ((tid & 31) == 0) red[tid >> 5] = qh_p;
    __syncthreads();
    if (tid == 0) {
        float t = 0.f;
#pragma unroll
        for (int w2 = 0; w2 < 8; w2++) t += red[w2];
        g_qhp[blockIdx.x] = t;
    }
}

// -------- Qh = Q@h + criterion + per-block argmin; scalars fused --------
__global__ void k_qhcrit(const float* __restrict__ Q, const float* __restrict__ y,
                         const float* __restrict__ nn, const float* __restrict__ nd,
                         float* __restrict__ out) {
    __shared__ float sv[8]; __shared__ int si[8];
    int tid = threadIdx.x;
    int gw = (blockIdx.x * 256 + tid) >> 5;
    int lane = tid & 31;

    // recompute qh + derived scalars locally (deterministic, identical per block)
    float qh = 0.f;
#pragma unroll
    for (int b2 = 0; b2 < 16; b2++) qh += g_qhp[b2];
    float pu = gs_pu;
    float npv = fmaxf(pu + qh, 0.0f);
    float pv = REGC + npv;

    const float4* Qr = reinterpret_cast<const float4*>(Q) + (size_t)gw * (MD/4);
    const float4* H4 = reinterpret_cast<const float4*>(g_h);
    float s = 0.f;
#pragma unroll 8
    for (int jb = lane; jb < MD/4; jb += 32) {
        float4 qv = Qr[jb], hv = H4[jb];
        s += qv.x*hv.x + qv.y*hv.y + qv.z*hv.z + qv.w*hv.w;
    }
#pragma unroll
    for (int o = 16; o > 0; o >>= 1) s += __shfl_xor_sync(0xffffffffu, s, o);
    if (lane == 0) {
        float cv;
        if (pu < JIT) {
            cv = 0.f;
        } else {
            float qi = g_q[gw];
            float dq = (g_alloc[gw] != 0.f) ? (Q[(size_t)gw*MD + gw] + qi*qi/pu)
                                            : __int_as_float(0x7f800000);
            float r = qi / pu;
            float qhm = qh - npv;
            float acc2 = 0.f;
#pragma unroll
            for (int yd = 0; yd < 4; yd++) {
                float c = (y[yd] - gs_pm[yd]) / pv;
                float num = g_Qmu[yd*MD + gw] + c*s + r*c*qhm;
                acc2 += fabsf(num / dq);
            }
            cv = acc2;
        }
        sv[tid >> 5] = cv; si[tid >> 5] = gw;
    }
    __syncthreads();
    if (tid == 0) {
        float bv = sv[0]; int bi = si[0];
#pragma unroll
        for (int w2 = 1; w2 < 8; w2++) {
            if (sv[w2] < bv || (sv[w2] == bv && si[w2] < bi)) { bv = sv[w2]; bi = si[w2]; }
        }
        g_pval[blockIdx.x] = bv; g_pidx[blockIdx.x] = bi;
    }
    // block 0 publishes the scalars + small outputs (consumed by later kernels)
    if (blockIdx.x == 0 && tid == 0) {
        gs_qh = qh; gs_npv = npv; gs_pv = pv;
        float cm = 0.f;
#pragma unroll
        for (int yd = 0; yd < 4; yd++) {
            float dy = y[yd] - gs_pm[yd];
            float c = dy / pv;
            gs_c[yd] = c;
            out[OFF_NN + yd] = nn[yd] + FFC * dy * dy / pv;
            cm += fabsf(c * (npv - qh));
        }
        out[OFF_ND] = nd[0] + FFC;
        gs_critM = cm;
    }
}

// -------- merged argmin + prune scalars + column copy --------
__global__ void k_colpfin(const float* __restrict__ Q, const int* __restrict__ tptr) {
    __shared__ float sv[256]; __shared__ int si[256];
    int tid = threadIdx.x;
    float v0 = g_pval[tid], v1 = g_pval[tid + 256];
    int   i0 = g_pidx[tid], i1 = g_pidx[tid + 256];
    float bv; int bi;
    if (v1 < v0 || (v1 == v0 && i1 < i0)) { bv = v1; bi = i1; } else { bv = v0; bi = i0; }
    sv[tid] = bv; si[tid] = bi;
    __syncthreads();
    for (int st = 128; st > 0; st >>= 1) {
        if (tid < st) {
            if (sv[tid+st] < sv[tid] || (sv[tid+st] == sv[tid] && si[tid+st] < si[tid])) {
                sv[tid] = sv[tid+st]; si[tid] = si[tid+st];
            }
        }
        __syncthreads();
    }
    float pu = gs_pu;
    int p;
    if (pu < JIT) p = MD;
    else { p = si[0]; if (gs_critM < sv[0]) p = MD; }

    int i = blockIdx.x * 256 + tid;
    g_colp[i] = (p < MD) ? Q[(size_t)i*MD + p] : 0.0f;

    if (blockIdx.x == 0 && tid == 0) {
        gs_prune = p;
        float qp = (p < MD) ? g_q[p] : 0.0f;
        gs_qp = qp;
        bool xal = (p == MD) ? true : (g_alloc[p] != 0.f);
        float qaa = (p == MD) ? (1.0f/pu) : (Q[(size_t)p*MD + p] + qp*qp/pu);
        gs_denom = xal ? qaa : __int_as_float(0x7f800000);
        int bits = tptr[0];
        gs_tval = (bits >= 0 && bits < (1 << 26)) ? (float)bits : __int_as_float(bits);
    }
}

// -------- Q_n writer (row per block) --------
__device__ __forceinline__ float qn_elem(int p, bool rowp, int j, float Qij,
                                         float qi, float qj, float colj,
                                         float qp, float ipu, float Bi, float dinv) {
    float m, Bj;
    if (p < MD) {
        if (rowp) m = (j == p) ? ipu : (-qj * ipu);
        else      m = (j == p) ? (-qi * ipu) : (Qij + qi*qj*ipu);
        Bj = (j == p) ? (-qp * ipu) : (colj + qj*qp*ipu);
    } else {
        m  = Qij + qi*qj*ipu;
        Bj = -qj * ipu;
    }
    return m - Bi * Bj * dinv;
}

__global__ void k_postQ(const float* __restrict__ Q, float* __restrict__ out) {
    int i = blockIdx.x;
    int tid = threadIdx.x;
    int p = gs_prune;
    float pu = gs_pu, qp = gs_qp, qi = g_q[i];
    float ipu = 1.0f / pu;
    float dinv = 1.0f / gs_denom;
    bool rowp = (p < MD) && (i == p);
    float Bi = (p < MD) ? (rowp ? (-qp*ipu) : (g_colp[i] + qi*qp*ipu)) : (-qi*ipu);

    const float4* Qr = reinterpret_cast<const float4*>(Q + (size_t)i*MD);
    float4* oq = reinterpret_cast<float4*>(out + OFF_Q + (size_t)i*MD);
    const float4* q4 = reinterpret_cast<const float4*>(g_q);
    const float4* c4 = reinterpret_cast<const float4*>(g_colp);

    for (int jb = tid; jb < MD/4; jb += 256) {
        float4 Qv = Qr[jb];
        float4 qq = q4[jb]; float4 cc = c4[jb];
        int j0 = jb * 4;
        float4 oqv;
        oqv.x = qn_elem(p, rowp, j0+0, Qv.x, qi, qq.x, cc.x, qp, ipu, Bi, dinv);
        oqv.y = qn_elem(p, rowp, j0+1, Qv.y, qi, qq.y, cc.y, qp, ipu, Bi, dinv);
        oqv.z = qn_elem(p, rowp, j0+2, Qv.z, qi, qq.z, cc.z, qp, ipu, Bi, dinv);
        oqv.w = qn_elem(p, rowp, j0+3, Qv.w, qi, qq.w, cc.w, qp, ipu, Bi, dinv);
        __stcs(&oq[jb], oqv);
    }
}

// -------- sig_n writer (row per block) --------
__global__ void k_postS(const float* __restrict__ sigma, const float* __restrict__ TI,
                        float* __restrict__ out) {
    int i = blockIdx.x;
    int tid = threadIdx.x;
    int p = gs_prune;
    float npv = gs_npv, ivp = 1.0f / gs_pv, tval = gs_tval;
    bool rowp = (p < MD) && (i == p);
    float hi = g_h[i];
    float tni = rowp ? tval : TI[i];
    float mi = (tni >= 0.f) ? 1.f : 0.f;
    float ppi = rowp ? npv : hi;

    const float4* Sr = reinterpret_cast<const float4*>(sigma + (size_t)i*MD);
    const unsigned* Kr = reinterpret_cast<const unsigned*>(g_kdd8 + (size_t)i*MD);
    float4* os = reinterpret_cast<float4*>(out + OFF_SIG + (size_t)i*MD);
    const float4* h4 = reinterpret_cast<const float4*>(g_h);
    const float4* t4 = reinterpret_cast<const float4*>(TI);

    for (int jb = tid; jb < MD/4; jb += 256) {
        float4 sg = __ldcs(&Sr[jb]);
        unsigned kp = __ldcs(&Kr[jb]);
        float4 hh = h4[jb]; float4 tt = t4[jb];
        int j0 = jb * 4;

        float4 kf = fp8x4_to_f4(kp);
        float kdf[4] = {kf.x, kf.y, kf.z, kf.w};
        float svv[4] = {sg.x, sg.y, sg.z, sg.w};
        float hvv[4] = {hh.x, hh.y, hh.z, hh.w};
        float tvv[4] = {tt.x, tt.y, tt.z, tt.w};
        float ov[4];
#pragma unroll
        for (int c = 0; c < 4; c++) {
            int j = j0 + c;
            float spre = FFC*svv[c] + (1.0f-FFC)*kdf[c];
            bool colp = (p < MD) && (j == p);
            float tj = colp ? tval : tvv[c];
            float mj = (tj >= 0.f) ? 1.f : 0.f;
            float ms  = rowp ? (colp ? npv : hvv[c]) : (colp ? hi : spre);
            float ppj = colp ? npv : hvv[c];
            ov[c] = mi * mj * (ms - ppi * ppj * ivp);
        }
        float4 osv; osv.x=ov[0]; osv.y=ov[1]; osv.z=ov[2]; osv.w=ov[3];
        __stcs(&os[jb], osv);
    }
}

// -------- tail: mu_n, dict_n, ti_n --------
__global__ void k_tail(const float* __restrict__ mu, const float* __restrict__ dict,
                       const float* __restrict__ x, const float* __restrict__ TI,
                       float* __restrict__ out) {
    int idx = blockIdx.x * 256 + threadIdx.x;   // 65536 threads
    int p = gs_prune;
    float tval = gs_tval;
    {
        int row = idx >> 4, c4i = idx & 15;
        float4 v;
        if (p < MD && row == p) v = *reinterpret_cast<const float4*>(x + c4i*4);
        else v = *reinterpret_cast<const float4*>(dict + (size_t)row*DD + c4i*4);
        *reinterpret_cast<float4*>(out + OFF_DICT + (size_t)row*DD + c4i*4) = v;
    }
    if (idx < MD) {
        bool rowp = (p < MD) && (idx == p);
        float tn = rowp ? tval : TI[idx];
        out[OFF_TI + idx] = tn;
        float sf = sqrtf(FFC);
        float hi = g_h[idx];
#pragma unroll
        for (int yd = 0; yd < 4; yd++) {
            float val;
            if (tn < 0.f) val = 0.f;
            else if (rowp) val = gs_pm[yd] + gs_c[yd] * gs_npv;
            else val = sf * mu[yd*MD + idx] + gs_c[yd] * hi;
            out[OFF_MU + yd*MD + idx] = val;
        }
    }
}

extern "C" void kernel_launch(void* const* d_in, const int* in_sizes, int n_in,
                              void* d_out, int out_size) {
    const float* dict = (const float*)d_in[0];
    const float* mu   = (const float*)d_in[1];
    const float* sigma= (const float*)d_in[2];
    const float* Q    = (const float*)d_in[3];
    const float* x    = (const float*)d_in[4];
    const float* y    = (const float*)d_in[5];
    const float* nn   = (const float*)d_in[6];
    const float* nd   = (const float*)d_in[7];
    const float* ti   = (const float*)d_in[8];
    const int*   tptr = (const int*)d_in[9];
    float* out = (float*)d_out;

    static cudaStream_t s_aux = nullptr;
    static cudaEvent_t ev_fork1, ev_join1, ev_fork2, ev_join2;
    if (!s_aux) {
        cudaStreamCreateWithFlags(&s_aux, cudaStreamNonBlocking);
        cudaEventCreateWithFlags(&ev_fork1, cudaEventDisableTiming);
        cudaEventCreateWithFlags(&ev_join1, cudaEventDisableTiming);
        cudaEventCreateWithFlags(&ev_fork2, cudaEventDisableTiming);
        cudaEventCreateWithFlags(&ev_join2, cudaEventDisableTiming);
    }

    k_kdx<<<16, 256>>>(dict, x, ti);
    k_matvec5<<<512, 256>>>(Q, mu);

    // fork: scalars1 + sigma@q on aux stream, overlapped with the GEMM pass
    cudaEventRecord(ev_fork1, 0);
    cudaStreamWaitEvent(s_aux, ev_fork1, 0);
    k_scalars1<<<1, 256, 0, s_aux>>>(mu);
    k_sigq<<<512, 256, 0, s_aux>>>(sigma);
    k_pass1<<<528, 256>>>(dict);
    cudaEventRecord(ev_join1, s_aux);
    cudaStreamWaitEvent(0, ev_join1, 0);

    k_hred<<<16, 256>>>();
    k_qhcrit<<<512, 256>>>(Q, y, nn, nd, out);
    k_colpfin<<<16, 256>>>(Q, tptr);

    // fork: tail + Q_n on aux, sig_n on main — disjoint inputs/outputs
    cudaEventRecord(ev_fork2, 0);
    cudaStreamWaitEvent(s_aux, ev_fork2, 0);
    k_tail<<<256, 256, 0, s_aux>>>(mu, dict, x, ti, out);
    k_postQ<<<4096, 256, 0, s_aux>>>(Q, out);
    k_postS<<<4096, 256>>>(sigma, ti, out);
    cudaEventRecord(ev_join2, s_aux);
    cudaStreamWaitEvent(0, ev_join2, 0);
}

// round 14
// speedup vs baseline: 1.7971x; 1.1031x over previous
#include <cuda_runtime.h>
#include <cuda_bf16.h>
#include <cuda_fp16.h>
#include <math.h>

#define MD 4096
#define DD 64
#define NJB 32
#define FFC 0.999f
#define REGC 0.01f
#define JIT 1e-10f
#define INV2LS2 (1.0f/128.0f)

#define OFF_MU   ((size_t)0)
#define OFF_SIG  ((size_t)16384)
#define OFF_Q    (OFF_SIG + (size_t)MD*MD)
#define OFF_DICT (OFF_Q   + (size_t)MD*MD)
#define OFF_TI   (OFF_DICT + (size_t)MD*DD)
#define OFF_NN   (OFF_TI + MD)
#define OFF_ND   (OFF_NN + 4)

// -------- scratch (device globals; allocations forbidden) --------
static __device__ float g_kdx[MD], g_alloc[MD], g_norm[MD];
static __device__ float g_q[MD], g_h[MD], g_hsig[MD], g_Qmu[4*MD];
static __device__ float g_hpart[NJB*MD];
static __device__ float g_colp[MD];
static __device__ unsigned char g_kdd8[(size_t)MD*MD];   // 16.7 MB fp8(e4m3) Kdd cache
static __device__ float g_pval[512];
static __device__ int   g_pidx[512];
static __device__ float g_qhp[16];
static __device__ float gs_pu, gs_pm[4], gs_qh, gs_npv, gs_pv, gs_c[4];
static __device__ float gs_critM, gs_denom, gs_qp, gs_tval;
static __device__ int   gs_prune;

__device__ __forceinline__ unsigned pk_bf2(float a, float b) {
    __nv_bfloat162 h = __floats2bfloat162_rn(a, b);
    return *reinterpret_cast<unsigned*>(&h);
}

__device__ __forceinline__ unsigned short pk_fp8(float lo, float hi) {
    unsigned short r;
    asm("cvt.rn.satfinite.e4m3x2.f32 %0, %1, %2;" : "=h"(r) : "f"(hi), "f"(lo));
    return r;
}

__device__ __forceinline__ float4 fp8x4_to_f4(unsigned v) {
    unsigned short lo = (unsigned short)(v & 0xFFFFu);
    unsigned short hi = (unsigned short)(v >> 16);
    unsigned r0, r1;
    asm("cvt.rn.f16x2.e4m3x2 %0, %1;" : "=r"(r0) : "h"(lo));
    asm("cvt.rn.f16x2.e4m3x2 %0, %1;" : "=r"(r1) : "h"(hi));
    __half2 h0 = *reinterpret_cast<__half2*>(&r0);
    __half2 h1 = *reinterpret_cast<__half2*>(&r1);
    float2 f0 = __half22float2(h0);
    float2 f1 = __half22float2(h1);
    return make_float4(f0.x, f0.y, f1.x, f1.y);
}

__device__ __forceinline__ void mma16816(float* c, unsigned a0, unsigned a1,
                                         unsigned a2, unsigned a3,
                                         unsigned b0, unsigned b1) {
    asm volatile(
        "mma.sync.aligned.m16n8k16.row.col.f32.bf16.bf16.f32 "
        "{%0,%1,%2,%3},{%4,%5,%6,%7},{%8,%9},{%0,%1,%2,%3};\n"
        : "+f"(c[0]), "+f"(c[1]), "+f"(c[2]), "+f"(c[3])
        : "r"(a0), "r"(a1), "r"(a2), "r"(a3), "r"(b0), "r"(b1));
}

// -------- K_dx, alloc, row norms --------
__global__ void k_kdx(const float* __restrict__ dict, const float* __restrict__ x,
                      const float* __restrict__ ti) {
    __shared__ float xs[DD];
    int tid = threadIdx.x;
    if (tid < DD) xs[tid] = x[tid];
    __syncthreads();
    int i = blockIdx.x * 256 + tid;
    const float* dr = dict + (size_t)i * DD;
    float a2 = 0.f, ip = 0.f, x2 = 0.f;
#pragma unroll
    for (int k = 0; k < DD; k++) { float d = dr[k], xv = xs[k]; a2 += d*d; ip += d*xv; x2 += xv*xv; }
    float d2 = fmaxf(a2 + x2 - 2.0f*ip, 0.0f);
    float al = (ti[i] >= 0.0f) ? 1.0f : 0.0f;
    g_kdx[i] = __expf(-d2 * INV2LS2) * al;
    g_alloc[i] = al;
    g_norm[i] = a2;
}

// -------- q = Q@kdx, Qmu = sqrt(FF)*Q@mu (warp per row) --------
__global__ void k_matvec5(const float* __restrict__ Q, const float* __restrict__ mu) {
    int gw = (blockIdx.x * 256 + threadIdx.x) >> 5;
    int lane = threadIdx.x & 31;
    const float4* Qr = reinterpret_cast<const float4*>(Q) + (size_t)gw * (MD/4);
    const float4* K4 = reinterpret_cast<const float4*>(g_kdx);
    const float4* M4 = reinterpret_cast<const float4*>(mu);
    float s[5] = {0,0,0,0,0};
#pragma unroll 8
    for (int jb = lane; jb < MD/4; jb += 32) {
        float4 qv = Qr[jb], kv = K4[jb];
        s[0] += qv.x*kv.x + qv.y*kv.y + qv.z*kv.z + qv.w*kv.w;
#pragma unroll
        for (int yd = 0; yd < 4; yd++) {
            float4 mv = M4[yd*(MD/4) + jb];
            s[1+yd] += qv.x*mv.x + qv.y*mv.y + qv.z*mv.z + qv.w*mv.w;
        }
    }
#pragma unroll
    for (int o = 16; o > 0; o >>= 1)
#pragma unroll
        for (int r = 0; r < 5; r++) s[r] += __shfl_xor_sync(0xffffffffu, s[r], o);
    if (lane == 0) {
        g_q[gw] = s[0];
        float sf = sqrtf(FFC);
#pragma unroll
        for (int yd = 0; yd < 4; yd++) g_Qmu[yd*MD + gw] = sf * s[1+yd];
    }
}

// -------- scalars 1: pu, pred_mean --------
__global__ void k_scalars1(const float* __restrict__ mu) {
    __shared__ float red[5][8];
    int tid = threadIdx.x;
    float s[5] = {0,0,0,0,0};
    for (int i = tid; i < MD; i += 256) {
        float qi = g_q[i];
        s[0] += g_kdx[i] * qi;
#pragma unroll
        for (int yd = 0; yd < 4; yd++) s[1+yd] += qi * mu[yd*MD + i];
    }
#pragma unroll
    for (int o = 16; o > 0; o >>= 1)
#pragma unroll
        for (int r = 0; r < 5; r++) s[r] += __shfl_xor_sync(0xffffffffu, s[r], o);
    if ((tid & 31) == 0)
#pragma unroll
        for (int r = 0; r < 5; r++) red[r][tid >> 5] = s[r];
    __syncthreads();
    if (tid == 0) {
        float t[5];
#pragma unroll
        for (int r = 0; r < 5; r++) { t[r] = 0.f;
#pragma unroll
            for (int w = 0; w < 8; w++) t[r] += red[r][w]; }
        gs_pu = fmaxf((1.0f + JIT) - t[0], 0.0f);
        float sf = sqrtf(FFC);
#pragma unroll
        for (int yd = 0; yd < 4; yd++) gs_pm[yd] = sf * t[1+yd];
    }
}

// -------- hsig = sigma @ q (warp per row, streaming loads: keep Q in L2) --------
__global__ void k_sigq(const float* __restrict__ sigma) {
    int gw = (blockIdx.x * 256 + threadIdx.x) >> 5;
    int lane = threadIdx.x & 31;
    const float4* Sr = reinterpret_cast<const float4*>(sigma) + (size_t)gw * (MD/4);
    const float4* Q4 = reinterpret_cast<const float4*>(g_q);
    float s = 0.f;
#pragma unroll 8
    for (int jb = lane; jb < MD/4; jb += 32) {
        float4 sv = __ldcs(&Sr[jb]);
        float4 qv = Q4[jb];
        s += sv.x*qv.x + sv.y*qv.y + sv.z*qv.z + sv.w*qv.w;
    }
#pragma unroll
    for (int o = 16; o > 0; o >>= 1) s += __shfl_xor_sync(0xffffffffu, s, o);
    if (lane == 0) g_hsig[gw] = s;
}

// =================== Tensor-core Kdd GEMM machinery ====================
#define LDB36 36
#define KDLD 132

__device__ __forceinline__ void fill_tiles(unsigned* AsU, unsigned* BsU,
                                           const float* __restrict__ dict,
                                           int I0, int J0, int tid) {
    const float4* dI = reinterpret_cast<const float4*>(dict + (size_t)I0 * DD);
    const float4* dJ = reinterpret_cast<const float4*>(dict + (size_t)J0 * DD);
    for (int idx = tid; idx < 2048; idx += 256) {
        int r = idx >> 4, c4 = idx & 15;
        float4 v = dI[r*16 + c4];
        AsU[r*LDB36 + c4*2]     = pk_bf2(v.x, v.y);
        AsU[r*LDB36 + c4*2 + 1] = pk_bf2(v.z, v.w);
        float4 w = dJ[r*16 + c4];
        BsU[r*LDB36 + c4*2]     = pk_bf2(w.x, w.y);
        BsU[r*LDB36 + c4*2 + 1] = pk_bf2(w.z, w.w);
    }
}

__device__ __forceinline__ void gemm_tiles(const unsigned* AsU, const unsigned* BsU,
                                           float acc[4][4][4], int wm, int wn,
                                           int g, int t) {
#pragma unroll
    for (int ks = 0; ks < 4; ks++) {
        unsigned bf[4][2];
#pragma unroll
        for (int n = 0; n < 4; n++) {
            int rb = wn*32 + n*8 + g;
            bf[n][0] = BsU[rb*LDB36 + ks*8 + t];
            bf[n][1] = BsU[rb*LDB36 + ks*8 + t + 4];
        }
#pragma unroll
        for (int m = 0; m < 4; m++) {
            int ra = wm*64 + m*16 + g;
            unsigned a0 = AsU[ra*LDB36 + ks*8 + t];
            unsigned a1 = AsU[(ra+8)*LDB36 + ks*8 + t];
            unsigned a2 = AsU[ra*LDB36 + ks*8 + t + 4];
            unsigned a3 = AsU[(ra+8)*LDB36 + ks*8 + t + 4];
#pragma unroll
            for (int n = 0; n < 4; n++)
                mma16816(acc[m][n], a0, a1, a2, a3, bf[n][0], bf[n][1]);
        }
    }
}

// ---- pass 1 (triangular): kd tiles (a,b)+(b,a) in fp8, deterministic h partials
__global__ void __launch_bounds__(256, 2) k_pass1(const float* __restrict__ dict) {
    __shared__ __align__(16) char raw[128*LDB36*4*2];
    __shared__ float qs[128], qI[128], nIv[128], nJv[128], aIv[128], aJv[128];

    unsigned* AsU = reinterpret_cast<unsigned*>(raw);
    unsigned* BsU = AsU + 128*LDB36;
    __nv_bfloat16* kdS = reinterpret_cast<__nv_bfloat16*>(raw);

    int tid = threadIdx.x;
    int lane = tid & 31, w = tid >> 5;
    int g = lane >> 2, t = lane & 3;
    int wm = w >> 2, wn = w & 3;

    int a = 0, rem = blockIdx.x;
    while (rem >= 32 - a) { rem -= 32 - a; a++; }
    int b = a + rem;
    int I0 = a * 128, J0 = b * 128;
    bool offdiag = (a != b);

    fill_tiles(AsU, BsU, dict, I0, J0, tid);
    if (tid < 128) {
        qs[tid]  = g_q[J0 + tid];
        qI[tid]  = g_q[I0 + tid];
        nJv[tid] = g_norm[J0 + tid]; aJv[tid] = g_alloc[J0 + tid];
        nIv[tid] = g_norm[I0 + tid]; aIv[tid] = g_alloc[I0 + tid];
    }
    __syncthreads();

    float acc[4][4][4];
#pragma unroll
    for (int m = 0; m < 4; m++)
#pragma unroll
        for (int n = 0; n < 4; n++)
#pragma unroll
            for (int r = 0; r < 4; r++) acc[m][n][r] = 0.f;

    gemm_tiles(AsU, BsU, acc, wm, wn, g, t);

    float colsum = 0.f;

#pragma unroll
    for (int half = 0; half < 2; half++) {
        __syncthreads();
        if (wm == half) {
#pragma unroll
            for (int m = 0; m < 4; m++)
#pragma unroll
                for (int n = 0; n < 4; n++)
#pragma unroll
                    for (int hf = 0; hf < 2; hf++) {
                        int rl = m*16 + g + 8*hf;
                        int cl = wn*32 + n*8 + 2*t;
                        float ni = nIv[half*64 + rl], ai = aIv[half*64 + rl];
                        float c0v = acc[m][n][2*hf], c1v = acc[m][n][2*hf+1];
                        float d0 = fmaxf(ni + nJv[cl]   - 2.0f*c0v, 0.0f);
                        float d1 = fmaxf(ni + nJv[cl+1] - 2.0f*c1v, 0.0f);
                        float k0 = __expf(-d0*INV2LS2) * ai * aJv[cl];
                        float k1 = __expf(-d1*INV2LS2) * ai * aJv[cl+1];
                        *reinterpret_cast<unsigned*>(&kdS[rl*KDLD + cl]) = pk_bf2(k0, k1);
                    }
        }
        __syncthreads();

#pragma unroll
        for (int r8 = 0; r8 < 8; r8++) {
            int r  = r8*8 + w;
            int ig = I0 + half*64 + r;
            uint2 kp = *reinterpret_cast<const uint2*>(&kdS[r*KDLD + lane*4]);
            float2 k01 = __bfloat1622float2(*reinterpret_cast<const __nv_bfloat162*>(&kp.x));
            float2 k23 = __bfloat1622float2(*reinterpret_cast<const __nv_bfloat162*>(&kp.y));
            int c0 = lane*4;
            float hsum = k01.x*qs[c0] + k01.y*qs[c0+1] + k23.x*qs[c0+2] + k23.y*qs[c0+3];
            unsigned short s0 = pk_fp8(k01.x, k01.y);
            unsigned short s1 = pk_fp8(k23.x, k23.y);
            unsigned word = (unsigned)s0 | ((unsigned)s1 << 16);
            __stcs(reinterpret_cast<unsigned*>(g_kdd8 + (size_t)ig*MD + J0 + c0), word);
#pragma unroll
            for (int o = 16; o > 0; o >>= 1)
                hsum += __shfl_xor_sync(0xffffffffu, hsum, o);
            if (lane == 0) g_hpart[(size_t)b*MD + ig] = hsum;
        }

        if (offdiag) {
            int jr = tid >> 1, chunk = tid & 1;
            unsigned short sh[16];
#pragma unroll
            for (int ii = 0; ii < 16; ii++) {
                int i0 = chunk*32 + 2*ii;
                __nv_bfloat16 v0 = kdS[i0*KDLD + jr];
                __nv_bfloat16 v1 = kdS[(i0+1)*KDLD + jr];
                float f0 = __bfloat162float(v0), f1 = __bfloat162float(v1);
                sh[ii] = pk_fp8(f0, f1);
                colsum += f0 * qI[half*64 + i0] + f1 * qI[half*64 + i0 + 1];
            }
            unsigned wrd[8];
#pragma unroll
            for (int k2 = 0; k2 < 8; k2++)
                wrd[k2] = (unsigned)sh[2*k2] | ((unsigned)sh[2*k2+1] << 16);
            unsigned char* dst = g_kdd8 + (size_t)(J0+jr)*MD + I0 + half*64 + chunk*32;
            uint4* d4 = reinterpret_cast<uint4*>(dst);
            __stcs(&d4[0], make_uint4(wrd[0], wrd[1], wrd[2], wrd[3]));
            __stcs(&d4[1], make_uint4(wrd[4], wrd[5], wrd[6], wrd[7]));
        }
    }

    if (offdiag) {
        float other = __shfl_xor_sync(0xffffffffu, colsum, 1);
        if ((tid & 1) == 0) {
            int jr = tid >> 1;
            g_hpart[(size_t)a*MD + J0 + jr] = colsum + other;
        }
    }
}

// -------- h reduce (parallel) --------
__global__ void k_hred() {
    __shared__ float red[8];
    int tid = threadIdx.x;
    int i = blockIdx.x * 256 + tid;
    float s = 0.f;
#pragma unroll
    for (int b = 0; b < NJB; b++) s += g_hpart[(size_t)b*MD + i];
    float h = FFC * g_hsig[i] + (1.0f - FFC) * s;
    g_h[i] = h;
    float qh_p = g_q[i] * h;
#pragma unroll
    for (int o = 16; o > 0; o >>= 1) qh_p += __shfl_xor_sync(0xffffffffu, qh_p, o);
    if ((tid & 31) == 0) red[tid >> 5] = qh_p;
    __syncthreads();
    if (tid == 0) {
        float t = 0.f;
#pragma unroll
        for (int w2 = 0; w2 < 8; w2++) t += red[w2];
        g_qhp[blockIdx.x] = t;
    }
}

// -------- scalars 2 (one warp): qh, npv, pv, c; nnum/nden out --------
__global__ void k_hfin(const float* __restrict__ y, const float* __restrict__ nn,
                       const float* __restrict__ nd, float* __restrict__ out) {
    if (threadIdx.x != 0) return;
    float qh = 0.f;
#pragma unroll
    for (int b = 0; b < 16; b++) qh += g_qhp[b];
    gs_qh = qh;
    float pu = gs_pu;
    float npv = fmaxf(pu + qh, 0.0f);
    float pv = REGC + npv;
    gs_npv = npv; gs_pv = pv;
    float cm = 0.f;
#pragma unroll
    for (int yd = 0; yd < 4; yd++) {
        float dy = y[yd] - gs_pm[yd];
        float c = dy / pv;
        gs_c[yd] = c;
        out[OFF_NN + yd] = nn[yd] + FFC * dy * dy / pv;
        cm += fabsf(c * (npv - qh));
    }
    out[OFF_ND] = nd[0] + FFC;
    gs_critM = cm;
}

// -------- Qh = Q@h + criterion + per-block argmin (scalars local) --------
__global__ void k_qhcrit(const float* __restrict__ Q, const float* __restrict__ y) {
    __shared__ float sv[8]; __shared__ int si[8];
    int tid = threadIdx.x;
    int gw = (blockIdx.x * 256 + tid) >> 5;
    int lane = tid & 31;

    float qh = 0.f;
#pragma unroll
    for (int b2 = 0; b2 < 16; b2++) qh += g_qhp[b2];
    float pu = gs_pu;
    float npv = fmaxf(pu + qh, 0.0f);
    float pv = REGC + npv;

    const float4* Qr = reinterpret_cast<const float4*>(Q) + (size_t)gw * (MD/4);
    const float4* H4 = reinterpret_cast<const float4*>(g_h);
    float s = 0.f;
#pragma unroll 8
    for (int jb = lane; jb < MD/4; jb += 32) {
        float4 qv = Qr[jb], hv = H4[jb];
        s += qv.x*hv.x + qv.y*hv.y + qv.z*hv.z + qv.w*hv.w;
    }
#pragma unroll
    for (int o = 16; o > 0; o >>= 1) s += __shfl_xor_sync(0xffffffffu, s, o);
    if (lane == 0) {
        float cv;
        if (pu < JIT) {
            cv = 0.f;
        } else {
            float qi = g_q[gw];
            float dq = (g_alloc[gw] != 0.f) ? (Q[(size_t)gw*MD + gw] + qi*qi/pu)
                                            : __int_as_float(0x7f800000);
            float r = qi / pu;
            float qhm = qh - npv;
            float acc2 = 0.f;
#pragma unroll
            for (int yd = 0; yd < 4; yd++) {
                float c = (y[yd] - gs_pm[yd]) / pv;
                float num = g_Qmu[yd*MD + gw] + c*s + r*c*qhm;
                acc2 += fabsf(num / dq);
            }
            cv = acc2;
        }
        sv[tid >> 5] = cv; si[tid >> 5] = gw;
    }
    __syncthreads();
    if (tid == 0) {
        float bv = sv[0]; int bi = si[0];
#pragma unroll
        for (int w2 = 1; w2 < 8; w2++) {
            if (sv[w2] < bv || (sv[w2] == bv && si[w2] < bi)) { bv = sv[w2]; bi = si[w2]; }
        }
        g_pval[blockIdx.x] = bv; g_pidx[blockIdx.x] = bi;
    }
}

// -------- merged argmin + prune scalars + column copy --------
__global__ void k_colpfin(const float* __restrict__ Q, const int* __restrict__ tptr) {
    __shared__ float sv[256]; __shared__ int si[256];
    int tid = threadIdx.x;
    float v0 = g_pval[tid], v1 = g_pval[tid + 256];
    int   i0 = g_pidx[tid], i1 = g_pidx[tid + 256];
    float bv; int bi;
    if (v1 < v0 || (v1 == v0 && i1 < i0)) { bv = v1; bi = i1; } else { bv = v0; bi = i0; }
    sv[tid] = bv; si[tid] = bi;
    __syncthreads();
    for (int st = 128; st > 0; st >>= 1) {
        if (tid < st) {
            if (sv[tid+st] < sv[tid] || (sv[tid+st] == sv[tid] && si[tid+st] < si[tid])) {
                sv[tid] = sv[tid+st]; si[tid] = si[tid+st];
            }
        }
        __syncthreads();
    }
    float pu = gs_pu;
    int p;
    if (pu < JIT) p = MD;
    else { p = si[0]; if (gs_critM < sv[0]) p = MD; }

    int i = blockIdx.x * 256 + tid;
    g_colp[i] = (p < MD) ? Q[(size_t)i*MD + p] : 0.0f;

    if (blockIdx.x == 0 && tid == 0) {
        gs_prune = p;
        float qp = (p < MD) ? g_q[p] : 0.0f;
        gs_qp = qp;
        bool xal = (p == MD) ? true : (g_alloc[p] != 0.f);
        float qaa = (p == MD) ? (1.0f/pu) : (Q[(size_t)p*MD + p] + qp*qp/pu);
        gs_denom = xal ? qaa : __int_as_float(0x7f800000);
        int bits = tptr[0];
        gs_tval = (bits >= 0 && bits < (1 << 26)) ? (float)bits : __int_as_float(bits);
    }
}

// -------- Q_n writer (row per block) --------
__device__ __forceinline__ float qn_elem(int p, bool rowp, int j, float Qij,
                                         float qi, float qj, float colj,
                                         float qp, float ipu, float Bi, float dinv) {
    float m, Bj;
    if (p < MD) {
        if (rowp) m = (j == p) ? ipu : (-qj * ipu);
        else      m = (j == p) ? (-qi * ipu) : (Qij + qi*qj*ipu);
        Bj = (j == p) ? (-qp * ipu) : (colj + qj*qp*ipu);
    } else {
        m  = Qij + qi*qj*ipu;
        Bj = -qj * ipu;
    }
    return m - Bi * Bj * dinv;
}

__global__ void k_postQ(const float* __restrict__ Q, float* __restrict__ out) {
    int i = blockIdx.x;
    int tid = threadIdx.x;
    int p = gs_prune;
    float pu = gs_pu, qp = gs_qp, qi = g_q[i];
    float ipu = 1.0f / pu;
    float dinv = 1.0f / gs_denom;
    bool rowp = (p < MD) && (i == p);
    float Bi = (p < MD) ? (rowp ? (-qp*ipu) : (g_colp[i] + qi*qp*ipu)) : (-qi*ipu);

    const float4* Qr = reinterpret_cast<const float4*>(Q + (size_t)i*MD);
    float4* oq = reinterpret_cast<float4*>(out + OFF_Q + (size_t)i*MD);
    const float4* q4 = reinterpret_cast<const float4*>(g_q);
    const float4* c4 = reinterpret_cast<const float4*>(g_colp);

#pragma unroll
    for (int jb = tid; jb < MD/4; jb += 256) {
        float4 Qv = Qr[jb];
        float4 qq = q4[jb]; float4 cc = c4[jb];
        int j0 = jb * 4;
        float4 oqv;
        oqv.x = qn_elem(p, rowp, j0+0, Qv.x, qi, qq.x, cc.x, qp, ipu, Bi, dinv);
        oqv.y = qn_elem(p, rowp, j0+1, Qv.y, qi, qq.y, cc.y, qp, ipu, Bi, dinv);
        oqv.z = qn_elem(p, rowp, j0+2, Qv.z, qi, qq.z, cc.z, qp, ipu, Bi, dinv);
        oqv.w = qn_elem(p, rowp, j0+3, Qv.w, qi, qq.w, cc.w, qp, ipu, Bi, dinv);
        __stcs(&oq[jb], oqv);
    }
}

// -------- sig_n bulk writer (prune-independent; exact for i,j != p) --------
__global__ void k_postS_pre(const float* __restrict__ sigma, const float* __restrict__ TI,
                            float* __restrict__ out) {
    int i = blockIdx.x;
    int tid = threadIdx.x;
    float ivp = 1.0f / gs_pv;
    float hi = g_h[i];
    float mi = (TI[i] >= 0.f) ? 1.f : 0.f;

    const float4* Sr = reinterpret_cast<const float4*>(sigma + (size_t)i*MD);
    const unsigned* Kr = reinterpret_cast<const unsigned*>(g_kdd8 + (size_t)i*MD);
    float4* os = reinterpret_cast<float4*>(out + OFF_SIG + (size_t)i*MD);
    const float4* h4 = reinterpret_cast<const float4*>(g_h);
    const float4* t4 = reinterpret_cast<const float4*>(TI);

#pragma unroll
    for (int jb = tid; jb < MD/4; jb += 256) {
        float4 sg = __ldcs(&Sr[jb]);
        unsigned kp = __ldcs(&Kr[jb]);
        float4 hh = h4[jb]; float4 tt = t4[jb];

        float4 kf = fp8x4_to_f4(kp);
        float kdf[4] = {kf.x, kf.y, kf.z, kf.w};
        float svv[4] = {sg.x, sg.y, sg.z, sg.w};
        float hvv[4] = {hh.x, hh.y, hh.z, hh.w};
        float tvv[4] = {tt.x, tt.y, tt.z, tt.w};
        float ov[4];
#pragma unroll
        for (int c = 0; c < 4; c++) {
            float spre = FFC*svv[c] + (1.0f-FFC)*kdf[c];
            float mj = (tvv[c] >= 0.f) ? 1.f : 0.f;
            ov[c] = mi * mj * (spre - hi * hvv[c] * ivp);
        }
        float4 osv; osv.x=ov[0]; osv.y=ov[1]; osv.z=ov[2]; osv.w=ov[3];
        __stcs(&os[jb], osv);
    }
}

// -------- sig_n fixup: rewrite row p and column p (only if p < MD) --------
__global__ void k_fix(const float* __restrict__ TI, float* __restrict__ out) {
    int p = gs_prune;
    if (p >= MD) return;
    float npv = gs_npv, ivp = 1.0f / gs_pv, tval = gs_tval;
    float mp = (tval >= 0.f) ? 1.f : 0.f;
    int b = blockIdx.x, tid = threadIdx.x;
    if (b < 16) {
        int j = b * 256 + tid;
        bool cp = (j == p);
        float tj = cp ? tval : TI[j];
        float mj = (tj >= 0.f) ? 1.f : 0.f;
        float ppj = cp ? npv : g_h[j];
        out[OFF_SIG + (size_t)p*MD + j] = mp * mj * (ppj - npv * ppj * ivp);
    } else {
        int i = (b - 16) * 256 + tid;
        if (i != p) {
            float mi = (TI[i] >= 0.f) ? 1.f : 0.f;
            float hi = g_h[i];
            out[OFF_SIG + (size_t)i*MD + p] = mi * mp * (hi - hi * npv * ivp);
        }
    }
}

// -------- tail: mu_n, dict_n, ti_n --------
__global__ void k_tail(const float* __restrict__ mu, const float* __restrict__ dict,
                       const float* __restrict__ x, const float* __restrict__ TI,
                       float* __restrict__ out) {
    int idx = blockIdx.x * 256 + threadIdx.x;
    int p = gs_prune;
    float tval = gs_tval;
    {
        int row = idx >> 4, c4i = idx & 15;
        float4 v;
        if (p < MD && row == p) v = *reinterpret_cast<const float4*>(x + c4i*4);
        else v = *reinterpret_cast<const float4*>(dict + (size_t)row*DD + c4i*4);
        *reinterpret_cast<float4*>(out + OFF_DICT + (size_t)row*DD + c4i*4) = v;
    }
    if (idx < MD) {
        bool rowp = (p < MD) && (idx == p);
        float tn = rowp ? tval : TI[idx];
        out[OFF_TI + idx] = tn;
        float sf = sqrtf(FFC);
        float hi = g_h[idx];
#pragma unroll
        for (int yd = 0; yd < 4; yd++) {
            float val;
            if (tn < 0.f) val = 0.f;
            else if (rowp) val = gs_pm[yd] + gs_c[yd] * gs_npv;
            else val = sf * mu[yd*MD + idx] + gs_c[yd] * hi;
            out[OFF_MU + yd*MD + idx] = val;
        }
    }
}

extern "C" void kernel_launch(void* const* d_in, const int* in_sizes, int n_in,
                              void* d_out, int out_size) {
    const float* dict = (const float*)d_in[0];
    const float* mu   = (const float*)d_in[1];
    const float* sigma= (const float*)d_in[2];
    const float* Q    = (const float*)d_in[3];
    const float* x    = (const float*)d_in[4];
    const float* y    = (const float*)d_in[5];
    const float* nn   = (const float*)d_in[6];
    const float* nd   = (const float*)d_in[7];
    const float* ti   = (const float*)d_in[8];
    const int*   tptr = (const int*)d_in[9];
    float* out = (float*)d_out;

    static cudaStream_t s_aux = nullptr;
    static cudaEvent_t ev_fork1, ev_join1, ev_fork2, ev_hfin, ev_colp, ev_end;
    if (!s_aux) {
        cudaStreamCreateWithFlags(&s_aux, cudaStreamNonBlocking);
        cudaEventCreateWithFlags(&ev_fork1, cudaEventDisableTiming);
        cudaEventCreateWithFlags(&ev_join1, cudaEventDisableTiming);
        cudaEventCreateWithFlags(&ev_fork2, cudaEventDisableTiming);
        cudaEventCreateWithFlags(&ev_hfin, cudaEventDisableTiming);
        cudaEventCreateWithFlags(&ev_colp, cudaEventDisableTiming);
        cudaEventCreateWithFlags(&ev_end, cudaEventDisableTiming);
    }

    k_kdx<<<16, 256>>>(dict, x, ti);
    k_matvec5<<<512, 256>>>(Q, mu);

    // fork1: scalars1 + sigma@q on aux, overlapped with GEMM pass on main
    cudaEventRecord(ev_fork1, 0);
    cudaStreamWaitEvent(s_aux, ev_fork1, 0);
    k_scalars1<<<1, 256, 0, s_aux>>>(mu);
    k_sigq<<<512, 256, 0, s_aux>>>(sigma);
    k_pass1<<<528, 256>>>(dict);
    cudaEventRecord(ev_join1, s_aux);
    cudaStreamWaitEvent(0, ev_join1, 0);

    k_hred<<<16, 256>>>();

    // fork2: aux does hfin + bulk sig_n (prune-independent); main does qhcrit
    cudaEventRecord(ev_fork2, 0);
    cudaStreamWaitEvent(s_aux, ev_fork2, 0);
    k_hfin<<<1, 32, 0, s_aux>>>(y, nn, nd, out);
    cudaEventRecord(ev_hfin, s_aux);
    k_postS_pre<<<4096, 256, 0, s_aux>>>(sigma, ti, out);

    k_qhcrit<<<512, 256>>>(Q, y);
    cudaStreamWaitEvent(0, ev_hfin, 0);          // colpfin reads gs_critM (hfin)
    k_colpfin<<<16, 256>>>(Q, tptr);
    cudaEventRecord(ev_colp, 0);
    k_postQ<<<4096, 256>>>(Q, out);

    cudaStreamWaitEvent(s_aux, ev_colp, 0);      // fix/tail need prune
    k_fix<<<32, 256, 0, s_aux>>>(ti, out);
    k_tail<<<256, 256, 0, s_aux>>>(mu, dict, x, ti, out);
    cudaEventRecord(ev_end, s_aux);
    cudaStreamWaitEvent(0, ev_end, 0);
}